// round 2
// baseline (speedup 1.0000x reference)
#include <cuda_runtime.h>
#include <cuda_bf16.h>
#include <math.h>

// Problem constants (fixed shapes per reference)
#define N_TOK   4096
#define D_EMB   1024
#define N_HEADS 16
#define D_HEAD  64
#define D3      (3 * D_EMB)   // 3072
#define N_GRAPHS 16

// ---------------- scratch (no allocation allowed) ----------------
__device__ float g_qkv[N_TOK * D3];      // [N, 3D]  (q | k | v), 50 MB
__device__ float g_attn[N_TOK * D_EMB];  // attention output [N, D], 16 MB
__device__ int   g_batch[N_TOK];         // normalized int32 batch ids
__device__ int   g_seg[N_GRAPHS + 1];    // segment boundaries

// ---------------- prep: dtype-sniff batch, normalize, boundaries ----------------
// batch is declared int64 in the reference, but JAX without x64 emits int32.
// Detect from bytes: values are 0..15 sorted. If int64 (LE), 32-bit word 4095
// is the high half of element 2047 == 0. If int32, word 4095 == batch[4095]
// == 15 (graph 15 nonempty w.p. ~1). So word[4095] != 0  =>  int32.
__global__ void prep_kernel(const void* __restrict__ batch_raw) {
    const int* w32 = (const int*)batch_raw;
    const bool is32 = (w32[N_TOK - 1] != 0);

    // normalize into g_batch
    for (int i = threadIdx.x; i < N_TOK; i += blockDim.x) {
        int v;
        if (is32) v = w32[i];
        else      v = (int)((const long long*)batch_raw)[i];
        g_batch[i] = v;
    }
    __syncthreads();

    // segment boundaries: g_seg[g] = lower_bound(g_batch, g)
    int g = threadIdx.x;
    if (g <= N_GRAPHS) {
        int lo = 0, hi = N_TOK;
        while (lo < hi) {
            int mid = (lo + hi) >> 1;
            if (g_batch[mid] < g) lo = mid + 1; else hi = mid;
        }
        g_seg[g] = lo;
    }
}

// ---------------- register-tiled SGEMM with bias ----------------
// C[M,N] = A[M,K] @ B[K,N] + bias[N]    (all row-major, dims multiples of tile)
#define BM 128
#define BN 128
#define BK 16
#define TM 8
#define TN 8

__global__ __launch_bounds__(256)
void sgemm_bias(int M, int N, int K,
                const float* __restrict__ A,
                const float* __restrict__ B,
                const float* __restrict__ bias,
                float* __restrict__ C)
{
    __shared__ float As[BK * BM];   // transposed A tile
    __shared__ float Bs[BK * BN];

    const int cRow = blockIdx.y;
    const int cCol = blockIdx.x;
    const int tid  = threadIdx.x;

    const int threadRow = tid / (BN / TN);   // 0..15
    const int threadCol = tid % (BN / TN);   // 0..15

    A    += (size_t)cRow * BM * K;
    B    += (size_t)cCol * BN;
    C    += (size_t)cRow * BM * N + cCol * BN;
    bias += (size_t)cCol * BN;

    const int innerRowA = tid / (BK / 4);    // 0..63
    const int innerColA = tid % (BK / 4);    // 0..3
    const int strideA   = 256 / (BK / 4);    // 64
    const int innerRowB = tid / (BN / 4);    // 0..7
    const int innerColB = tid % (BN / 4);    // 0..31
    const int strideB   = 256 / (BN / 4);    // 8

    float acc[TM * TN] = {0.f};
    float regM[TM], regN[TN];

    for (int bk = 0; bk < K; bk += BK) {
        // A tile -> As (transposed: As[k][m])
        #pragma unroll
        for (int off = 0; off < BM; off += strideA) {
            float4 t = *reinterpret_cast<const float4*>(
                A + (size_t)(innerRowA + off) * K + innerColA * 4);
            As[(innerColA * 4 + 0) * BM + innerRowA + off] = t.x;
            As[(innerColA * 4 + 1) * BM + innerRowA + off] = t.y;
            As[(innerColA * 4 + 2) * BM + innerRowA + off] = t.z;
            As[(innerColA * 4 + 3) * BM + innerRowA + off] = t.w;
        }
        // B tile -> Bs
        #pragma unroll
        for (int off = 0; off < BK; off += strideB) {
            *reinterpret_cast<float4*>(Bs + (innerRowB + off) * BN + innerColB * 4) =
                *reinterpret_cast<const float4*>(B + (size_t)(innerRowB + off) * N + innerColB * 4);
        }
        __syncthreads();

        A += BK;
        B += (size_t)BK * N;

        #pragma unroll
        for (int k = 0; k < BK; k++) {
            #pragma unroll
            for (int i = 0; i < TM; i++) regM[i] = As[k * BM + threadRow * TM + i];
            #pragma unroll
            for (int j = 0; j < TN; j++) regN[j] = Bs[k * BN + threadCol * TN + j];
            #pragma unroll
            for (int i = 0; i < TM; i++)
                #pragma unroll
                for (int j = 0; j < TN; j++)
                    acc[i * TN + j] += regM[i] * regN[j];
        }
        __syncthreads();
    }

    // epilogue: add bias, store with float4
    #pragma unroll
    for (int i = 0; i < TM; i++) {
        #pragma unroll
        for (int j = 0; j < TN; j += 4) {
            int col = threadCol * TN + j;
            float4 t;
            t.x = acc[i * TN + j + 0] + bias[col + 0];
            t.y = acc[i * TN + j + 1] + bias[col + 1];
            t.z = acc[i * TN + j + 2] + bias[col + 2];
            t.w = acc[i * TN + j + 3] + bias[col + 3];
            *reinterpret_cast<float4*>(C + (size_t)(threadRow * TM + i) * N + col) = t;
        }
    }
}

// ---------------- attention: one warp per (head, query) ----------------
// Block-diagonal mask (sorted batch) => only attend within own segment.
// The +1.0 mask constant is softmax-invariant and dropped.
__global__ __launch_bounds__(256)
void attn_kernel(const float* __restrict__ qkv,
                 float* __restrict__ out)
{
    const int warp_id = (blockIdx.x * blockDim.x + threadIdx.x) >> 5;
    const int lane    = threadIdx.x & 31;
    // n varies fastest: consecutive warps share head + segment -> L1/L2 reuse
    const int h = warp_id / N_TOK;
    const int n = warp_id % N_TOK;
    if (h >= N_HEADS) return;

    const float* qp = qkv + (size_t)n * D3 + h * D_HEAD;
    const float q0 = qp[lane];
    const float q1 = qp[lane + 32];

    const int g = g_batch[n];
    const int s = g_seg[g];
    const int e = g_seg[g + 1];

    float mmax = -INFINITY, l = 0.f, acc0 = 0.f, acc1 = 0.f;

    const float* kbase = qkv + D_EMB     + h * D_HEAD;   // k columns
    const float* vbase = qkv + 2 * D_EMB + h * D_HEAD;   // v columns

    for (int m = s; m < e; m++) {
        const float* kp = kbase + (size_t)m * D3;
        float part = fmaf(q0, kp[lane], q1 * kp[lane + 32]);
        #pragma unroll
        for (int o = 16; o > 0; o >>= 1)
            part += __shfl_xor_sync(0xffffffffu, part, o);
        const float sc = part * 0.125f;   // 1/sqrt(64)

        const float mnew = fmaxf(mmax, sc);
        const float corr = __expf(mmax - mnew);   // exp(-inf)=0 handles first iter
        const float p    = __expf(sc - mnew);
        l = fmaf(l, corr, p);

        const float* vp = vbase + (size_t)m * D3;
        acc0 = fmaf(acc0, corr, p * vp[lane]);
        acc1 = fmaf(acc1, corr, p * vp[lane + 32]);
        mmax = mnew;
    }

    const float inv = (l > 0.f) ? (1.f / l) : 0.f;
    float* op = out + (size_t)n * D_EMB + h * D_HEAD;
    op[lane]      = acc0 * inv;
    op[lane + 32] = acc1 * inv;
}

// ---------------- launcher ----------------
extern "C" void kernel_launch(void* const* d_in, const int* in_sizes, int n_in,
                              void* d_out, int out_size)
{
    const float* x     = (const float*)d_in[0];
    const void*  batch = d_in[1];               // dtype sniffed on device
    const float* W_in  = (const float*)d_in[2];
    const float* b_in  = (const float*)d_in[3];
    const float* W_out = (const float*)d_in[4];
    const float* b_out = (const float*)d_in[5];
    float*       out   = (float*)d_out;

    float* qkv;  cudaGetSymbolAddress((void**)&qkv,  g_qkv);
    float* attn; cudaGetSymbolAddress((void**)&attn, g_attn);

    // 1. normalize batch dtype + segment boundaries
    prep_kernel<<<1, 256>>>(batch);

    // 2. qkv = x @ W_in + b_in       [4096,1024]x[1024,3072]
    {
        dim3 grid(D3 / BN, N_TOK / BM);
        sgemm_bias<<<grid, 256>>>(N_TOK, D3, D_EMB, x, W_in, b_in, qkv);
    }

    // 3. segment-local attention (one warp per head x query)
    {
        int total_warps = N_HEADS * N_TOK;           // 65536
        int blocks = total_warps / 8;                // 256 threads = 8 warps / block
        attn_kernel<<<blocks, 256>>>(qkv, attn);
    }

    // 4. out = attn @ W_out + b_out  [4096,1024]x[1024,1024]
    {
        dim3 grid(D_EMB / BN, N_TOK / BM);
        sgemm_bias<<<grid, 256>>>(N_TOK, D_EMB, D_EMB, attn, W_out, b_out, out);
    }
}

// round 3
// speedup vs baseline: 1.5138x; 1.5138x over previous
#include <cuda_runtime.h>
#include <cuda_bf16.h>
#include <math.h>

// Problem constants (fixed shapes per reference)
#define N_TOK   4096
#define D_EMB   1024
#define N_HEADS 16
#define D_HEAD  64
#define D3      (3 * D_EMB)   // 3072
#define N_GRAPHS 16

#define TQ 64
#define TK 64
#define MAX_TILES 80   // sum ceil(len/64) <= 4096/64 + 16

// ---------------- scratch (no allocation allowed) ----------------
__device__ float g_qkv[N_TOK * D3];      // [N, 3D]  (q | k | v)
__device__ float g_attn[N_TOK * D_EMB];  // attention output [N, D]
__device__ int   g_batch[N_TOK];
__device__ int   g_seg[N_GRAPHS + 1];
__device__ int   g_tile_seg[MAX_TILES];
__device__ int   g_tile_q0[MAX_TILES];
__device__ int   g_ntiles;

// ---------------- prep: dtype-sniff batch, boundaries, tile worklist ----------------
// batch declared int64 in the reference but JAX w/o x64 emits int32.
// If int64 (LE), 32-bit word 4095 is high half of element 2047 == 0.
// If int32, word 4095 == batch[4095] == 15. word[4095]!=0 => int32.
__global__ void prep_kernel(const void* __restrict__ batch_raw) {
    const int* w32 = (const int*)batch_raw;
    const bool is32 = (w32[N_TOK - 1] != 0);

    for (int i = threadIdx.x; i < N_TOK; i += blockDim.x) {
        int v;
        if (is32) v = w32[i];
        else      v = (int)((const long long*)batch_raw)[i];
        g_batch[i] = v;
    }
    __syncthreads();

    int g = threadIdx.x;
    if (g <= N_GRAPHS) {
        int lo = 0, hi = N_TOK;
        while (lo < hi) {
            int mid = (lo + hi) >> 1;
            if (g_batch[mid] < g) lo = mid + 1; else hi = mid;
        }
        g_seg[g] = lo;
    }
    __syncthreads();

    if (threadIdx.x == 0) {
        int cnt = 0;
        for (int s = 0; s < N_GRAPHS; s++) {
            for (int q = g_seg[s]; q < g_seg[s + 1]; q += TQ) {
                g_tile_seg[cnt] = s;
                g_tile_q0[cnt]  = q;
                cnt++;
            }
        }
        g_ntiles = cnt;
    }
}

// ---------------- register-tiled SGEMM with bias ----------------
#define BM 128
#define BN 128
#define BK 16
#define TM 8
#define TN 8

__global__ __launch_bounds__(256)
void sgemm_bias(int M, int N, int K,
                const float* __restrict__ A,
                const float* __restrict__ B,
                const float* __restrict__ bias,
                float* __restrict__ C)
{
    __shared__ float As[BK * BM];   // transposed A tile
    __shared__ float Bs[BK * BN];

    const int cRow = blockIdx.y;
    const int cCol = blockIdx.x;
    const int tid  = threadIdx.x;

    const int threadRow = tid / (BN / TN);
    const int threadCol = tid % (BN / TN);

    A    += (size_t)cRow * BM * K;
    B    += (size_t)cCol * BN;
    C    += (size_t)cRow * BM * N + cCol * BN;
    bias += (size_t)cCol * BN;

    const int innerRowA = tid / (BK / 4);
    const int innerColA = tid % (BK / 4);
    const int strideA   = 256 / (BK / 4);
    const int innerRowB = tid / (BN / 4);
    const int innerColB = tid % (BN / 4);
    const int strideB   = 256 / (BN / 4);

    float acc[TM * TN] = {0.f};
    float regM[TM], regN[TN];

    for (int bk = 0; bk < K; bk += BK) {
        #pragma unroll
        for (int off = 0; off < BM; off += strideA) {
            float4 t = *reinterpret_cast<const float4*>(
                A + (size_t)(innerRowA + off) * K + innerColA * 4);
            As[(innerColA * 4 + 0) * BM + innerRowA + off] = t.x;
            As[(innerColA * 4 + 1) * BM + innerRowA + off] = t.y;
            As[(innerColA * 4 + 2) * BM + innerRowA + off] = t.z;
            As[(innerColA * 4 + 3) * BM + innerRowA + off] = t.w;
        }
        #pragma unroll
        for (int off = 0; off < BK; off += strideB) {
            *reinterpret_cast<float4*>(Bs + (innerRowB + off) * BN + innerColB * 4) =
                *reinterpret_cast<const float4*>(B + (size_t)(innerRowB + off) * N + innerColB * 4);
        }
        __syncthreads();

        A += BK;
        B += (size_t)BK * N;

        #pragma unroll
        for (int k = 0; k < BK; k++) {
            #pragma unroll
            for (int i = 0; i < TM; i++) regM[i] = As[k * BM + threadRow * TM + i];
            #pragma unroll
            for (int j = 0; j < TN; j++) regN[j] = Bs[k * BN + threadCol * TN + j];
            #pragma unroll
            for (int i = 0; i < TM; i++)
                #pragma unroll
                for (int j = 0; j < TN; j++)
                    acc[i * TN + j] += regM[i] * regN[j];
        }
        __syncthreads();
    }

    #pragma unroll
    for (int i = 0; i < TM; i++) {
        #pragma unroll
        for (int j = 0; j < TN; j += 4) {
            int col = threadCol * TN + j;
            float4 t;
            t.x = acc[i * TN + j + 0] + bias[col + 0];
            t.y = acc[i * TN + j + 1] + bias[col + 1];
            t.z = acc[i * TN + j + 2] + bias[col + 2];
            t.w = acc[i * TN + j + 3] + bias[col + 3];
            *reinterpret_cast<float4*>(C + (size_t)(threadRow * TM + i) * N + col) = t;
        }
    }
}

// ---------------- tiled flash attention ----------------
// One block per (head, 64-query tile of a segment). 256 threads = 16x16 grid,
// each thread owns a 4x4 register tile. K buffer is reused for transposed P.
// The +1.0 in-block mask constant is softmax-invariant and dropped.
__global__ __launch_bounds__(256)
void attn_tiled(const float* __restrict__ qkv, float* __restrict__ out)
{
    const int tile = blockIdx.x;
    if (tile >= g_ntiles) return;
    const int h   = blockIdx.y;
    const int seg = g_tile_seg[tile];
    const int q0  = g_tile_q0[tile];
    const int s   = g_seg[seg];
    const int e   = g_seg[seg + 1];
    const int qlen = min(TQ, e - q0);
    (void)s;

    __shared__ float Qt[TQ][64];    // [d][i]   (Q transposed)
    __shared__ float KPt[TK][64];   // K phase: [d][j]; P phase: [j][i]
    __shared__ float Vs[TK][64];    // [j][d]

    const int tid = threadIdx.x;
    const int tr  = tid >> 4;       // 0..15  -> rows  tr*4 .. tr*4+3
    const int tc  = tid & 15;       // 0..15  -> cols  tc*4 .. tc*4+3

    // ---- load Q tile transposed ----
    {
        const int i  = tid >> 2;          // 0..63
        const int d0 = (tid & 3) * 16;    // 0,16,32,48
        const bool valid = (i < qlen);
        const float* src = qkv + (size_t)(q0 + i) * D3 + h * D_HEAD + d0;
        #pragma unroll
        for (int f = 0; f < 4; f++) {
            float4 t = valid ? *reinterpret_cast<const float4*>(src + f * 4)
                             : make_float4(0.f, 0.f, 0.f, 0.f);
            Qt[d0 + f * 4 + 0][i] = t.x;
            Qt[d0 + f * 4 + 1][i] = t.y;
            Qt[d0 + f * 4 + 2][i] = t.z;
            Qt[d0 + f * 4 + 3][i] = t.w;
        }
    }

    float m[4], l[4], O[4][4];
    #pragma unroll
    for (int ii = 0; ii < 4; ii++) {
        m[ii] = -INFINITY; l[ii] = 0.f;
        #pragma unroll
        for (int dd = 0; dd < 4; dd++) O[ii][dd] = 0.f;
    }

    for (int m0 = g_seg[seg]; m0 < e; m0 += TK) {
        const int klen = min(TK, e - m0);
        __syncthreads();   // previous iter's P/V reads done before overwrite

        // ---- load K transposed + V row-major ----
        {
            const int j  = tid >> 2;
            const int d0 = (tid & 3) * 16;
            const bool valid = (j < klen);
            const float* ksrc = qkv + (size_t)(m0 + j) * D3 + D_EMB     + h * D_HEAD + d0;
            const float* vsrc = qkv + (size_t)(m0 + j) * D3 + 2 * D_EMB + h * D_HEAD + d0;
            #pragma unroll
            for (int f = 0; f < 4; f++) {
                float4 t = valid ? *reinterpret_cast<const float4*>(ksrc + f * 4)
                                 : make_float4(0.f, 0.f, 0.f, 0.f);
                KPt[d0 + f * 4 + 0][j] = t.x;
                KPt[d0 + f * 4 + 1][j] = t.y;
                KPt[d0 + f * 4 + 2][j] = t.z;
                KPt[d0 + f * 4 + 3][j] = t.w;
                float4 v = valid ? *reinterpret_cast<const float4*>(vsrc + f * 4)
                                 : make_float4(0.f, 0.f, 0.f, 0.f);
                *reinterpret_cast<float4*>(&Vs[j][d0 + f * 4]) = v;
            }
        }
        __syncthreads();

        // ---- S = Q @ K^T (4x4 per thread) ----
        float acc[4][4];
        #pragma unroll
        for (int ii = 0; ii < 4; ii++)
            #pragma unroll
            for (int jj = 0; jj < 4; jj++) acc[ii][jj] = 0.f;

        #pragma unroll 8
        for (int d = 0; d < 64; d++) {
            float4 qv = *reinterpret_cast<const float4*>(&Qt[d][tr * 4]);
            float4 kv = *reinterpret_cast<const float4*>(&KPt[d][tc * 4]);
            const float qa[4] = {qv.x, qv.y, qv.z, qv.w};
            const float ka[4] = {kv.x, kv.y, kv.z, kv.w};
            #pragma unroll
            for (int ii = 0; ii < 4; ii++)
                #pragma unroll
                for (int jj = 0; jj < 4; jj++)
                    acc[ii][jj] = fmaf(qa[ii], ka[jj], acc[ii][jj]);
        }

        // ---- online softmax (rows distributed over 16 lanes sharing tr) ----
        float p[4][4], corr[4];
        #pragma unroll
        for (int ii = 0; ii < 4; ii++) {
            float rmax = -INFINITY;
            #pragma unroll
            for (int jj = 0; jj < 4; jj++) {
                float sc = (tc * 4 + jj < klen) ? acc[ii][jj] * 0.125f : -INFINITY;
                acc[ii][jj] = sc;
                rmax = fmaxf(rmax, sc);
            }
            #pragma unroll
            for (int o = 1; o < 16; o <<= 1)
                rmax = fmaxf(rmax, __shfl_xor_sync(0xffffffffu, rmax, o));

            const float mnew = fmaxf(m[ii], rmax);
            corr[ii] = __expf(m[ii] - mnew);      // exp(-inf)=0 first iter
            float rsum = 0.f;
            #pragma unroll
            for (int jj = 0; jj < 4; jj++) {
                float pv = __expf(acc[ii][jj] - mnew);
                p[ii][jj] = pv;
                rsum += pv;
            }
            #pragma unroll
            for (int o = 1; o < 16; o <<= 1)
                rsum += __shfl_xor_sync(0xffffffffu, rsum, o);

            l[ii] = fmaf(l[ii], corr[ii], rsum);
            m[ii] = mnew;
            #pragma unroll
            for (int dd = 0; dd < 4; dd++) O[ii][dd] *= corr[ii];
        }

        __syncthreads();   // all K reads done; safe to overwrite KPt with P

        // ---- stage P transposed: KPt[j][i] = p ----
        #pragma unroll
        for (int jj = 0; jj < 4; jj++)
            #pragma unroll
            for (int ii = 0; ii < 4; ii++)
                KPt[tc * 4 + jj][tr * 4 + ii] = p[ii][jj];
        __syncthreads();

        // ---- O += P @ V ---- (invalid j have p=0)
        #pragma unroll 8
        for (int j = 0; j < 64; j++) {
            float4 pv = *reinterpret_cast<const float4*>(&KPt[j][tr * 4]);
            float4 vv = *reinterpret_cast<const float4*>(&Vs[j][tc * 4]);
            const float pa[4] = {pv.x, pv.y, pv.z, pv.w};
            const float va[4] = {vv.x, vv.y, vv.z, vv.w};
            #pragma unroll
            for (int ii = 0; ii < 4; ii++)
                #pragma unroll
                for (int dd = 0; dd < 4; dd++)
                    O[ii][dd] = fmaf(pa[ii], va[dd], O[ii][dd]);
        }
    }

    // ---- write O / l ----
    #pragma unroll
    for (int ii = 0; ii < 4; ii++) {
        const int i = tr * 4 + ii;
        if (i < qlen) {
            const float inv = 1.f / l[ii];
            float4 t;
            t.x = O[ii][0] * inv;
            t.y = O[ii][1] * inv;
            t.z = O[ii][2] * inv;
            t.w = O[ii][3] * inv;
            *reinterpret_cast<float4*>(
                out + (size_t)(q0 + i) * D_EMB + h * D_HEAD + tc * 4) = t;
        }
    }
}

// ---------------- launcher ----------------
extern "C" void kernel_launch(void* const* d_in, const int* in_sizes, int n_in,
                              void* d_out, int out_size)
{
    const float* x     = (const float*)d_in[0];
    const void*  batch = d_in[1];
    const float* W_in  = (const float*)d_in[2];
    const float* b_in  = (const float*)d_in[3];
    const float* W_out = (const float*)d_in[4];
    const float* b_out = (const float*)d_in[5];
    float*       out   = (float*)d_out;

    float* qkv;  cudaGetSymbolAddress((void**)&qkv,  g_qkv);
    float* attn; cudaGetSymbolAddress((void**)&attn, g_attn);

    prep_kernel<<<1, 256>>>(batch);

    {   // qkv = x @ W_in + b_in  [4096,1024]x[1024,3072]
        dim3 grid(D3 / BN, N_TOK / BM);
        sgemm_bias<<<grid, 256>>>(N_TOK, D3, D_EMB, x, W_in, b_in, qkv);
    }

    {   // segment-local tiled attention
        dim3 grid(MAX_TILES, N_HEADS);
        attn_tiled<<<grid, 256>>>(qkv, attn);
    }

    {   // out = attn @ W_out + b_out  [4096,1024]x[1024,1024]
        dim3 grid(D_EMB / BN, N_TOK / BM);
        sgemm_bias<<<grid, 256>>>(N_TOK, D_EMB, D_EMB, attn, W_out, b_out, out);
    }
}

// round 4
// speedup vs baseline: 2.8747x; 1.8990x over previous
#include <cuda_runtime.h>
#include <cuda_bf16.h>
#include <math.h>

// Problem constants (fixed shapes per reference)
#define N_TOK   4096
#define D_EMB   1024
#define N_HEADS 16
#define D_HEAD  64
#define D3      (3 * D_EMB)   // 3072
#define N_GRAPHS 16

#define TQ 64
#define TK 64
#define MAX_TILES 80   // sum ceil(len/64) <= 4096/64 + 16

// ---------------- scratch (no allocation allowed) ----------------
__device__ float g_qkv[N_TOK * D3];      // [N, 3D]  (q | k | v)
__device__ float g_attn[N_TOK * D_EMB];  // attention output [N, D]
__device__ int   g_batch[N_TOK];
__device__ int   g_seg[N_GRAPHS + 1];
__device__ int   g_tile_seg[MAX_TILES];
__device__ int   g_tile_q0[MAX_TILES];
__device__ int   g_ntiles;

// ---------------- prep: dtype-sniff batch, boundaries, tile worklist ----------------
__global__ void prep_kernel(const void* __restrict__ batch_raw) {
    const int* w32 = (const int*)batch_raw;
    const bool is32 = (w32[N_TOK - 1] != 0);

    for (int i = threadIdx.x; i < N_TOK; i += blockDim.x) {
        int v;
        if (is32) v = w32[i];
        else      v = (int)((const long long*)batch_raw)[i];
        g_batch[i] = v;
    }
    __syncthreads();

    int g = threadIdx.x;
    if (g <= N_GRAPHS) {
        int lo = 0, hi = N_TOK;
        while (lo < hi) {
            int mid = (lo + hi) >> 1;
            if (g_batch[mid] < g) lo = mid + 1; else hi = mid;
        }
        g_seg[g] = lo;
    }
    __syncthreads();

    if (threadIdx.x == 0) {
        int cnt = 0;
        for (int s = 0; s < N_GRAPHS; s++) {
            for (int q = g_seg[s]; q < g_seg[s + 1]; q += TQ) {
                g_tile_seg[cnt] = s;
                g_tile_q0[cnt]  = q;
                cnt++;
            }
        }
        g_ntiles = cnt;
    }
}

// ---------------- tf32 helpers ----------------
__device__ __forceinline__ unsigned f2tf32(float x) {
    unsigned r;
    asm("cvt.rna.tf32.f32 %0, %1;" : "=r"(r) : "f"(x));
    return r;
}

__device__ __forceinline__ void mma_tf32(float* c, const unsigned* a, const unsigned* b) {
    asm volatile(
        "mma.sync.aligned.m16n8k8.row.col.f32.tf32.tf32.f32 "
        "{%0,%1,%2,%3}, {%4,%5,%6,%7}, {%8,%9}, {%0,%1,%2,%3};"
        : "+f"(c[0]), "+f"(c[1]), "+f"(c[2]), "+f"(c[3])
        : "r"(a[0]), "r"(a[1]), "r"(a[2]), "r"(a[3]),
          "r"(b[0]), "r"(b[1]));
}

// ---------------- tf32 tensor-core GEMM with bias ----------------
// C[M,N] = A[M,K] @ B[K,N] + bias[N]; M,N mult of 128, K mult of 16.
// Block 256 thr = 8 warps (2x4); block tile 128x128, BK=16; warp tile 64x32.
// Fragments stored permuted in smem so the inner loop is LDS.128/LDS.64 -> MMA.
__global__ __launch_bounds__(256, 2)
void gemm_tf32_bias(int M, int N, int K,
                    const float* __restrict__ A,
                    const float* __restrict__ B,
                    const float* __restrict__ bias,
                    float* __restrict__ C)
{
    __shared__ unsigned As[2048];  // (kb2:2, mb:8) groups x 32 t x 4 r
    __shared__ unsigned Bs[2048];  // (kb2:2, nb:16) groups x 32 t x 2 r

    const int tid  = threadIdx.x;
    const int warp = tid >> 5;
    const int lane = tid & 31;
    const int wm   = warp >> 2;          // 0..1
    const int wn   = warp & 3;           // 0..3
    const int bm   = blockIdx.y * 128;
    const int bn   = blockIdx.x * 128;

    // --- staging lane decomposition (A): conflict-free STS ---
    const int a_c  = lane & 3;
    const int a_d  = (lane >> 2) & 1;
    const int a_g0 = (lane >> 3) & 1;
    const int a_h  = (lane >> 4) & 1;
    const int a_mb = warp;               // m-block 0..7
    // --- staging lane decomposition (B): 2-way STS ---
    const int b_g  = lane & 7;
    const int b_c  = (lane >> 3) & 3;

    float acc[4][4][4];
    #pragma unroll
    for (int i = 0; i < 4; i++)
        #pragma unroll
        for (int j = 0; j < 4; j++)
            #pragma unroll
            for (int r = 0; r < 4; r++) acc[i][j][r] = 0.f;

    float av[8], bv[8];

    // prefetch tile 0
    {
        #pragma unroll
        for (int gh = 0; gh < 4; gh++)
            #pragma unroll
            for (int kb2 = 0; kb2 < 2; kb2++) {
                int m = a_mb * 16 + a_h * 8 + gh * 2 + a_g0;
                int k = kb2 * 8 + a_d * 4 + a_c;
                av[gh * 2 + kb2] = A[(size_t)(bm + m) * K + k];
            }
        #pragma unroll
        for (int d2 = 0; d2 < 2; d2++)
            #pragma unroll
            for (int kb2 = 0; kb2 < 2; kb2++)
                #pragma unroll
                for (int nbl = 0; nbl < 2; nbl++) {
                    int n = (warp * 2 + nbl) * 8 + b_g;
                    int k = kb2 * 8 + d2 * 4 + b_c;
                    bv[(d2 * 2 + kb2) * 2 + nbl] = B[(size_t)k * N + bn + n];
                }
    }

    const int KT = K >> 4;
    for (int kt = 0; kt < KT; kt++) {
        __syncthreads();   // previous compute done

        // --- STS current tile (converted to tf32) ---
        #pragma unroll
        for (int gh = 0; gh < 4; gh++)
            #pragma unroll
            for (int kb2 = 0; kb2 < 2; kb2++) {
                int g = gh * 2 + a_g0;
                int idx = (((kb2 << 3) + a_mb) << 7) + ((g << 2) + a_c) * 4 + a_h + 2 * a_d;
                As[idx] = f2tf32(av[gh * 2 + kb2]);
            }
        #pragma unroll
        for (int d2 = 0; d2 < 2; d2++)
            #pragma unroll
            for (int kb2 = 0; kb2 < 2; kb2++)
                #pragma unroll
                for (int nbl = 0; nbl < 2; nbl++) {
                    int nb = warp * 2 + nbl;
                    int idx = (((kb2 << 4) + nb) << 6) + ((b_g << 2) + b_c) * 2 + d2;
                    Bs[idx] = f2tf32(bv[(d2 * 2 + kb2) * 2 + nbl]);
                }
        __syncthreads();

        // --- prefetch next tile (overlaps MMA) ---
        if (kt + 1 < KT) {
            int k0 = (kt + 1) << 4;
            #pragma unroll
            for (int gh = 0; gh < 4; gh++)
                #pragma unroll
                for (int kb2 = 0; kb2 < 2; kb2++) {
                    int m = a_mb * 16 + a_h * 8 + gh * 2 + a_g0;
                    int k = k0 + kb2 * 8 + a_d * 4 + a_c;
                    av[gh * 2 + kb2] = A[(size_t)(bm + m) * K + k];
                }
            #pragma unroll
            for (int d2 = 0; d2 < 2; d2++)
                #pragma unroll
                for (int kb2 = 0; kb2 < 2; kb2++)
                    #pragma unroll
                    for (int nbl = 0; nbl < 2; nbl++) {
                        int n = (warp * 2 + nbl) * 8 + b_g;
                        int k = k0 + kb2 * 8 + d2 * 4 + b_c;
                        bv[(d2 * 2 + kb2) * 2 + nbl] = B[(size_t)k * N + bn + n];
                    }
        }

        // --- compute: 2 k8-steps, 16 mma each ---
        #pragma unroll
        for (int kb2 = 0; kb2 < 2; kb2++) {
            unsigned afr[4][4];
            unsigned bfr[4][2];
            #pragma unroll
            for (int i = 0; i < 4; i++) {
                int grp = kb2 * 8 + wm * 4 + i;
                uint4 t = *reinterpret_cast<const uint4*>(&As[(grp << 7) + (lane << 2)]);
                afr[i][0] = t.x; afr[i][1] = t.y; afr[i][2] = t.z; afr[i][3] = t.w;
            }
            #pragma unroll
            for (int j = 0; j < 4; j++) {
                int grp = kb2 * 16 + wn * 4 + j;
                uint2 t = *reinterpret_cast<const uint2*>(&Bs[(grp << 6) + (lane << 1)]);
                bfr[j][0] = t.x; bfr[j][1] = t.y;
            }
            #pragma unroll
            for (int i = 0; i < 4; i++)
                #pragma unroll
                for (int j = 0; j < 4; j++)
                    mma_tf32(acc[i][j], afr[i], bfr[j]);
        }
    }

    // --- epilogue: bias + store ---
    const int lg = lane >> 2;   // 0..7  (row within 8)
    const int lc = lane & 3;    // col pair
    #pragma unroll
    for (int i = 0; i < 4; i++) {
        const int m0 = bm + wm * 64 + i * 16 + lg;
        #pragma unroll
        for (int j = 0; j < 4; j++) {
            const int n0 = bn + wn * 32 + j * 8 + lc * 2;
            const float bx = bias[n0];
            const float by = bias[n0 + 1];
            float2 v0 = make_float2(acc[i][j][0] + bx, acc[i][j][1] + by);
            float2 v1 = make_float2(acc[i][j][2] + bx, acc[i][j][3] + by);
            *reinterpret_cast<float2*>(C + (size_t)m0 * N + n0)       = v0;
            *reinterpret_cast<float2*>(C + (size_t)(m0 + 8) * N + n0) = v1;
        }
    }
}

// ---------------- tiled flash attention (unchanged from R3) ----------------
__global__ __launch_bounds__(256)
void attn_tiled(const float* __restrict__ qkv, float* __restrict__ out)
{
    const int tile = blockIdx.x;
    if (tile >= g_ntiles) return;
    const int h   = blockIdx.y;
    const int seg = g_tile_seg[tile];
    const int q0  = g_tile_q0[tile];
    const int e   = g_seg[seg + 1];
    const int qlen = min(TQ, e - q0);

    __shared__ float Qt[TQ][64];
    __shared__ float KPt[TK][64];
    __shared__ float Vs[TK][64];

    const int tid = threadIdx.x;
    const int tr  = tid >> 4;
    const int tc  = tid & 15;

    {
        const int i  = tid >> 2;
        const int d0 = (tid & 3) * 16;
        const bool valid = (i < qlen);
        const float* src = qkv + (size_t)(q0 + i) * D3 + h * D_HEAD + d0;
        #pragma unroll
        for (int f = 0; f < 4; f++) {
            float4 t = valid ? *reinterpret_cast<const float4*>(src + f * 4)
                             : make_float4(0.f, 0.f, 0.f, 0.f);
            Qt[d0 + f * 4 + 0][i] = t.x;
            Qt[d0 + f * 4 + 1][i] = t.y;
            Qt[d0 + f * 4 + 2][i] = t.z;
            Qt[d0 + f * 4 + 3][i] = t.w;
        }
    }

    float m[4], l[4], O[4][4];
    #pragma unroll
    for (int ii = 0; ii < 4; ii++) {
        m[ii] = -INFINITY; l[ii] = 0.f;
        #pragma unroll
        for (int dd = 0; dd < 4; dd++) O[ii][dd] = 0.f;
    }

    for (int m0 = g_seg[seg]; m0 < e; m0 += TK) {
        const int klen = min(TK, e - m0);
        __syncthreads();

        {
            const int j  = tid >> 2;
            const int d0 = (tid & 3) * 16;
            const bool valid = (j < klen);
            const float* ksrc = qkv + (size_t)(m0 + j) * D3 + D_EMB     + h * D_HEAD + d0;
            const float* vsrc = qkv + (size_t)(m0 + j) * D3 + 2 * D_EMB + h * D_HEAD + d0;
            #pragma unroll
            for (int f = 0; f < 4; f++) {
                float4 t = valid ? *reinterpret_cast<const float4*>(ksrc + f * 4)
                                 : make_float4(0.f, 0.f, 0.f, 0.f);
                KPt[d0 + f * 4 + 0][j] = t.x;
                KPt[d0 + f * 4 + 1][j] = t.y;
                KPt[d0 + f * 4 + 2][j] = t.z;
                KPt[d0 + f * 4 + 3][j] = t.w;
                float4 v = valid ? *reinterpret_cast<const float4*>(vsrc + f * 4)
                                 : make_float4(0.f, 0.f, 0.f, 0.f);
                *reinterpret_cast<float4*>(&Vs[j][d0 + f * 4]) = v;
            }
        }
        __syncthreads();

        float acc[4][4];
        #pragma unroll
        for (int ii = 0; ii < 4; ii++)
            #pragma unroll
            for (int jj = 0; jj < 4; jj++) acc[ii][jj] = 0.f;

        #pragma unroll 8
        for (int d = 0; d < 64; d++) {
            float4 qv = *reinterpret_cast<const float4*>(&Qt[d][tr * 4]);
            float4 kv = *reinterpret_cast<const float4*>(&KPt[d][tc * 4]);
            const float qa[4] = {qv.x, qv.y, qv.z, qv.w};
            const float ka[4] = {kv.x, kv.y, kv.z, kv.w};
            #pragma unroll
            for (int ii = 0; ii < 4; ii++)
                #pragma unroll
                for (int jj = 0; jj < 4; jj++)
                    acc[ii][jj] = fmaf(qa[ii], ka[jj], acc[ii][jj]);
        }

        float p[4][4], corr[4];
        #pragma unroll
        for (int ii = 0; ii < 4; ii++) {
            float rmax = -INFINITY;
            #pragma unroll
            for (int jj = 0; jj < 4; jj++) {
                float sc = (tc * 4 + jj < klen) ? acc[ii][jj] * 0.125f : -INFINITY;
                acc[ii][jj] = sc;
                rmax = fmaxf(rmax, sc);
            }
            #pragma unroll
            for (int o = 1; o < 16; o <<= 1)
                rmax = fmaxf(rmax, __shfl_xor_sync(0xffffffffu, rmax, o));

            const float mnew = fmaxf(m[ii], rmax);
            corr[ii] = __expf(m[ii] - mnew);
            float rsum = 0.f;
            #pragma unroll
            for (int jj = 0; jj < 4; jj++) {
                float pv = __expf(acc[ii][jj] - mnew);
                p[ii][jj] = pv;
                rsum += pv;
            }
            #pragma unroll
            for (int o = 1; o < 16; o <<= 1)
                rsum += __shfl_xor_sync(0xffffffffu, rsum, o);

            l[ii] = fmaf(l[ii], corr[ii], rsum);
            m[ii] = mnew;
            #pragma unroll
            for (int dd = 0; dd < 4; dd++) O[ii][dd] *= corr[ii];
        }

        __syncthreads();

        #pragma unroll
        for (int jj = 0; jj < 4; jj++)
            #pragma unroll
            for (int ii = 0; ii < 4; ii++)
                KPt[tc * 4 + jj][tr * 4 + ii] = p[ii][jj];
        __syncthreads();

        #pragma unroll 8
        for (int j = 0; j < 64; j++) {
            float4 pv = *reinterpret_cast<const float4*>(&KPt[j][tr * 4]);
            float4 vv = *reinterpret_cast<const float4*>(&Vs[j][tc * 4]);
            const float pa[4] = {pv.x, pv.y, pv.z, pv.w};
            const float va[4] = {vv.x, vv.y, vv.z, vv.w};
            #pragma unroll
            for (int ii = 0; ii < 4; ii++)
                #pragma unroll
                for (int dd = 0; dd < 4; dd++)
                    O[ii][dd] = fmaf(pa[ii], va[dd], O[ii][dd]);
        }
    }

    #pragma unroll
    for (int ii = 0; ii < 4; ii++) {
        const int i = tr * 4 + ii;
        if (i < qlen) {
            const float inv = 1.f / l[ii];
            float4 t;
            t.x = O[ii][0] * inv;
            t.y = O[ii][1] * inv;
            t.z = O[ii][2] * inv;
            t.w = O[ii][3] * inv;
            *reinterpret_cast<float4*>(
                out + (size_t)(q0 + i) * D_EMB + h * D_HEAD + tc * 4) = t;
        }
    }
}

// ---------------- launcher ----------------
extern "C" void kernel_launch(void* const* d_in, const int* in_sizes, int n_in,
                              void* d_out, int out_size)
{
    const float* x     = (const float*)d_in[0];
    const void*  batch = d_in[1];
    const float* W_in  = (const float*)d_in[2];
    const float* b_in  = (const float*)d_in[3];
    const float* W_out = (const float*)d_in[4];
    const float* b_out = (const float*)d_in[5];
    float*       out   = (float*)d_out;

    float* qkv;  cudaGetSymbolAddress((void**)&qkv,  g_qkv);
    float* attn; cudaGetSymbolAddress((void**)&attn, g_attn);

    prep_kernel<<<1, 256>>>(batch);

    {   // qkv = x @ W_in + b_in  [4096,1024]x[1024,3072]
        dim3 grid(D3 / 128, N_TOK / 128);
        gemm_tf32_bias<<<grid, 256>>>(N_TOK, D3, D_EMB, x, W_in, b_in, qkv);
    }

    {   // segment-local tiled attention
        dim3 grid(MAX_TILES, N_HEADS);
        attn_tiled<<<grid, 256>>>(qkv, attn);
    }

    {   // out = attn @ W_out + b_out  [4096,1024]x[1024,1024]
        dim3 grid(D_EMB / 128, N_TOK / 128);
        gemm_tf32_bias<<<grid, 256>>>(N_TOK, D_EMB, D_EMB, attn, W_out, b_out, out);
    }
}

// round 5
// speedup vs baseline: 2.8968x; 1.0077x over previous
#include <cuda_runtime.h>
#include <cuda_bf16.h>
#include <math.h>

// Problem constants (fixed shapes per reference)
#define N_TOK   4096
#define D_EMB   1024
#define N_HEADS 16
#define D_HEAD  64
#define D3      (3 * D_EMB)   // 3072
#define N_GRAPHS 16

#define TQ 64
#define TK 64
#define MAX_TILES 80   // sum ceil(len/64) <= 4096/64 + 16

// ---------------- scratch (no allocation allowed) ----------------
__device__ float g_qkv[N_TOK * D3];      // [N, 3D]  (q | k | v)
__device__ float g_attn[N_TOK * D_EMB];  // attention output [N, D]
__device__ int   g_batch[N_TOK];
__device__ int   g_seg[N_GRAPHS + 1];
__device__ int   g_tile_seg[MAX_TILES];
__device__ int   g_tile_q0[MAX_TILES];
__device__ int   g_ntiles;

// ---------------- prep: dtype-sniff batch, boundaries, tile worklist ----------------
__global__ void prep_kernel(const void* __restrict__ batch_raw) {
    const int* w32 = (const int*)batch_raw;
    const bool is32 = (w32[N_TOK - 1] != 0);

    for (int i = threadIdx.x; i < N_TOK; i += blockDim.x) {
        int v;
        if (is32) v = w32[i];
        else      v = (int)((const long long*)batch_raw)[i];
        g_batch[i] = v;
    }
    __syncthreads();

    int g = threadIdx.x;
    if (g <= N_GRAPHS) {
        int lo = 0, hi = N_TOK;
        while (lo < hi) {
            int mid = (lo + hi) >> 1;
            if (g_batch[mid] < g) lo = mid + 1; else hi = mid;
        }
        g_seg[g] = lo;
    }
    __syncthreads();

    if (threadIdx.x == 0) {
        int cnt = 0;
        for (int s = 0; s < N_GRAPHS; s++) {
            for (int q = g_seg[s]; q < g_seg[s + 1]; q += TQ) {
                g_tile_seg[cnt] = s;
                g_tile_q0[cnt]  = q;
                cnt++;
            }
        }
        g_ntiles = cnt;
    }
}

// ---------------- tf32 helpers ----------------
__device__ __forceinline__ unsigned f2tf32(float x) {
    unsigned r;
    asm("cvt.rna.tf32.f32 %0, %1;" : "=r"(r) : "f"(x));
    return r;
}

__device__ __forceinline__ void mma_tf32(float* c, const unsigned* a, const unsigned* b) {
    asm volatile(
        "mma.sync.aligned.m16n8k8.row.col.f32.tf32.tf32.f32 "
        "{%0,%1,%2,%3}, {%4,%5,%6,%7}, {%8,%9}, {%0,%1,%2,%3};"
        : "+f"(c[0]), "+f"(c[1]), "+f"(c[2]), "+f"(c[3])
        : "r"(a[0]), "r"(a[1]), "r"(a[2]), "r"(a[3]),
          "r"(b[0]), "r"(b[1]));
}

// ---------------- tf32 tensor-core GEMM with bias (double-buffered) ----------------
// C[M,N] = A[M,K] @ B[K,N] + bias[N]; M,N mult of 128, K mult of 16.
// Block 256 thr = 8 warps (2x4); block tile 128x128, BK=16; warp tile 64x32.
// Smem tiles double-buffered: ONE barrier per k-tile; STS/LDG of tile k+1
// overlap the MMA stream of tile k.
__global__ __launch_bounds__(256, 2)
void gemm_tf32_bias(int M, int N, int K,
                    const float* __restrict__ A,
                    const float* __restrict__ B,
                    const float* __restrict__ bias,
                    float* __restrict__ C)
{
    __shared__ unsigned As[2][2048];  // (kb2:2, mb:8) groups x 32 t x 4 r
    __shared__ unsigned Bs[2][2048];  // (kb2:2, nb:16) groups x 32 t x 2 r

    const int tid  = threadIdx.x;
    const int warp = tid >> 5;
    const int lane = tid & 31;
    const int wm   = warp >> 2;          // 0..1
    const int wn   = warp & 3;           // 0..3
    const int bm   = blockIdx.y * 128;
    const int bn   = blockIdx.x * 128;

    // --- staging lane decomposition (A): conflict-free STS ---
    const int a_c  = lane & 3;
    const int a_d  = (lane >> 2) & 1;
    const int a_g0 = (lane >> 3) & 1;
    const int a_h  = (lane >> 4) & 1;
    const int a_mb = warp;               // m-block 0..7
    // --- staging lane decomposition (B): 2-way STS ---
    const int b_g  = lane & 7;
    const int b_c  = (lane >> 3) & 3;

    float acc[4][4][4];
    #pragma unroll
    for (int i = 0; i < 4; i++)
        #pragma unroll
        for (int j = 0; j < 4; j++)
            #pragma unroll
            for (int r = 0; r < 4; r++) acc[i][j][r] = 0.f;

    float av[8], bv[8];

    auto ldg_tile = [&](int kt) {
        const int k0 = kt << 4;
        #pragma unroll
        for (int gh = 0; gh < 4; gh++)
            #pragma unroll
            for (int kb2 = 0; kb2 < 2; kb2++) {
                int m = a_mb * 16 + a_h * 8 + gh * 2 + a_g0;
                int k = k0 + kb2 * 8 + a_d * 4 + a_c;
                av[gh * 2 + kb2] = A[(size_t)(bm + m) * K + k];
            }
        #pragma unroll
        for (int d2 = 0; d2 < 2; d2++)
            #pragma unroll
            for (int kb2 = 0; kb2 < 2; kb2++)
                #pragma unroll
                for (int nbl = 0; nbl < 2; nbl++) {
                    int n = (warp * 2 + nbl) * 8 + b_g;
                    int k = k0 + kb2 * 8 + d2 * 4 + b_c;
                    bv[(d2 * 2 + kb2) * 2 + nbl] = B[(size_t)k * N + bn + n];
                }
    };

    auto sts_tile = [&](int buf) {
        #pragma unroll
        for (int gh = 0; gh < 4; gh++)
            #pragma unroll
            for (int kb2 = 0; kb2 < 2; kb2++) {
                int g = gh * 2 + a_g0;
                int idx = (((kb2 << 3) + a_mb) << 7) + ((g << 2) + a_c) * 4 + a_h + 2 * a_d;
                As[buf][idx] = f2tf32(av[gh * 2 + kb2]);
            }
        #pragma unroll
        for (int d2 = 0; d2 < 2; d2++)
            #pragma unroll
            for (int kb2 = 0; kb2 < 2; kb2++)
                #pragma unroll
                for (int nbl = 0; nbl < 2; nbl++) {
                    int nb = warp * 2 + nbl;
                    int idx = (((kb2 << 4) + nb) << 6) + ((b_g << 2) + b_c) * 2 + d2;
                    Bs[buf][idx] = f2tf32(bv[(d2 * 2 + kb2) * 2 + nbl]);
                }
    };

    auto compute = [&](int buf) {
        #pragma unroll
        for (int kb2 = 0; kb2 < 2; kb2++) {
            unsigned afr[4][4];
            unsigned bfr[4][2];
            #pragma unroll
            for (int i = 0; i < 4; i++) {
                int grp = kb2 * 8 + wm * 4 + i;
                uint4 t = *reinterpret_cast<const uint4*>(&As[buf][(grp << 7) + (lane << 2)]);
                afr[i][0] = t.x; afr[i][1] = t.y; afr[i][2] = t.z; afr[i][3] = t.w;
            }
            #pragma unroll
            for (int j = 0; j < 4; j++) {
                int grp = kb2 * 16 + wn * 4 + j;
                uint2 t = *reinterpret_cast<const uint2*>(&Bs[buf][(grp << 6) + (lane << 1)]);
                bfr[j][0] = t.x; bfr[j][1] = t.y;
            }
            #pragma unroll
            for (int i = 0; i < 4; i++)
                #pragma unroll
                for (int j = 0; j < 4; j++)
                    mma_tf32(acc[i][j], afr[i], bfr[j]);
        }
    };

    const int KT = K >> 4;

    // prologue: buffer 0 holds tile 0; registers hold tile 1
    ldg_tile(0);
    sts_tile(0);
    ldg_tile(1);
    __syncthreads();

    for (int kt = 0; kt < KT; kt++) {
        const int cur = kt & 1;
        if (kt + 1 < KT) sts_tile(cur ^ 1);   // publish tile kt+1 (regs) to alt buffer
        if (kt + 2 < KT) ldg_tile(kt + 2);    // fetch tile kt+2 into regs
        compute(cur);                          // MMA on tile kt
        __syncthreads();                       // single barrier per k-tile
    }

    // --- epilogue: bias + store ---
    const int lg = lane >> 2;   // 0..7  (row within 8)
    const int lc = lane & 3;    // col pair
    #pragma unroll
    for (int i = 0; i < 4; i++) {
        const int m0 = bm + wm * 64 + i * 16 + lg;
        #pragma unroll
        for (int j = 0; j < 4; j++) {
            const int n0 = bn + wn * 32 + j * 8 + lc * 2;
            const float bx = bias[n0];
            const float by = bias[n0 + 1];
            float2 v0 = make_float2(acc[i][j][0] + bx, acc[i][j][1] + by);
            float2 v1 = make_float2(acc[i][j][2] + bx, acc[i][j][3] + by);
            *reinterpret_cast<float2*>(C + (size_t)m0 * N + n0)       = v0;
            *reinterpret_cast<float2*>(C + (size_t)(m0 + 8) * N + n0) = v1;
        }
    }
}

// ---------------- tiled flash attention (unchanged) ----------------
__global__ __launch_bounds__(256)
void attn_tiled(const float* __restrict__ qkv, float* __restrict__ out)
{
    const int tile = blockIdx.x;
    if (tile >= g_ntiles) return;
    const int h   = blockIdx.y;
    const int seg = g_tile_seg[tile];
    const int q0  = g_tile_q0[tile];
    const int e   = g_seg[seg + 1];
    const int qlen = min(TQ, e - q0);

    __shared__ float Qt[TQ][64];
    __shared__ float KPt[TK][64];
    __shared__ float Vs[TK][64];

    const int tid = threadIdx.x;
    const int tr  = tid >> 4;
    const int tc  = tid & 15;

    {
        const int i  = tid >> 2;
        const int d0 = (tid & 3) * 16;
        const bool valid = (i < qlen);
        const float* src = qkv + (size_t)(q0 + i) * D3 + h * D_HEAD + d0;
        #pragma unroll
        for (int f = 0; f < 4; f++) {
            float4 t = valid ? *reinterpret_cast<const float4*>(src + f * 4)
                             : make_float4(0.f, 0.f, 0.f, 0.f);
            Qt[d0 + f * 4 + 0][i] = t.x;
            Qt[d0 + f * 4 + 1][i] = t.y;
            Qt[d0 + f * 4 + 2][i] = t.z;
            Qt[d0 + f * 4 + 3][i] = t.w;
        }
    }

    float m[4], l[4], O[4][4];
    #pragma unroll
    for (int ii = 0; ii < 4; ii++) {
        m[ii] = -INFINITY; l[ii] = 0.f;
        #pragma unroll
        for (int dd = 0; dd < 4; dd++) O[ii][dd] = 0.f;
    }

    for (int m0 = g_seg[seg]; m0 < e; m0 += TK) {
        const int klen = min(TK, e - m0);
        __syncthreads();

        {
            const int j  = tid >> 2;
            const int d0 = (tid & 3) * 16;
            const bool valid = (j < klen);
            const float* ksrc = qkv + (size_t)(m0 + j) * D3 + D_EMB     + h * D_HEAD + d0;
            const float* vsrc = qkv + (size_t)(m0 + j) * D3 + 2 * D_EMB + h * D_HEAD + d0;
            #pragma unroll
            for (int f = 0; f < 4; f++) {
                float4 t = valid ? *reinterpret_cast<const float4*>(ksrc + f * 4)
                                 : make_float4(0.f, 0.f, 0.f, 0.f);
                KPt[d0 + f * 4 + 0][j] = t.x;
                KPt[d0 + f * 4 + 1][j] = t.y;
                KPt[d0 + f * 4 + 2][j] = t.z;
                KPt[d0 + f * 4 + 3][j] = t.w;
                float4 v = valid ? *reinterpret_cast<const float4*>(vsrc + f * 4)
                                 : make_float4(0.f, 0.f, 0.f, 0.f);
                *reinterpret_cast<float4*>(&Vs[j][d0 + f * 4]) = v;
            }
        }
        __syncthreads();

        float acc[4][4];
        #pragma unroll
        for (int ii = 0; ii < 4; ii++)
            #pragma unroll
            for (int jj = 0; jj < 4; jj++) acc[ii][jj] = 0.f;

        #pragma unroll 8
        for (int d = 0; d < 64; d++) {
            float4 qv = *reinterpret_cast<const float4*>(&Qt[d][tr * 4]);
            float4 kv = *reinterpret_cast<const float4*>(&KPt[d][tc * 4]);
            const float qa[4] = {qv.x, qv.y, qv.z, qv.w};
            const float ka[4] = {kv.x, kv.y, kv.z, kv.w};
            #pragma unroll
            for (int ii = 0; ii < 4; ii++)
                #pragma unroll
                for (int jj = 0; jj < 4; jj++)
                    acc[ii][jj] = fmaf(qa[ii], ka[jj], acc[ii][jj]);
        }

        float p[4][4], corr[4];
        #pragma unroll
        for (int ii = 0; ii < 4; ii++) {
            float rmax = -INFINITY;
            #pragma unroll
            for (int jj = 0; jj < 4; jj++) {
                float sc = (tc * 4 + jj < klen) ? acc[ii][jj] * 0.125f : -INFINITY;
                acc[ii][jj] = sc;
                rmax = fmaxf(rmax, sc);
            }
            #pragma unroll
            for (int o = 1; o < 16; o <<= 1)
                rmax = fmaxf(rmax, __shfl_xor_sync(0xffffffffu, rmax, o));

            const float mnew = fmaxf(m[ii], rmax);
            corr[ii] = __expf(m[ii] - mnew);
            float rsum = 0.f;
            #pragma unroll
            for (int jj = 0; jj < 4; jj++) {
                float pv = __expf(acc[ii][jj] - mnew);
                p[ii][jj] = pv;
                rsum += pv;
            }
            #pragma unroll
            for (int o = 1; o < 16; o <<= 1)
                rsum += __shfl_xor_sync(0xffffffffu, rsum, o);

            l[ii] = fmaf(l[ii], corr[ii], rsum);
            m[ii] = mnew;
            #pragma unroll
            for (int dd = 0; dd < 4; dd++) O[ii][dd] *= corr[ii];
        }

        __syncthreads();

        #pragma unroll
        for (int jj = 0; jj < 4; jj++)
            #pragma unroll
            for (int ii = 0; ii < 4; ii++)
                KPt[tc * 4 + jj][tr * 4 + ii] = p[ii][jj];
        __syncthreads();

        #pragma unroll 8
        for (int j = 0; j < 64; j++) {
            float4 pv = *reinterpret_cast<const float4*>(&KPt[j][tr * 4]);
            float4 vv = *reinterpret_cast<const float4*>(&Vs[j][tc * 4]);
            const float pa[4] = {pv.x, pv.y, pv.z, pv.w};
            const float va[4] = {vv.x, vv.y, vv.z, vv.w};
            #pragma unroll
            for (int ii = 0; ii < 4; ii++)
                #pragma unroll
                for (int dd = 0; dd < 4; dd++)
                    O[ii][dd] = fmaf(pa[ii], va[dd], O[ii][dd]);
        }
    }

    #pragma unroll
    for (int ii = 0; ii < 4; ii++) {
        const int i = tr * 4 + ii;
        if (i < qlen) {
            const float inv = 1.f / l[ii];
            float4 t;
            t.x = O[ii][0] * inv;
            t.y = O[ii][1] * inv;
            t.z = O[ii][2] * inv;
            t.w = O[ii][3] * inv;
            *reinterpret_cast<float4*>(
                out + (size_t)(q0 + i) * D_EMB + h * D_HEAD + tc * 4) = t;
        }
    }
}

// ---------------- launcher ----------------
extern "C" void kernel_launch(void* const* d_in, const int* in_sizes, int n_in,
                              void* d_out, int out_size)
{
    const float* x     = (const float*)d_in[0];
    const void*  batch = d_in[1];
    const float* W_in  = (const float*)d_in[2];
    const float* b_in  = (const float*)d_in[3];
    const float* W_out = (const float*)d_in[4];
    const float* b_out = (const float*)d_in[5];
    float*       out   = (float*)d_out;

    float* qkv;  cudaGetSymbolAddress((void**)&qkv,  g_qkv);
    float* attn; cudaGetSymbolAddress((void**)&attn, g_attn);

    prep_kernel<<<1, 256>>>(batch);

    {   // qkv = x @ W_in + b_in  [4096,1024]x[1024,3072]
        dim3 grid(D3 / 128, N_TOK / 128);
        gemm_tf32_bias<<<grid, 256>>>(N_TOK, D3, D_EMB, x, W_in, b_in, qkv);
    }

    {   // segment-local tiled attention
        dim3 grid(MAX_TILES, N_HEADS);
        attn_tiled<<<grid, 256>>>(qkv, attn);
    }

    {   // out = attn @ W_out + b_out  [4096,1024]x[1024,1024]
        dim3 grid(D_EMB / 128, N_TOK / 128);
        gemm_tf32_bias<<<grid, 256>>>(N_TOK, D_EMB, D_EMB, attn, W_out, b_out, out);
    }
}

// round 6
// speedup vs baseline: 3.0967x; 1.0690x over previous
#include <cuda_runtime.h>
#include <cuda_bf16.h>
#include <math.h>

// Problem constants (fixed shapes per reference)
#define N_TOK   4096
#define D_EMB   1024
#define N_HEADS 16
#define D_HEAD  64
#define D3      (3 * D_EMB)   // 3072
#define N_GRAPHS 16

#define TQ 64
#define TK 64
#define MAX_TILES 80   // sum ceil(len/64) <= 4096/64 + 16

// ---------------- scratch (no allocation allowed) ----------------
__device__ float g_qkv[N_TOK * D3];      // [N, 3D]  (q | k | v)
__device__ float g_attn[N_TOK * D_EMB];  // attention output (tf32-rounded)
__device__ float g_xt[N_TOK * D_EMB];    // x, tf32-rounded
__device__ float g_wit[D_EMB * D3];      // W_in, tf32-rounded
__device__ float g_wot[D_EMB * D_EMB];   // W_out, tf32-rounded
__device__ int   g_batch[N_TOK];
__device__ int   g_seg[N_GRAPHS + 1];
__device__ int   g_tile_seg[MAX_TILES];
__device__ int   g_tile_q0[MAX_TILES];
__device__ int   g_ntiles;

// ---------------- prep: dtype-sniff batch, boundaries, tile worklist ----------------
__global__ void prep_kernel(const void* __restrict__ batch_raw) {
    const int* w32 = (const int*)batch_raw;
    const bool is32 = (w32[N_TOK - 1] != 0);

    for (int i = threadIdx.x; i < N_TOK; i += blockDim.x) {
        int v;
        if (is32) v = w32[i];
        else      v = (int)((const long long*)batch_raw)[i];
        g_batch[i] = v;
    }
    __syncthreads();

    int g = threadIdx.x;
    if (g <= N_GRAPHS) {
        int lo = 0, hi = N_TOK;
        while (lo < hi) {
            int mid = (lo + hi) >> 1;
            if (g_batch[mid] < g) lo = mid + 1; else hi = mid;
        }
        g_seg[g] = lo;
    }
    __syncthreads();

    if (threadIdx.x == 0) {
        int cnt = 0;
        for (int s = 0; s < N_GRAPHS; s++) {
            for (int q = g_seg[s]; q < g_seg[s + 1]; q += TQ) {
                g_tile_seg[cnt] = s;
                g_tile_q0[cnt]  = q;
                cnt++;
            }
        }
        g_ntiles = cnt;
    }
}

// ---------------- tf32 helpers ----------------
__device__ __forceinline__ unsigned f2tf32(float x) {
    unsigned r;
    asm("cvt.rna.tf32.f32 %0, %1;" : "=r"(r) : "f"(x));
    return r;
}

__device__ __forceinline__ void mma_tf32(float* c, const unsigned* a, const unsigned* b) {
    asm volatile(
        "mma.sync.aligned.m16n8k8.row.col.f32.tf32.tf32.f32 "
        "{%0,%1,%2,%3}, {%4,%5,%6,%7}, {%8,%9}, {%0,%1,%2,%3};"
        : "+f"(c[0]), "+f"(c[1]), "+f"(c[2]), "+f"(c[3])
        : "r"(a[0]), "r"(a[1]), "r"(a[2]), "r"(a[3]),
          "r"(b[0]), "r"(b[1]));
}

__device__ __forceinline__ void cp_async16(unsigned smem_addr, const void* gptr) {
    asm volatile("cp.async.ca.shared.global [%0], [%1], 16;"
                 :: "r"(smem_addr), "l"(gptr));
}

// ---------------- elementwise tf32 rounding pass ----------------
__global__ void cvt_tf32_kernel(const float4* __restrict__ in,
                                float4* __restrict__ out, int n4) {
    int i = blockIdx.x * blockDim.x + threadIdx.x;
    if (i < n4) {
        float4 v = in[i];
        float4 r;
        r.x = __uint_as_float(f2tf32(v.x));
        r.y = __uint_as_float(f2tf32(v.y));
        r.z = __uint_as_float(f2tf32(v.z));
        r.w = __uint_as_float(f2tf32(v.w));
        out[i] = r;
    }
}

// ---------------- tf32 GEMM: cp.async staging, pre-rounded inputs ----------------
// C[M,N] = A[M,K] @ B[K,N] + bias[N]; M,N mult of 128, K mult of 32.
// A,B must be tf32-pre-rounded fp32. Block tile 128x128, BK=32; 8 warps (2x4),
// warp tile 64x32. Double-buffered smem loaded with LDGSTS.128.
#define A_STRIDE 36          // words; banks for a-frag = 4q+c (distinct)
#define B_STRIDE 136         // words; 136%32==8 -> banks 8c+q (distinct)
#define A_SZ (128 * A_STRIDE)
#define B_SZ (32 * B_STRIDE)
#define GEMM_SMEM ((2 * A_SZ + 2 * B_SZ) * 4)

__global__ __launch_bounds__(256, 2)
void gemm_tf32_cp(int M, int N, int K,
                  const float* __restrict__ A,
                  const float* __restrict__ B,
                  const float* __restrict__ bias,
                  float* __restrict__ C)
{
    extern __shared__ float smem[];
    float* As = smem;                // 2 x 128 x A_STRIDE
    float* Bs = smem + 2 * A_SZ;     // 2 x 32  x B_STRIDE

    const int tid  = threadIdx.x;
    const int warp = tid >> 5;
    const int lane = tid & 31;
    const int wm   = warp >> 2;      // 0..1
    const int wn   = warp & 3;       // 0..3
    const int bm   = blockIdx.y * 128;
    const int bn   = blockIdx.x * 128;

    const unsigned a_smem0 = (unsigned)__cvta_generic_to_shared(As);
    const unsigned b_smem0 = (unsigned)__cvta_generic_to_shared(Bs);

    // cp.async thread mapping
    const int a_row  = tid >> 1;            // 0..127
    const int a_half = tid & 1;             // 16-float half of 32-float row chunk
    const int b_chk  = tid & 31;            // 16B chunk within 512B row
    const int b_rb   = tid >> 5;            // k-row base (0..7), +8 per step

    const float* aSrcBase = A + (size_t)(bm + a_row) * K + a_half * 16;
    const unsigned aDst   = a_smem0 + (unsigned)(a_row * A_STRIDE + a_half * 16) * 4u;
    const float* bSrcBase = B + (size_t)b_rb * N + bn + b_chk * 4;
    const unsigned bDst   = b_smem0 + (unsigned)(b_rb * B_STRIDE + b_chk * 4) * 4u;

    auto cp_tile = [&](int kt, int buf) {
        const int k0 = kt << 5;
        const float* as = aSrcBase + k0;
        const unsigned ad = aDst + (unsigned)(buf * A_SZ) * 4u;
        #pragma unroll
        for (int j = 0; j < 4; j++)
            cp_async16(ad + j * 16u, as + j * 4);
        const float* bs = bSrcBase + (size_t)k0 * N;
        const unsigned bd = bDst + (unsigned)(buf * B_SZ) * 4u;
        #pragma unroll
        for (int jj = 0; jj < 4; jj++)
            cp_async16(bd + (unsigned)(jj * 8 * B_STRIDE) * 4u,
                       bs + (size_t)(jj * 8) * N);
        asm volatile("cp.async.commit_group;");
    };

    float acc[4][4][4];
    #pragma unroll
    for (int i = 0; i < 4; i++)
        #pragma unroll
        for (int j = 0; j < 4; j++)
            #pragma unroll
            for (int r = 0; r < 4; r++) acc[i][j][r] = 0.f;

    // per-lane fragment offsets
    const int aq = lane >> 2;   // row within 8
    const int ac = lane & 3;    // k within 4
    const int a_base_off = aq * A_STRIDE + ac;          // + row*A_STRIDE + k
    const int b_base_off = ac * B_STRIDE + (lane >> 2); // + k*B_STRIDE + n

    const int KT = K >> 5;
    cp_tile(0, 0);

    for (int kt = 0; kt < KT; kt++) {
        const int buf = kt & 1;
        asm volatile("cp.async.wait_group 0;");
        __syncthreads();
        if (kt + 1 < KT) cp_tile(kt + 1, buf ^ 1);

        const float* a = As + buf * A_SZ;
        const float* b = Bs + buf * B_SZ;

        #pragma unroll
        for (int kb = 0; kb < 4; kb++) {
            unsigned afr[4][4];
            unsigned bfr[4][2];
            #pragma unroll
            for (int i = 0; i < 4; i++) {
                const int base = (wm * 64 + i * 16) * A_STRIDE + kb * 8 + a_base_off;
                afr[i][0] = __float_as_uint(a[base]);
                afr[i][1] = __float_as_uint(a[base + 8 * A_STRIDE]);
                afr[i][2] = __float_as_uint(a[base + 4]);
                afr[i][3] = __float_as_uint(a[base + 8 * A_STRIDE + 4]);
            }
            #pragma unroll
            for (int j = 0; j < 4; j++) {
                const int base = kb * 8 * B_STRIDE + wn * 32 + j * 8 + b_base_off;
                bfr[j][0] = __float_as_uint(b[base]);
                bfr[j][1] = __float_as_uint(b[base + 4 * B_STRIDE]);
            }
            #pragma unroll
            for (int i = 0; i < 4; i++)
                #pragma unroll
                for (int j = 0; j < 4; j++)
                    mma_tf32(acc[i][j], afr[i], bfr[j]);
        }
        __syncthreads();
    }

    // --- epilogue: bias + store ---
    const int lg = lane >> 2;
    const int lc = lane & 3;
    #pragma unroll
    for (int i = 0; i < 4; i++) {
        const int m0 = bm + wm * 64 + i * 16 + lg;
        #pragma unroll
        for (int j = 0; j < 4; j++) {
            const int n0 = bn + wn * 32 + j * 8 + lc * 2;
            const float bx = bias[n0];
            const float by = bias[n0 + 1];
            float2 v0 = make_float2(acc[i][j][0] + bx, acc[i][j][1] + by);
            float2 v1 = make_float2(acc[i][j][2] + bx, acc[i][j][3] + by);
            *reinterpret_cast<float2*>(C + (size_t)m0 * N + n0)       = v0;
            *reinterpret_cast<float2*>(C + (size_t)(m0 + 8) * N + n0) = v1;
        }
    }
}

// ---------------- tiled flash attention (output tf32-rounded for GEMM2) ----------------
__global__ __launch_bounds__(256)
void attn_tiled(const float* __restrict__ qkv, float* __restrict__ out)
{
    const int tile = blockIdx.x;
    if (tile >= g_ntiles) return;
    const int h   = blockIdx.y;
    const int seg = g_tile_seg[tile];
    const int q0  = g_tile_q0[tile];
    const int e   = g_seg[seg + 1];
    const int qlen = min(TQ, e - q0);

    __shared__ float Qt[TQ][64];
    __shared__ float KPt[TK][64];
    __shared__ float Vs[TK][64];

    const int tid = threadIdx.x;
    const int tr  = tid >> 4;
    const int tc  = tid & 15;

    {
        const int i  = tid >> 2;
        const int d0 = (tid & 3) * 16;
        const bool valid = (i < qlen);
        const float* src = qkv + (size_t)(q0 + i) * D3 + h * D_HEAD + d0;
        #pragma unroll
        for (int f = 0; f < 4; f++) {
            float4 t = valid ? *reinterpret_cast<const float4*>(src + f * 4)
                             : make_float4(0.f, 0.f, 0.f, 0.f);
            Qt[d0 + f * 4 + 0][i] = t.x;
            Qt[d0 + f * 4 + 1][i] = t.y;
            Qt[d0 + f * 4 + 2][i] = t.z;
            Qt[d0 + f * 4 + 3][i] = t.w;
        }
    }

    float m[4], l[4], O[4][4];
    #pragma unroll
    for (int ii = 0; ii < 4; ii++) {
        m[ii] = -INFINITY; l[ii] = 0.f;
        #pragma unroll
        for (int dd = 0; dd < 4; dd++) O[ii][dd] = 0.f;
    }

    for (int m0 = g_seg[seg]; m0 < e; m0 += TK) {
        const int klen = min(TK, e - m0);
        __syncthreads();

        {
            const int j  = tid >> 2;
            const int d0 = (tid & 3) * 16;
            const bool valid = (j < klen);
            const float* ksrc = qkv + (size_t)(m0 + j) * D3 + D_EMB     + h * D_HEAD + d0;
            const float* vsrc = qkv + (size_t)(m0 + j) * D3 + 2 * D_EMB + h * D_HEAD + d0;
            #pragma unroll
            for (int f = 0; f < 4; f++) {
                float4 t = valid ? *reinterpret_cast<const float4*>(ksrc + f * 4)
                                 : make_float4(0.f, 0.f, 0.f, 0.f);
                KPt[d0 + f * 4 + 0][j] = t.x;
                KPt[d0 + f * 4 + 1][j] = t.y;
                KPt[d0 + f * 4 + 2][j] = t.z;
                KPt[d0 + f * 4 + 3][j] = t.w;
                float4 v = valid ? *reinterpret_cast<const float4*>(vsrc + f * 4)
                                 : make_float4(0.f, 0.f, 0.f, 0.f);
                *reinterpret_cast<float4*>(&Vs[j][d0 + f * 4]) = v;
            }
        }
        __syncthreads();

        float acc[4][4];
        #pragma unroll
        for (int ii = 0; ii < 4; ii++)
            #pragma unroll
            for (int jj = 0; jj < 4; jj++) acc[ii][jj] = 0.f;

        #pragma unroll 8
        for (int d = 0; d < 64; d++) {
            float4 qv = *reinterpret_cast<const float4*>(&Qt[d][tr * 4]);
            float4 kv = *reinterpret_cast<const float4*>(&KPt[d][tc * 4]);
            const float qa[4] = {qv.x, qv.y, qv.z, qv.w};
            const float ka[4] = {kv.x, kv.y, kv.z, kv.w};
            #pragma unroll
            for (int ii = 0; ii < 4; ii++)
                #pragma unroll
                for (int jj = 0; jj < 4; jj++)
                    acc[ii][jj] = fmaf(qa[ii], ka[jj], acc[ii][jj]);
        }

        float p[4][4], corr[4];
        #pragma unroll
        for (int ii = 0; ii < 4; ii++) {
            float rmax = -INFINITY;
            #pragma unroll
            for (int jj = 0; jj < 4; jj++) {
                float sc = (tc * 4 + jj < klen) ? acc[ii][jj] * 0.125f : -INFINITY;
                acc[ii][jj] = sc;
                rmax = fmaxf(rmax, sc);
            }
            #pragma unroll
            for (int o = 1; o < 16; o <<= 1)
                rmax = fmaxf(rmax, __shfl_xor_sync(0xffffffffu, rmax, o));

            const float mnew = fmaxf(m[ii], rmax);
            corr[ii] = __expf(m[ii] - mnew);
            float rsum = 0.f;
            #pragma unroll
            for (int jj = 0; jj < 4; jj++) {
                float pv = __expf(acc[ii][jj] - mnew);
                p[ii][jj] = pv;
                rsum += pv;
            }
            #pragma unroll
            for (int o = 1; o < 16; o <<= 1)
                rsum += __shfl_xor_sync(0xffffffffu, rsum, o);

            l[ii] = fmaf(l[ii], corr[ii], rsum);
            m[ii] = mnew;
            #pragma unroll
            for (int dd = 0; dd < 4; dd++) O[ii][dd] *= corr[ii];
        }

        __syncthreads();

        #pragma unroll
        for (int jj = 0; jj < 4; jj++)
            #pragma unroll
            for (int ii = 0; ii < 4; ii++)
                KPt[tc * 4 + jj][tr * 4 + ii] = p[ii][jj];
        __syncthreads();

        #pragma unroll 8
        for (int j = 0; j < 64; j++) {
            float4 pv = *reinterpret_cast<const float4*>(&KPt[j][tr * 4]);
            float4 vv = *reinterpret_cast<const float4*>(&Vs[j][tc * 4]);
            const float pa[4] = {pv.x, pv.y, pv.z, pv.w};
            const float va[4] = {vv.x, vv.y, vv.z, vv.w};
            #pragma unroll
            for (int ii = 0; ii < 4; ii++)
                #pragma unroll
                for (int dd = 0; dd < 4; dd++)
                    O[ii][dd] = fmaf(pa[ii], va[dd], O[ii][dd]);
        }
    }

    #pragma unroll
    for (int ii = 0; ii < 4; ii++) {
        const int i = tr * 4 + ii;
        if (i < qlen) {
            const float inv = 1.f / l[ii];
            float4 t;   // tf32-round here: GEMM2 consumes this as pre-rounded A
            t.x = __uint_as_float(f2tf32(O[ii][0] * inv));
            t.y = __uint_as_float(f2tf32(O[ii][1] * inv));
            t.z = __uint_as_float(f2tf32(O[ii][2] * inv));
            t.w = __uint_as_float(f2tf32(O[ii][3] * inv));
            *reinterpret_cast<float4*>(
                out + (size_t)(q0 + i) * D_EMB + h * D_HEAD + tc * 4) = t;
        }
    }
}

// ---------------- launcher ----------------
extern "C" void kernel_launch(void* const* d_in, const int* in_sizes, int n_in,
                              void* d_out, int out_size)
{
    const float* x     = (const float*)d_in[0];
    const void*  batch = d_in[1];
    const float* W_in  = (const float*)d_in[2];
    const float* b_in  = (const float*)d_in[3];
    const float* W_out = (const float*)d_in[4];
    const float* b_out = (const float*)d_in[5];
    float*       out   = (float*)d_out;

    float* qkv;  cudaGetSymbolAddress((void**)&qkv,  g_qkv);
    float* attn; cudaGetSymbolAddress((void**)&attn, g_attn);
    float* xt;   cudaGetSymbolAddress((void**)&xt,   g_xt);
    float* wit;  cudaGetSymbolAddress((void**)&wit,  g_wit);
    float* wot;  cudaGetSymbolAddress((void**)&wot,  g_wot);

    cudaFuncSetAttribute(gemm_tf32_cp,
                         cudaFuncAttributeMaxDynamicSharedMemorySize, GEMM_SMEM);

    prep_kernel<<<1, 256>>>(batch);

    // tf32 pre-rounding passes
    {
        int n4 = (N_TOK * D_EMB) / 4;
        cvt_tf32_kernel<<<(n4 + 255) / 256, 256>>>((const float4*)x, (float4*)xt, n4);
        n4 = (D_EMB * D3) / 4;
        cvt_tf32_kernel<<<(n4 + 255) / 256, 256>>>((const float4*)W_in, (float4*)wit, n4);
        n4 = (D_EMB * D_EMB) / 4;
        cvt_tf32_kernel<<<(n4 + 255) / 256, 256>>>((const float4*)W_out, (float4*)wot, n4);
    }

    {   // qkv = x @ W_in + b_in  [4096,1024]x[1024,3072]
        dim3 grid(D3 / 128, N_TOK / 128);
        gemm_tf32_cp<<<grid, 256, GEMM_SMEM>>>(N_TOK, D3, D_EMB, xt, wit, b_in, qkv);
    }

    {   // segment-local tiled attention (emits tf32-rounded output)
        dim3 grid(MAX_TILES, N_HEADS);
        attn_tiled<<<grid, 256>>>(qkv, attn);
    }

    {   // out = attn @ W_out + b_out  [4096,1024]x[1024,1024]
        dim3 grid(D_EMB / 128, N_TOK / 128);
        gemm_tf32_cp<<<grid, 256, GEMM_SMEM>>>(N_TOK, D_EMB, D_EMB, attn, wot, b_out, out);
    }
}

// round 7
// speedup vs baseline: 3.2725x; 1.0568x over previous
#include <cuda_runtime.h>
#include <cuda_bf16.h>
#include <math.h>

// Problem constants (fixed shapes per reference)
#define N_TOK   4096
#define D_EMB   1024
#define N_HEADS 16
#define D_HEAD  64
#define D3      (3 * D_EMB)   // 3072
#define N_GRAPHS 16

#define TQ 64
#define TK 64
#define MAX_TILES 80   // sum ceil(len/64) <= 4096/64 + 16

// ---------------- scratch (no allocation allowed) ----------------
__device__ float g_qkv[N_TOK * D3];      // [N, 3D]  (q | k | v)
__device__ float g_attn[N_TOK * D_EMB];  // attention output (tf32-rounded)
__device__ float g_xt[N_TOK * D_EMB];    // x, tf32-rounded
__device__ float g_wit[D_EMB * D3];      // W_in, tf32-rounded
__device__ float g_wot[D_EMB * D_EMB];   // W_out, tf32-rounded
__device__ int   g_batch[N_TOK];
__device__ int   g_seg[N_GRAPHS + 1];
__device__ int   g_tile_seg[MAX_TILES];
__device__ int   g_tile_q0[MAX_TILES];
__device__ int   g_ntiles;

// ---------------- prep: dtype-sniff batch, boundaries, tile worklist ----------------
__global__ void prep_kernel(const void* __restrict__ batch_raw) {
    const int* w32 = (const int*)batch_raw;
    const bool is32 = (w32[N_TOK - 1] != 0);

    for (int i = threadIdx.x; i < N_TOK; i += blockDim.x) {
        int v;
        if (is32) v = w32[i];
        else      v = (int)((const long long*)batch_raw)[i];
        g_batch[i] = v;
    }
    __syncthreads();

    int g = threadIdx.x;
    if (g <= N_GRAPHS) {
        int lo = 0, hi = N_TOK;
        while (lo < hi) {
            int mid = (lo + hi) >> 1;
            if (g_batch[mid] < g) lo = mid + 1; else hi = mid;
        }
        g_seg[g] = lo;
    }
    __syncthreads();

    if (threadIdx.x == 0) {
        int cnt = 0;
        for (int s = 0; s < N_GRAPHS; s++) {
            for (int q = g_seg[s]; q < g_seg[s + 1]; q += TQ) {
                g_tile_seg[cnt] = s;
                g_tile_q0[cnt]  = q;
                cnt++;
            }
        }
        g_ntiles = cnt;
    }
}

// ---------------- tf32 helpers ----------------
__device__ __forceinline__ unsigned f2tf32(float x) {
    unsigned r;
    asm("cvt.rna.tf32.f32 %0, %1;" : "=r"(r) : "f"(x));
    return r;
}

__device__ __forceinline__ void mma_tf32(float* c, const unsigned* a, const unsigned* b) {
    asm volatile(
        "mma.sync.aligned.m16n8k8.row.col.f32.tf32.tf32.f32 "
        "{%0,%1,%2,%3}, {%4,%5,%6,%7}, {%8,%9}, {%0,%1,%2,%3};"
        : "+f"(c[0]), "+f"(c[1]), "+f"(c[2]), "+f"(c[3])
        : "r"(a[0]), "r"(a[1]), "r"(a[2]), "r"(a[3]),
          "r"(b[0]), "r"(b[1]));
}

__device__ __forceinline__ void cp_async16(unsigned smem_addr, const void* gptr) {
    asm volatile("cp.async.ca.shared.global [%0], [%1], 16;"
                 :: "r"(smem_addr), "l"(gptr));
}

// ---------------- elementwise tf32 rounding pass ----------------
__global__ void cvt_tf32_kernel(const float4* __restrict__ in,
                                float4* __restrict__ out, int n4) {
    int i = blockIdx.x * blockDim.x + threadIdx.x;
    if (i < n4) {
        float4 v = in[i];
        float4 r;
        r.x = __uint_as_float(f2tf32(v.x));
        r.y = __uint_as_float(f2tf32(v.y));
        r.z = __uint_as_float(f2tf32(v.z));
        r.w = __uint_as_float(f2tf32(v.w));
        out[i] = r;
    }
}

// ---------------- tf32 GEMM: block 128x256, warp tile 64x64, cp.async ----------------
// C[M,N] = A[M,K] @ B[K,N] + bias[N]; M mult of 128, N mult of 256, K mult of 32.
// A,B must be tf32-pre-rounded fp32. 8 warps (2x4), each owning 64x64.
// Fragment traffic: 128B/MMA (was 192) -> smem crossbar no longer the limiter.
#define A_STRIDE 36          // words; a-frag banks = 4q+c (distinct)
#define B_STRIDE 264         // words; 264%32==8 -> b-frag banks 8c+q (distinct)
#define A_SZ (128 * A_STRIDE)
#define B_SZ (32 * B_STRIDE)
#define GEMM_SMEM ((2 * A_SZ + 2 * B_SZ) * 4)

__global__ __launch_bounds__(256, 1)
void gemm_tf32_cp(int M, int N, int K,
                  const float* __restrict__ A,
                  const float* __restrict__ B,
                  const float* __restrict__ bias,
                  float* __restrict__ C)
{
    extern __shared__ float smem[];
    float* As = smem;                // 2 x 128 x A_STRIDE
    float* Bs = smem + 2 * A_SZ;     // 2 x 32  x B_STRIDE

    const int tid  = threadIdx.x;
    const int warp = tid >> 5;
    const int lane = tid & 31;
    const int wm   = warp >> 2;      // 0..1  -> m offset wm*64
    const int wn   = warp & 3;       // 0..3  -> n offset wn*64
    const int bm   = blockIdx.y * 128;
    const int bn   = blockIdx.x * 256;

    const unsigned a_smem0 = (unsigned)__cvta_generic_to_shared(As);
    const unsigned b_smem0 = (unsigned)__cvta_generic_to_shared(Bs);

    // cp.async thread mapping
    const int a_row  = tid >> 1;            // 0..127
    const int a_half = tid & 1;             // which 64B half of the 128B row
    const int b_chk  = tid & 63;            // 16B chunk within 1KB row
    const int b_rb   = tid >> 6;            // k-row base 0..3, +4 per step

    const float* aSrcBase = A + (size_t)(bm + a_row) * K + a_half * 16;
    const unsigned aDst   = a_smem0 + (unsigned)(a_row * A_STRIDE + a_half * 16) * 4u;
    const float* bSrcBase = B + (size_t)b_rb * N + bn + b_chk * 4;
    const unsigned bDst   = b_smem0 + (unsigned)(b_rb * B_STRIDE + b_chk * 4) * 4u;

    auto cp_tile = [&](int kt, int buf) {
        const int k0 = kt << 5;
        const float* as = aSrcBase + k0;
        const unsigned ad = aDst + (unsigned)(buf * A_SZ) * 4u;
        #pragma unroll
        for (int j = 0; j < 4; j++)
            cp_async16(ad + j * 16u, as + j * 4);
        const float* bs = bSrcBase + (size_t)k0 * N;
        const unsigned bd = bDst + (unsigned)(buf * B_SZ) * 4u;
        #pragma unroll
        for (int jj = 0; jj < 8; jj++)
            cp_async16(bd + (unsigned)(jj * 4 * B_STRIDE) * 4u,
                       bs + (size_t)(jj * 4) * N);
        asm volatile("cp.async.commit_group;");
    };

    float acc[4][8][4];
    #pragma unroll
    for (int i = 0; i < 4; i++)
        #pragma unroll
        for (int j = 0; j < 8; j++)
            #pragma unroll
            for (int r = 0; r < 4; r++) acc[i][j][r] = 0.f;

    // per-lane fragment offsets
    const int aq = lane >> 2;   // row within 8
    const int ac = lane & 3;    // k within 4
    const int a_base_off = aq * A_STRIDE + ac;
    const int b_base_off = ac * B_STRIDE + aq;

    const int KT = K >> 5;
    cp_tile(0, 0);

    for (int kt = 0; kt < KT; kt++) {
        const int buf = kt & 1;
        asm volatile("cp.async.wait_group 0;");
        __syncthreads();
        if (kt + 1 < KT) cp_tile(kt + 1, buf ^ 1);

        const float* a = As + buf * A_SZ;
        const float* b = Bs + buf * B_SZ;

        #pragma unroll
        for (int kb = 0; kb < 4; kb++) {
            unsigned afr[4][4];
            #pragma unroll
            for (int i = 0; i < 4; i++) {
                const int base = (wm * 64 + i * 16) * A_STRIDE + kb * 8 + a_base_off;
                afr[i][0] = __float_as_uint(a[base]);
                afr[i][1] = __float_as_uint(a[base + 8 * A_STRIDE]);
                afr[i][2] = __float_as_uint(a[base + 4]);
                afr[i][3] = __float_as_uint(a[base + 8 * A_STRIDE + 4]);
            }
            #pragma unroll
            for (int j = 0; j < 8; j++) {
                unsigned bfr[2];
                const int base = kb * 8 * B_STRIDE + wn * 64 + j * 8 + b_base_off;
                bfr[0] = __float_as_uint(b[base]);
                bfr[1] = __float_as_uint(b[base + 4 * B_STRIDE]);
                #pragma unroll
                for (int i = 0; i < 4; i++)
                    mma_tf32(acc[i][j], afr[i], bfr);
            }
        }
        __syncthreads();
    }

    // --- epilogue: bias + store ---
    const int lg = lane >> 2;
    const int lc = lane & 3;
    #pragma unroll
    for (int i = 0; i < 4; i++) {
        const int m0 = bm + wm * 64 + i * 16 + lg;
        #pragma unroll
        for (int j = 0; j < 8; j++) {
            const int n0 = bn + wn * 64 + j * 8 + lc * 2;
            const float bx = bias[n0];
            const float by = bias[n0 + 1];
            float2 v0 = make_float2(acc[i][j][0] + bx, acc[i][j][1] + by);
            float2 v1 = make_float2(acc[i][j][2] + bx, acc[i][j][3] + by);
            *reinterpret_cast<float2*>(C + (size_t)m0 * N + n0)       = v0;
            *reinterpret_cast<float2*>(C + (size_t)(m0 + 8) * N + n0) = v1;
        }
    }
}

// ---------------- tiled flash attention (output tf32-rounded for GEMM2) ----------------
__global__ __launch_bounds__(256)
void attn_tiled(const float* __restrict__ qkv, float* __restrict__ out)
{
    const int tile = blockIdx.x;
    if (tile >= g_ntiles) return;
    const int h   = blockIdx.y;
    const int seg = g_tile_seg[tile];
    const int q0  = g_tile_q0[tile];
    const int e   = g_seg[seg + 1];
    const int qlen = min(TQ, e - q0);

    __shared__ float Qt[TQ][64];
    __shared__ float KPt[TK][64];
    __shared__ float Vs[TK][64];

    const int tid = threadIdx.x;
    const int tr  = tid >> 4;
    const int tc  = tid & 15;

    {
        const int i  = tid >> 2;
        const int d0 = (tid & 3) * 16;
        const bool valid = (i < qlen);
        const float* src = qkv + (size_t)(q0 + i) * D3 + h * D_HEAD + d0;
        #pragma unroll
        for (int f = 0; f < 4; f++) {
            float4 t = valid ? *reinterpret_cast<const float4*>(src + f * 4)
                             : make_float4(0.f, 0.f, 0.f, 0.f);
            Qt[d0 + f * 4 + 0][i] = t.x;
            Qt[d0 + f * 4 + 1][i] = t.y;
            Qt[d0 + f * 4 + 2][i] = t.z;
            Qt[d0 + f * 4 + 3][i] = t.w;
        }
    }

    float m[4], l[4], O[4][4];
    #pragma unroll
    for (int ii = 0; ii < 4; ii++) {
        m[ii] = -INFINITY; l[ii] = 0.f;
        #pragma unroll
        for (int dd = 0; dd < 4; dd++) O[ii][dd] = 0.f;
    }

    for (int m0 = g_seg[seg]; m0 < e; m0 += TK) {
        const int klen = min(TK, e - m0);
        __syncthreads();

        {
            const int j  = tid >> 2;
            const int d0 = (tid & 3) * 16;
            const bool valid = (j < klen);
            const float* ksrc = qkv + (size_t)(m0 + j) * D3 + D_EMB     + h * D_HEAD + d0;
            const float* vsrc = qkv + (size_t)(m0 + j) * D3 + 2 * D_EMB + h * D_HEAD + d0;
            #pragma unroll
            for (int f = 0; f < 4; f++) {
                float4 t = valid ? *reinterpret_cast<const float4*>(ksrc + f * 4)
                                 : make_float4(0.f, 0.f, 0.f, 0.f);
                KPt[d0 + f * 4 + 0][j] = t.x;
                KPt[d0 + f * 4 + 1][j] = t.y;
                KPt[d0 + f * 4 + 2][j] = t.z;
                KPt[d0 + f * 4 + 3][j] = t.w;
                float4 v = valid ? *reinterpret_cast<const float4*>(vsrc + f * 4)
                                 : make_float4(0.f, 0.f, 0.f, 0.f);
                *reinterpret_cast<float4*>(&Vs[j][d0 + f * 4]) = v;
            }
        }
        __syncthreads();

        float acc[4][4];
        #pragma unroll
        for (int ii = 0; ii < 4; ii++)
            #pragma unroll
            for (int jj = 0; jj < 4; jj++) acc[ii][jj] = 0.f;

        #pragma unroll 8
        for (int d = 0; d < 64; d++) {
            float4 qv = *reinterpret_cast<const float4*>(&Qt[d][tr * 4]);
            float4 kv = *reinterpret_cast<const float4*>(&KPt[d][tc * 4]);
            const float qa[4] = {qv.x, qv.y, qv.z, qv.w};
            const float ka[4] = {kv.x, kv.y, kv.z, kv.w};
            #pragma unroll
            for (int ii = 0; ii < 4; ii++)
                #pragma unroll
                for (int jj = 0; jj < 4; jj++)
                    acc[ii][jj] = fmaf(qa[ii], ka[jj], acc[ii][jj]);
        }

        float p[4][4], corr[4];
        #pragma unroll
        for (int ii = 0; ii < 4; ii++) {
            float rmax = -INFINITY;
            #pragma unroll
            for (int jj = 0; jj < 4; jj++) {
                float sc = (tc * 4 + jj < klen) ? acc[ii][jj] * 0.125f : -INFINITY;
                acc[ii][jj] = sc;
                rmax = fmaxf(rmax, sc);
            }
            #pragma unroll
            for (int o = 1; o < 16; o <<= 1)
                rmax = fmaxf(rmax, __shfl_xor_sync(0xffffffffu, rmax, o));

            const float mnew = fmaxf(m[ii], rmax);
            corr[ii] = __expf(m[ii] - mnew);
            float rsum = 0.f;
            #pragma unroll
            for (int jj = 0; jj < 4; jj++) {
                float pv = __expf(acc[ii][jj] - mnew);
                p[ii][jj] = pv;
                rsum += pv;
            }
            #pragma unroll
            for (int o = 1; o < 16; o <<= 1)
                rsum += __shfl_xor_sync(0xffffffffu, rsum, o);

            l[ii] = fmaf(l[ii], corr[ii], rsum);
            m[ii] = mnew;
            #pragma unroll
            for (int dd = 0; dd < 4; dd++) O[ii][dd] *= corr[ii];
        }

        __syncthreads();

        #pragma unroll
        for (int jj = 0; jj < 4; jj++)
            #pragma unroll
            for (int ii = 0; ii < 4; ii++)
                KPt[tc * 4 + jj][tr * 4 + ii] = p[ii][jj];
        __syncthreads();

        #pragma unroll 8
        for (int j = 0; j < 64; j++) {
            float4 pv = *reinterpret_cast<const float4*>(&KPt[j][tr * 4]);
            float4 vv = *reinterpret_cast<const float4*>(&Vs[j][tc * 4]);
            const float pa[4] = {pv.x, pv.y, pv.z, pv.w};
            const float va[4] = {vv.x, vv.y, vv.z, vv.w};
            #pragma unroll
            for (int ii = 0; ii < 4; ii++)
                #pragma unroll
                for (int dd = 0; dd < 4; dd++)
                    O[ii][dd] = fmaf(pa[ii], va[dd], O[ii][dd]);
        }
    }

    #pragma unroll
    for (int ii = 0; ii < 4; ii++) {
        const int i = tr * 4 + ii;
        if (i < qlen) {
            const float inv = 1.f / l[ii];
            float4 t;   // tf32-round here: GEMM2 consumes this as pre-rounded A
            t.x = __uint_as_float(f2tf32(O[ii][0] * inv));
            t.y = __uint_as_float(f2tf32(O[ii][1] * inv));
            t.z = __uint_as_float(f2tf32(O[ii][2] * inv));
            t.w = __uint_as_float(f2tf32(O[ii][3] * inv));
            *reinterpret_cast<float4*>(
                out + (size_t)(q0 + i) * D_EMB + h * D_HEAD + tc * 4) = t;
        }
    }
}

// ---------------- launcher ----------------
extern "C" void kernel_launch(void* const* d_in, const int* in_sizes, int n_in,
                              void* d_out, int out_size)
{
    const float* x     = (const float*)d_in[0];
    const void*  batch = d_in[1];
    const float* W_in  = (const float*)d_in[2];
    const float* b_in  = (const float*)d_in[3];
    const float* W_out = (const float*)d_in[4];
    const float* b_out = (const float*)d_in[5];
    float*       out   = (float*)d_out;

    float* qkv;  cudaGetSymbolAddress((void**)&qkv,  g_qkv);
    float* attn; cudaGetSymbolAddress((void**)&attn, g_attn);
    float* xt;   cudaGetSymbolAddress((void**)&xt,   g_xt);
    float* wit;  cudaGetSymbolAddress((void**)&wit,  g_wit);
    float* wot;  cudaGetSymbolAddress((void**)&wot,  g_wot);

    cudaFuncSetAttribute(gemm_tf32_cp,
                         cudaFuncAttributeMaxDynamicSharedMemorySize, GEMM_SMEM);

    prep_kernel<<<1, 256>>>(batch);

    // tf32 pre-rounding passes
    {
        int n4 = (N_TOK * D_EMB) / 4;
        cvt_tf32_kernel<<<(n4 + 255) / 256, 256>>>((const float4*)x, (float4*)xt, n4);
        n4 = (D_EMB * D3) / 4;
        cvt_tf32_kernel<<<(n4 + 255) / 256, 256>>>((const float4*)W_in, (float4*)wit, n4);
        n4 = (D_EMB * D_EMB) / 4;
        cvt_tf32_kernel<<<(n4 + 255) / 256, 256>>>((const float4*)W_out, (float4*)wot, n4);
    }

    {   // qkv = x @ W_in + b_in  [4096,1024]x[1024,3072]
        dim3 grid(D3 / 256, N_TOK / 128);
        gemm_tf32_cp<<<grid, 256, GEMM_SMEM>>>(N_TOK, D3, D_EMB, xt, wit, b_in, qkv);
    }

    {   // segment-local tiled attention (emits tf32-rounded output)
        dim3 grid(MAX_TILES, N_HEADS);
        attn_tiled<<<grid, 256>>>(qkv, attn);
    }

    {   // out = attn @ W_out + b_out  [4096,1024]x[1024,1024]
        dim3 grid(D_EMB / 256, N_TOK / 128);
        gemm_tf32_cp<<<grid, 256, GEMM_SMEM>>>(N_TOK, D_EMB, D_EMB, attn, wot, b_out, out);
    }
}

// round 9
// speedup vs baseline: 4.1439x; 1.2663x over previous
#include <cuda_runtime.h>
#include <cuda_bf16.h>
#include <math.h>

// Problem constants (fixed shapes per reference)
#define N_TOK   4096
#define D_EMB   1024
#define N_HEADS 16
#define D_HEAD  64
#define D3      (3 * D_EMB)   // 3072
#define N_GRAPHS 16

#define TQ 64
#define TK 64
#define MAX_TILES 80

// ---------------- scratch (no allocation allowed) ----------------
__device__ float g_qkv[N_TOK * D3];
__device__ float g_attn[N_TOK * D_EMB];  // attention output (tf32-rounded)
__device__ float g_xt[N_TOK * D_EMB];    // x, tf32-rounded
__device__ float g_wit[D_EMB * D3];      // W_in, tf32-rounded
__device__ float g_wot[D_EMB * D_EMB];   // W_out, tf32-rounded
__device__ int   g_batch[N_TOK];
__device__ int   g_seg[N_GRAPHS + 1];
__device__ int   g_tile_seg[MAX_TILES];
__device__ int   g_tile_q0[MAX_TILES];
__device__ int   g_ntiles;

// ---------------- prep ----------------
__global__ void prep_kernel(const void* __restrict__ batch_raw) {
    const int* w32 = (const int*)batch_raw;
    const bool is32 = (w32[N_TOK - 1] != 0);
    for (int i = threadIdx.x; i < N_TOK; i += blockDim.x) {
        int v;
        if (is32) v = w32[i];
        else      v = (int)((const long long*)batch_raw)[i];
        g_batch[i] = v;
    }
    __syncthreads();
    int g = threadIdx.x;
    if (g <= N_GRAPHS) {
        int lo = 0, hi = N_TOK;
        while (lo < hi) {
            int mid = (lo + hi) >> 1;
            if (g_batch[mid] < g) lo = mid + 1; else hi = mid;
        }
        g_seg[g] = lo;
    }
    __syncthreads();
    if (threadIdx.x == 0) {
        int cnt = 0;
        for (int s = 0; s < N_GRAPHS; s++)
            for (int q = g_seg[s]; q < g_seg[s + 1]; q += TQ) {
                g_tile_seg[cnt] = s;
                g_tile_q0[cnt]  = q;
                cnt++;
            }
        g_ntiles = cnt;
    }
}

// ---------------- tf32 helpers ----------------
__device__ __forceinline__ unsigned f2tf32(float x) {
    unsigned r;
    asm("cvt.rna.tf32.f32 %0, %1;" : "=r"(r) : "f"(x));
    return r;
}

__device__ __forceinline__ void mma_tf32(float* c, const unsigned* a, const unsigned* b) {
    asm volatile(
        "mma.sync.aligned.m16n8k8.row.col.f32.tf32.tf32.f32 "
        "{%0,%1,%2,%3}, {%4,%5,%6,%7}, {%8,%9}, {%0,%1,%2,%3};"
        : "+f"(c[0]), "+f"(c[1]), "+f"(c[2]), "+f"(c[3])
        : "r"(a[0]), "r"(a[1]), "r"(a[2]), "r"(a[3]),
          "r"(b[0]), "r"(b[1]));
}

__device__ __forceinline__ void cp_async16(unsigned smem_addr, const void* gptr) {
    asm volatile("cp.async.ca.shared.global [%0], [%1], 16;"
                 :: "r"(smem_addr), "l"(gptr));
}

// ---------------- elementwise tf32 rounding ----------------
__global__ void cvt_tf32_kernel(const float4* __restrict__ in,
                                float4* __restrict__ out, int n4) {
    int i = blockIdx.x * blockDim.x + threadIdx.x;
    if (i < n4) {
        float4 v = in[i];
        float4 r;
        r.x = __uint_as_float(f2tf32(v.x));
        r.y = __uint_as_float(f2tf32(v.y));
        r.z = __uint_as_float(f2tf32(v.z));
        r.w = __uint_as_float(f2tf32(v.w));
        out[i] = r;
    }
}

// ---------------- tf32 GEMM: block 128x256, warp tile 64x64, cp.async (R7) ----------------
#define A_STRIDE 36
#define B_STRIDE 264
#define A_SZ (128 * A_STRIDE)
#define B_SZ (32 * B_STRIDE)
#define GEMM_SMEM ((2 * A_SZ + 2 * B_SZ) * 4)

__global__ __launch_bounds__(256, 1)
void gemm_tf32_cp(int M, int N, int K,
                  const float* __restrict__ A,
                  const float* __restrict__ B,
                  const float* __restrict__ bias,
                  float* __restrict__ C)
{
    extern __shared__ float smem[];
    float* As = smem;
    float* Bs = smem + 2 * A_SZ;

    const int tid  = threadIdx.x;
    const int warp = tid >> 5;
    const int lane = tid & 31;
    const int wm   = warp >> 2;
    const int wn   = warp & 3;
    const int bm   = blockIdx.y * 128;
    const int bn   = blockIdx.x * 256;

    const unsigned a_smem0 = (unsigned)__cvta_generic_to_shared(As);
    const unsigned b_smem0 = (unsigned)__cvta_generic_to_shared(Bs);

    const int a_row  = tid >> 1;
    const int a_half = tid & 1;
    const int b_chk  = tid & 63;
    const int b_rb   = tid >> 6;

    const float* aSrcBase = A + (size_t)(bm + a_row) * K + a_half * 16;
    const unsigned aDst   = a_smem0 + (unsigned)(a_row * A_STRIDE + a_half * 16) * 4u;
    const float* bSrcBase = B + (size_t)b_rb * N + bn + b_chk * 4;
    const unsigned bDst   = b_smem0 + (unsigned)(b_rb * B_STRIDE + b_chk * 4) * 4u;

    auto cp_tile = [&](int kt, int buf) {
        const int k0 = kt << 5;
        const float* as = aSrcBase + k0;
        const unsigned ad = aDst + (unsigned)(buf * A_SZ) * 4u;
        #pragma unroll
        for (int j = 0; j < 4; j++)
            cp_async16(ad + j * 16u, as + j * 4);
        const float* bs = bSrcBase + (size_t)k0 * N;
        const unsigned bd = bDst + (unsigned)(buf * B_SZ) * 4u;
        #pragma unroll
        for (int jj = 0; jj < 8; jj++)
            cp_async16(bd + (unsigned)(jj * 4 * B_STRIDE) * 4u,
                       bs + (size_t)(jj * 4) * N);
        asm volatile("cp.async.commit_group;");
    };

    float acc[4][8][4];
    #pragma unroll
    for (int i = 0; i < 4; i++)
        #pragma unroll
        for (int j = 0; j < 8; j++)
            #pragma unroll
            for (int r = 0; r < 4; r++) acc[i][j][r] = 0.f;

    const int aq = lane >> 2;
    const int ac = lane & 3;
    const int a_base_off = aq * A_STRIDE + ac;
    const int b_base_off = ac * B_STRIDE + aq;

    const int KT = K >> 5;
    cp_tile(0, 0);

    for (int kt = 0; kt < KT; kt++) {
        const int buf = kt & 1;
        asm volatile("cp.async.wait_group 0;");
        __syncthreads();
        if (kt + 1 < KT) cp_tile(kt + 1, buf ^ 1);

        const float* a = As + buf * A_SZ;
        const float* b = Bs + buf * B_SZ;

        #pragma unroll
        for (int kb = 0; kb < 4; kb++) {
            unsigned afr[4][4];
            #pragma unroll
            for (int i = 0; i < 4; i++) {
                const int base = (wm * 64 + i * 16) * A_STRIDE + kb * 8 + a_base_off;
                afr[i][0] = __float_as_uint(a[base]);
                afr[i][1] = __float_as_uint(a[base + 8 * A_STRIDE]);
                afr[i][2] = __float_as_uint(a[base + 4]);
                afr[i][3] = __float_as_uint(a[base + 8 * A_STRIDE + 4]);
            }
            #pragma unroll
            for (int j = 0; j < 8; j++) {
                unsigned bfr[2];
                const int base = kb * 8 * B_STRIDE + wn * 64 + j * 8 + b_base_off;
                bfr[0] = __float_as_uint(b[base]);
                bfr[1] = __float_as_uint(b[base + 4 * B_STRIDE]);
                #pragma unroll
                for (int i = 0; i < 4; i++)
                    mma_tf32(acc[i][j], afr[i], bfr);
            }
        }
        __syncthreads();
    }

    const int lg = lane >> 2;
    const int lc = lane & 3;
    #pragma unroll
    for (int i = 0; i < 4; i++) {
        const int m0 = bm + wm * 64 + i * 16 + lg;
        #pragma unroll
        for (int j = 0; j < 8; j++) {
            const int n0 = bn + wn * 64 + j * 8 + lc * 2;
            const float bx = bias[n0];
            const float by = bias[n0 + 1];
            float2 v0 = make_float2(acc[i][j][0] + bx, acc[i][j][1] + by);
            float2 v1 = make_float2(acc[i][j][2] + bx, acc[i][j][3] + by);
            *reinterpret_cast<float2*>(C + (size_t)m0 * N + n0)       = v0;
            *reinterpret_cast<float2*>(C + (size_t)(m0 + 8) * N + n0) = v1;
        }
    }
}

// ---------------- tensor-core flash attention ----------------
// One block per (head, 64-query tile). 128 threads = 4 warps, warp w owns
// rows 16w..16w+15. S=Q·K^T and O+=P·V via mma.m16n8k8.tf32; online softmax
// on accumulator fragments; P routed through smem (layout mismatch tf32).
#define QK_STRIDE 68   // a/b frag banks: 4*(lane/4)+lane%4 -> distinct
#define V_STRIDE  72   // v b-frag banks: 8*kc+lane/4       -> distinct
#define ATTN_SMEM ((3 * 64 * QK_STRIDE + 64 * V_STRIDE) * 4)

__global__ __launch_bounds__(128)
void attn_tc(const float* __restrict__ qkv, float* __restrict__ out)
{
    const int tile = blockIdx.x;
    if (tile >= g_ntiles) return;
    const int h   = blockIdx.y;
    const int seg = g_tile_seg[tile];
    const int q0  = g_tile_q0[tile];
    const int e   = g_seg[seg + 1];
    const int qlen = min(TQ, e - q0);

    extern __shared__ float sm[];
    float* Qs = sm;                          // [64][QK_STRIDE]
    float* Ks = Qs + 64 * QK_STRIDE;         // [64][QK_STRIDE]
    float* Ps = Ks + 64 * QK_STRIDE;         // [64][QK_STRIDE]
    float* Vs = Ps + 64 * QK_STRIDE;         // [64][V_STRIDE]

    const int tid  = threadIdx.x;
    const int warp = tid >> 5;
    const int lane = tid & 31;
    const int lq   = lane >> 2;     // group id (row within 8)
    const int kc   = lane & 3;      // thread in group

    // ---- load Q (tf32-rounded). thread: row=tid&63, half=(tid>>6)*32 ----
    {
        const int i  = tid & 63;
        const int d0 = (tid >> 6) * 32;
        const bool valid = (i < qlen);
        const float* src = qkv + (size_t)(q0 + i) * D3 + h * D_HEAD + d0;
        #pragma unroll
        for (int f = 0; f < 8; f++) {
            float4 t = valid ? *reinterpret_cast<const float4*>(src + f * 4)
                             : make_float4(0.f, 0.f, 0.f, 0.f);
            float* dst = Qs + i * QK_STRIDE + d0 + f * 4;
            dst[0] = __uint_as_float(f2tf32(t.x));
            dst[1] = __uint_as_float(f2tf32(t.y));
            dst[2] = __uint_as_float(f2tf32(t.z));
            dst[3] = __uint_as_float(f2tf32(t.w));
        }
    }

    const int r0 = warp * 16 + lq;   // accumulator rows r0, r0+8

    float m0 = -INFINITY, m1 = -INFINITY, l0 = 0.f, l1 = 0.f;
    float oacc[8][4];
    #pragma unroll
    for (int nb = 0; nb < 8; nb++)
        #pragma unroll
        for (int r = 0; r < 4; r++) oacc[nb][r] = 0.f;

    for (int mm0 = g_seg[seg]; mm0 < e; mm0 += TK) {
        const int klen = min(TK, e - mm0);
        __syncthreads();   // everyone done with Ks/Vs/Ps of previous tile

        // ---- load K, V (tf32-rounded) ----
        {
            const int j  = tid & 63;
            const int d0 = (tid >> 6) * 32;
            const bool valid = (j < klen);
            const float* ksrc = qkv + (size_t)(mm0 + j) * D3 + D_EMB     + h * D_HEAD + d0;
            const float* vsrc = qkv + (size_t)(mm0 + j) * D3 + 2 * D_EMB + h * D_HEAD + d0;
            #pragma unroll
            for (int f = 0; f < 8; f++) {
                float4 t = valid ? *reinterpret_cast<const float4*>(ksrc + f * 4)
                                 : make_float4(0.f, 0.f, 0.f, 0.f);
                float* kd = Ks + j * QK_STRIDE + d0 + f * 4;
                kd[0] = __uint_as_float(f2tf32(t.x));
                kd[1] = __uint_as_float(f2tf32(t.y));
                kd[2] = __uint_as_float(f2tf32(t.z));
                kd[3] = __uint_as_float(f2tf32(t.w));
                float4 v = valid ? *reinterpret_cast<const float4*>(vsrc + f * 4)
                                 : make_float4(0.f, 0.f, 0.f, 0.f);
                float* vd = Vs + j * V_STRIDE + d0 + f * 4;
                vd[0] = __uint_as_float(f2tf32(v.x));
                vd[1] = __uint_as_float(f2tf32(v.y));
                vd[2] = __uint_as_float(f2tf32(v.z));
                vd[3] = __uint_as_float(f2tf32(v.w));
            }
        }
        __syncthreads();

        // ---- S = Q @ K^T ----
        unsigned afr[8][4];
        #pragma unroll
        for (int ks = 0; ks < 8; ks++) {
            const int kb = ks * 8 + kc;
            afr[ks][0] = __float_as_uint(Qs[r0 * QK_STRIDE + kb]);
            afr[ks][1] = __float_as_uint(Qs[(r0 + 8) * QK_STRIDE + kb]);
            afr[ks][2] = __float_as_uint(Qs[r0 * QK_STRIDE + kb + 4]);
            afr[ks][3] = __float_as_uint(Qs[(r0 + 8) * QK_STRIDE + kb + 4]);
        }
        float sacc[8][4];
        #pragma unroll
        for (int nb = 0; nb < 8; nb++) {
            #pragma unroll
            for (int r = 0; r < 4; r++) sacc[nb][r] = 0.f;
            const int brow = nb * 8 + lq;
            #pragma unroll
            for (int ks = 0; ks < 8; ks++) {
                unsigned bfr[2];
                bfr[0] = __float_as_uint(Ks[brow * QK_STRIDE + ks * 8 + kc]);
                bfr[1] = __float_as_uint(Ks[brow * QK_STRIDE + ks * 8 + kc + 4]);
                mma_tf32(sacc[nb], afr[ks], bfr);
            }
        }

        // ---- online softmax on fragments ----
        float rmax0 = -INFINITY, rmax1 = -INFINITY;
        #pragma unroll
        for (int nb = 0; nb < 8; nb++) {
            #pragma unroll
            for (int r = 0; r < 4; r++) {
                const int col = nb * 8 + 2 * kc + (r & 1);
                float s = (col < klen) ? sacc[nb][r] * 0.125f : -INFINITY;
                sacc[nb][r] = s;
                if (r < 2) rmax0 = fmaxf(rmax0, s);
                else       rmax1 = fmaxf(rmax1, s);
            }
        }
        #pragma unroll
        for (int o = 1; o < 4; o <<= 1) {
            rmax0 = fmaxf(rmax0, __shfl_xor_sync(0xffffffffu, rmax0, o));
            rmax1 = fmaxf(rmax1, __shfl_xor_sync(0xffffffffu, rmax1, o));
        }
        const float mn0 = fmaxf(m0, rmax0);
        const float mn1 = fmaxf(m1, rmax1);
        const float corr0 = __expf(m0 - mn0);
        const float corr1 = __expf(m1 - mn1);
        float rsum0 = 0.f, rsum1 = 0.f;
        #pragma unroll
        for (int nb = 0; nb < 8; nb++) {
            const int cb = nb * 8 + 2 * kc;
            float p0 = __expf(sacc[nb][0] - mn0);
            float p1 = __expf(sacc[nb][1] - mn0);
            float p2 = __expf(sacc[nb][2] - mn1);
            float p3 = __expf(sacc[nb][3] - mn1);
            rsum0 += p0 + p1;
            rsum1 += p2 + p3;
            Ps[r0 * QK_STRIDE + cb]           = __uint_as_float(f2tf32(p0));
            Ps[r0 * QK_STRIDE + cb + 1]       = __uint_as_float(f2tf32(p1));
            Ps[(r0 + 8) * QK_STRIDE + cb]     = __uint_as_float(f2tf32(p2));
            Ps[(r0 + 8) * QK_STRIDE + cb + 1] = __uint_as_float(f2tf32(p3));
        }
        #pragma unroll
        for (int o = 1; o < 4; o <<= 1) {
            rsum0 += __shfl_xor_sync(0xffffffffu, rsum0, o);
            rsum1 += __shfl_xor_sync(0xffffffffu, rsum1, o);
        }
        l0 = l0 * corr0 + rsum0;
        l1 = l1 * corr1 + rsum1;
        m0 = mn0;
        m1 = mn1;
        #pragma unroll
        for (int nb = 0; nb < 8; nb++) {
            oacc[nb][0] *= corr0;
            oacc[nb][1] *= corr0;
            oacc[nb][2] *= corr1;
            oacc[nb][3] *= corr1;
        }
        __syncthreads();   // all P stores visible

        // ---- O += P @ V ----
        unsigned pfr[8][4];
        #pragma unroll
        for (int ks = 0; ks < 8; ks++) {
            const int kb = ks * 8 + kc;
            pfr[ks][0] = __float_as_uint(Ps[r0 * QK_STRIDE + kb]);
            pfr[ks][1] = __float_as_uint(Ps[(r0 + 8) * QK_STRIDE + kb]);
            pfr[ks][2] = __float_as_uint(Ps[r0 * QK_STRIDE + kb + 4]);
            pfr[ks][3] = __float_as_uint(Ps[(r0 + 8) * QK_STRIDE + kb + 4]);
        }
        #pragma unroll
        for (int nb = 0; nb < 8; nb++) {
            const int nn = nb * 8 + lq;
            #pragma unroll
            for (int ks = 0; ks < 8; ks++) {
                unsigned bfr[2];
                bfr[0] = __float_as_uint(Vs[(ks * 8 + kc) * V_STRIDE + nn]);
                bfr[1] = __float_as_uint(Vs[(ks * 8 + kc + 4) * V_STRIDE + nn]);
                mma_tf32(oacc[nb], pfr[ks], bfr);
            }
        }
    }

    // ---- write O / l (tf32-rounded for GEMM2) ----
    const float inv0 = 1.f / l0;
    const float inv1 = 1.f / l1;
    #pragma unroll
    for (int nb = 0; nb < 8; nb++) {
        const int col = nb * 8 + 2 * kc;
        if (r0 < qlen) {
            float2 v;
            v.x = __uint_as_float(f2tf32(oacc[nb][0] * inv0));
            v.y = __uint_as_float(f2tf32(oacc[nb][1] * inv0));
            *reinterpret_cast<float2*>(
                out + (size_t)(q0 + r0) * D_EMB + h * D_HEAD + col) = v;
        }
        if (r0 + 8 < qlen) {
            float2 v;
            v.x = __uint_as_float(f2tf32(oacc[nb][2] * inv1));
            v.y = __uint_as_float(f2tf32(oacc[nb][3] * inv1));
            *reinterpret_cast<float2*>(
                out + (size_t)(q0 + r0 + 8) * D_EMB + h * D_HEAD + col) = v;
        }
    }
}

// ---------------- launcher ----------------
extern "C" void kernel_launch(void* const* d_in, const int* in_sizes, int n_in,
                              void* d_out, int out_size)
{
    const float* x     = (const float*)d_in[0];
    const void*  batch = d_in[1];
    const float* W_in  = (const float*)d_in[2];
    const float* b_in  = (const float*)d_in[3];
    const float* W_out = (const float*)d_in[4];
    const float* b_out = (const float*)d_in[5];
    float*       out   = (float*)d_out;

    float* qkv;  cudaGetSymbolAddress((void**)&qkv,  g_qkv);
    float* attn; cudaGetSymbolAddress((void**)&attn, g_attn);
    float* xt;   cudaGetSymbolAddress((void**)&xt,   g_xt);
    float* wit;  cudaGetSymbolAddress((void**)&wit,  g_wit);
    float* wot;  cudaGetSymbolAddress((void**)&wot,  g_wot);

    cudaFuncSetAttribute(gemm_tf32_cp,
                         cudaFuncAttributeMaxDynamicSharedMemorySize, GEMM_SMEM);
    cudaFuncSetAttribute(attn_tc,
                         cudaFuncAttributeMaxDynamicSharedMemorySize, ATTN_SMEM);

    prep_kernel<<<1, 256>>>(batch);

    // tf32 pre-rounding passes
    {
        int n4 = (N_TOK * D_EMB) / 4;
        cvt_tf32_kernel<<<(n4 + 255) / 256, 256>>>((const float4*)x, (float4*)xt, n4);
        n4 = (D_EMB * D3) / 4;
        cvt_tf32_kernel<<<(n4 + 255) / 256, 256>>>((const float4*)W_in, (float4*)wit, n4);
        n4 = (D_EMB * D_EMB) / 4;
        cvt_tf32_kernel<<<(n4 + 255) / 256, 256>>>((const float4*)W_out, (float4*)wot, n4);
    }

    {   // qkv = x @ W_in + b_in
        dim3 grid(D3 / 256, N_TOK / 128);
        gemm_tf32_cp<<<grid, 256, GEMM_SMEM>>>(N_TOK, D3, D_EMB, xt, wit, b_in, qkv);
    }

    {   // segment-local tensor-core attention
        dim3 grid(MAX_TILES, N_HEADS);
        attn_tc<<<grid, 128, ATTN_SMEM>>>(qkv, attn);
    }

    {   // out = attn @ W_out + b_out
        dim3 grid(D_EMB / 256, N_TOK / 128);
        gemm_tf32_cp<<<grid, 256, GEMM_SMEM>>>(N_TOK, D_EMB, D_EMB, attn, wot, b_out, out);
    }
}

// round 10
// speedup vs baseline: 4.1518x; 1.0019x over previous
#include <cuda_runtime.h>
#include <cuda_bf16.h>
#include <math.h>

// Problem constants (fixed shapes per reference)
#define N_TOK   4096
#define D_EMB   1024
#define N_HEADS 16
#define D_HEAD  64
#define D3      (3 * D_EMB)   // 3072
#define N_GRAPHS 16

#define TQ 64
#define TK 64
#define MAX_TILES 80

// ---------------- scratch (no allocation allowed) ----------------
__device__ float g_qkv[N_TOK * D3];
__device__ float g_attn[N_TOK * D_EMB];  // attention output (tf32-rounded)
__device__ float g_xt[N_TOK * D_EMB];    // x, tf32-rounded
__device__ float g_wit[D_EMB * D3];      // W_in, tf32-rounded
__device__ float g_wot[D_EMB * D_EMB];   // W_out, tf32-rounded
__device__ int   g_batch[N_TOK];
__device__ int   g_seg[N_GRAPHS + 1];
__device__ int   g_tile_seg[MAX_TILES];
__device__ int   g_tile_q0[MAX_TILES];
__device__ int   g_ntiles;

// ---------------- prep ----------------
__global__ void prep_kernel(const void* __restrict__ batch_raw) {
    const int* w32 = (const int*)batch_raw;
    const bool is32 = (w32[N_TOK - 1] != 0);
    for (int i = threadIdx.x; i < N_TOK; i += blockDim.x) {
        int v;
        if (is32) v = w32[i];
        else      v = (int)((const long long*)batch_raw)[i];
        g_batch[i] = v;
    }
    __syncthreads();
    int g = threadIdx.x;
    if (g <= N_GRAPHS) {
        int lo = 0, hi = N_TOK;
        while (lo < hi) {
            int mid = (lo + hi) >> 1;
            if (g_batch[mid] < g) lo = mid + 1; else hi = mid;
        }
        g_seg[g] = lo;
    }
    __syncthreads();
    if (threadIdx.x == 0) {
        int cnt = 0;
        for (int s = 0; s < N_GRAPHS; s++)
            for (int q = g_seg[s]; q < g_seg[s + 1]; q += TQ) {
                g_tile_seg[cnt] = s;
                g_tile_q0[cnt]  = q;
                cnt++;
            }
        g_ntiles = cnt;
    }
}

// ---------------- tf32 helpers ----------------
__device__ __forceinline__ unsigned f2tf32(float x) {
    unsigned r;
    asm("cvt.rna.tf32.f32 %0, %1;" : "=r"(r) : "f"(x));
    return r;
}

__device__ __forceinline__ void mma_tf32(float* c, const unsigned* a, const unsigned* b) {
    asm volatile(
        "mma.sync.aligned.m16n8k8.row.col.f32.tf32.tf32.f32 "
        "{%0,%1,%2,%3}, {%4,%5,%6,%7}, {%8,%9}, {%0,%1,%2,%3};"
        : "+f"(c[0]), "+f"(c[1]), "+f"(c[2]), "+f"(c[3])
        : "r"(a[0]), "r"(a[1]), "r"(a[2]), "r"(a[3]),
          "r"(b[0]), "r"(b[1]));
}

__device__ __forceinline__ void cp_async16(unsigned smem_addr, const void* gptr) {
    asm volatile("cp.async.ca.shared.global [%0], [%1], 16;"
                 :: "r"(smem_addr), "l"(gptr));
}

// ---------------- elementwise tf32 rounding ----------------
__global__ void cvt_tf32_kernel(const float4* __restrict__ in,
                                float4* __restrict__ out, int n4) {
    int i = blockIdx.x * blockDim.x + threadIdx.x;
    if (i < n4) {
        float4 v = in[i];
        float4 r;
        r.x = __uint_as_float(f2tf32(v.x));
        r.y = __uint_as_float(f2tf32(v.y));
        r.z = __uint_as_float(f2tf32(v.z));
        r.w = __uint_as_float(f2tf32(v.w));
        out[i] = r;
    }
}

// ---------------- tf32 GEMM: block 128x256, warp tile 64x64, cp.async (R7) ----------------
#define A_STRIDE 36
#define B_STRIDE 264
#define A_SZ (128 * A_STRIDE)
#define B_SZ (32 * B_STRIDE)
#define GEMM_SMEM ((2 * A_SZ + 2 * B_SZ) * 4)

__global__ __launch_bounds__(256, 1)
void gemm_tf32_cp(int M, int N, int K,
                  const float* __restrict__ A,
                  const float* __restrict__ B,
                  const float* __restrict__ bias,
                  float* __restrict__ C)
{
    extern __shared__ float smem[];
    float* As = smem;
    float* Bs = smem + 2 * A_SZ;

    const int tid  = threadIdx.x;
    const int warp = tid >> 5;
    const int lane = tid & 31;
    const int wm   = warp >> 2;
    const int wn   = warp & 3;
    const int bm   = blockIdx.y * 128;
    const int bn   = blockIdx.x * 256;

    const unsigned a_smem0 = (unsigned)__cvta_generic_to_shared(As);
    const unsigned b_smem0 = (unsigned)__cvta_generic_to_shared(Bs);

    const int a_row  = tid >> 1;
    const int a_half = tid & 1;
    const int b_chk  = tid & 63;
    const int b_rb   = tid >> 6;

    const float* aSrcBase = A + (size_t)(bm + a_row) * K + a_half * 16;
    const unsigned aDst   = a_smem0 + (unsigned)(a_row * A_STRIDE + a_half * 16) * 4u;
    const float* bSrcBase = B + (size_t)b_rb * N + bn + b_chk * 4;
    const unsigned bDst   = b_smem0 + (unsigned)(b_rb * B_STRIDE + b_chk * 4) * 4u;

    auto cp_tile = [&](int kt, int buf) {
        const int k0 = kt << 5;
        const float* as = aSrcBase + k0;
        const unsigned ad = aDst + (unsigned)(buf * A_SZ) * 4u;
        #pragma unroll
        for (int j = 0; j < 4; j++)
            cp_async16(ad + j * 16u, as + j * 4);
        const float* bs = bSrcBase + (size_t)k0 * N;
        const unsigned bd = bDst + (unsigned)(buf * B_SZ) * 4u;
        #pragma unroll
        for (int jj = 0; jj < 8; jj++)
            cp_async16(bd + (unsigned)(jj * 4 * B_STRIDE) * 4u,
                       bs + (size_t)(jj * 4) * N);
        asm volatile("cp.async.commit_group;");
    };

    float acc[4][8][4];
    #pragma unroll
    for (int i = 0; i < 4; i++)
        #pragma unroll
        for (int j = 0; j < 8; j++)
            #pragma unroll
            for (int r = 0; r < 4; r++) acc[i][j][r] = 0.f;

    const int aq = lane >> 2;
    const int ac = lane & 3;
    const int a_base_off = aq * A_STRIDE + ac;
    const int b_base_off = ac * B_STRIDE + aq;

    const int KT = K >> 5;
    cp_tile(0, 0);

    for (int kt = 0; kt < KT; kt++) {
        const int buf = kt & 1;
        asm volatile("cp.async.wait_group 0;");
        __syncthreads();
        if (kt + 1 < KT) cp_tile(kt + 1, buf ^ 1);

        const float* a = As + buf * A_SZ;
        const float* b = Bs + buf * B_SZ;

        #pragma unroll
        for (int kb = 0; kb < 4; kb++) {
            unsigned afr[4][4];
            #pragma unroll
            for (int i = 0; i < 4; i++) {
                const int base = (wm * 64 + i * 16) * A_STRIDE + kb * 8 + a_base_off;
                afr[i][0] = __float_as_uint(a[base]);
                afr[i][1] = __float_as_uint(a[base + 8 * A_STRIDE]);
                afr[i][2] = __float_as_uint(a[base + 4]);
                afr[i][3] = __float_as_uint(a[base + 8 * A_STRIDE + 4]);
            }
            #pragma unroll
            for (int j = 0; j < 8; j++) {
                unsigned bfr[2];
                const int base = kb * 8 * B_STRIDE + wn * 64 + j * 8 + b_base_off;
                bfr[0] = __float_as_uint(b[base]);
                bfr[1] = __float_as_uint(b[base + 4 * B_STRIDE]);
                #pragma unroll
                for (int i = 0; i < 4; i++)
                    mma_tf32(acc[i][j], afr[i], bfr);
            }
        }
        __syncthreads();
    }

    const int lg = lane >> 2;
    const int lc = lane & 3;
    #pragma unroll
    for (int i = 0; i < 4; i++) {
        const int m0 = bm + wm * 64 + i * 16 + lg;
        #pragma unroll
        for (int j = 0; j < 8; j++) {
            const int n0 = bn + wn * 64 + j * 8 + lc * 2;
            const float bx = bias[n0];
            const float by = bias[n0 + 1];
            float2 v0 = make_float2(acc[i][j][0] + bx, acc[i][j][1] + by);
            float2 v1 = make_float2(acc[i][j][2] + bx, acc[i][j][3] + by);
            *reinterpret_cast<float2*>(C + (size_t)m0 * N + n0)       = v0;
            *reinterpret_cast<float2*>(C + (size_t)(m0 + 8) * N + n0) = v1;
        }
    }
}

// ---------------- tensor-core flash attention ----------------
// One block per (head, 64-query tile). 128 threads = 4 warps, warp w owns
// rows 16w..16w+15. S=Q·K^T and O+=P·V via mma.m16n8k8.tf32; online softmax
// on accumulator fragments; P routed through smem (layout mismatch tf32).
#define QK_STRIDE 68   // a/b frag banks: 4*(lane/4)+lane%4 -> distinct
#define V_STRIDE  72   // v b-frag banks: 8*kc+lane/4       -> distinct
#define ATTN_SMEM ((3 * 64 * QK_STRIDE + 64 * V_STRIDE) * 4)

__global__ __launch_bounds__(128)
void attn_tc(const float* __restrict__ qkv, float* __restrict__ out)
{
    const int tile = blockIdx.x;
    if (tile >= g_ntiles) return;
    const int h   = blockIdx.y;
    const int seg = g_tile_seg[tile];
    const int q0  = g_tile_q0[tile];
    const int e   = g_seg[seg + 1];
    const int qlen = min(TQ, e - q0);

    extern __shared__ float sm[];
    float* Qs = sm;                          // [64][QK_STRIDE]
    float* Ks = Qs + 64 * QK_STRIDE;         // [64][QK_STRIDE]
    float* Ps = Ks + 64 * QK_STRIDE;         // [64][QK_STRIDE]
    float* Vs = Ps + 64 * QK_STRIDE;         // [64][V_STRIDE]

    const int tid  = threadIdx.x;
    const int warp = tid >> 5;
    const int lane = tid & 31;
    const int lq   = lane >> 2;     // group id (row within 8)
    const int kc   = lane & 3;      // thread in group

    // ---- load Q (tf32-rounded). thread: row=tid&63, half=(tid>>6)*32 ----
    {
        const int i  = tid & 63;
        const int d0 = (tid >> 6) * 32;
        const bool valid = (i < qlen);
        const float* src = qkv + (size_t)(q0 + i) * D3 + h * D_HEAD + d0;
        #pragma unroll
        for (int f = 0; f < 8; f++) {
            float4 t = valid ? *reinterpret_cast<const float4*>(src + f * 4)
                             : make_float4(0.f, 0.f, 0.f, 0.f);
            float* dst = Qs + i * QK_STRIDE + d0 + f * 4;
            dst[0] = __uint_as_float(f2tf32(t.x));
            dst[1] = __uint_as_float(f2tf32(t.y));
            dst[2] = __uint_as_float(f2tf32(t.z));
            dst[3] = __uint_as_float(f2tf32(t.w));
        }
    }

    const int r0 = warp * 16 + lq;   // accumulator rows r0, r0+8

    float m0 = -INFINITY, m1 = -INFINITY, l0 = 0.f, l1 = 0.f;
    float oacc[8][4];
    #pragma unroll
    for (int nb = 0; nb < 8; nb++)
        #pragma unroll
        for (int r = 0; r < 4; r++) oacc[nb][r] = 0.f;

    for (int mm0 = g_seg[seg]; mm0 < e; mm0 += TK) {
        const int klen = min(TK, e - mm0);
        __syncthreads();   // everyone done with Ks/Vs/Ps of previous tile

        // ---- load K, V (tf32-rounded) ----
        {
            const int j  = tid & 63;
            const int d0 = (tid >> 6) * 32;
            const bool valid = (j < klen);
            const float* ksrc = qkv + (size_t)(mm0 + j) * D3 + D_EMB     + h * D_HEAD + d0;
            const float* vsrc = qkv + (size_t)(mm0 + j) * D3 + 2 * D_EMB + h * D_HEAD + d0;
            #pragma unroll
            for (int f = 0; f < 8; f++) {
                float4 t = valid ? *reinterpret_cast<const float4*>(ksrc + f * 4)
                                 : make_float4(0.f, 0.f, 0.f, 0.f);
                float* kd = Ks + j * QK_STRIDE + d0 + f * 4;
                kd[0] = __uint_as_float(f2tf32(t.x));
                kd[1] = __uint_as_float(f2tf32(t.y));
                kd[2] = __uint_as_float(f2tf32(t.z));
                kd[3] = __uint_as_float(f2tf32(t.w));
                float4 v = valid ? *reinterpret_cast<const float4*>(vsrc + f * 4)
                                 : make_float4(0.f, 0.f, 0.f, 0.f);
                float* vd = Vs + j * V_STRIDE + d0 + f * 4;
                vd[0] = __uint_as_float(f2tf32(v.x));
                vd[1] = __uint_as_float(f2tf32(v.y));
                vd[2] = __uint_as_float(f2tf32(v.z));
                vd[3] = __uint_as_float(f2tf32(v.w));
            }
        }
        __syncthreads();

        // ---- S = Q @ K^T ----
        unsigned afr[8][4];
        #pragma unroll
        for (int ks = 0; ks < 8; ks++) {
            const int kb = ks * 8 + kc;
            afr[ks][0] = __float_as_uint(Qs[r0 * QK_STRIDE + kb]);
            afr[ks][1] = __float_as_uint(Qs[(r0 + 8) * QK_STRIDE + kb]);
            afr[ks][2] = __float_as_uint(Qs[r0 * QK_STRIDE + kb + 4]);
            afr[ks][3] = __float_as_uint(Qs[(r0 + 8) * QK_STRIDE + kb + 4]);
        }
        float sacc[8][4];
        #pragma unroll
        for (int nb = 0; nb < 8; nb++) {
            #pragma unroll
            for (int r = 0; r < 4; r++) sacc[nb][r] = 0.f;
            const int brow = nb * 8 + lq;
            #pragma unroll
            for (int ks = 0; ks < 8; ks++) {
                unsigned bfr[2];
                bfr[0] = __float_as_uint(Ks[brow * QK_STRIDE + ks * 8 + kc]);
                bfr[1] = __float_as_uint(Ks[brow * QK_STRIDE + ks * 8 + kc + 4]);
                mma_tf32(sacc[nb], afr[ks], bfr);
            }
        }

        // ---- online softmax on fragments ----
        float rmax0 = -INFINITY, rmax1 = -INFINITY;
        #pragma unroll
        for (int nb = 0; nb < 8; nb++) {
            #pragma unroll
            for (int r = 0; r < 4; r++) {
                const int col = nb * 8 + 2 * kc + (r & 1);
                float s = (col < klen) ? sacc[nb][r] * 0.125f : -INFINITY;
                sacc[nb][r] = s;
                if (r < 2) rmax0 = fmaxf(rmax0, s);
                else       rmax1 = fmaxf(rmax1, s);
            }
        }
        #pragma unroll
        for (int o = 1; o < 4; o <<= 1) {
            rmax0 = fmaxf(rmax0, __shfl_xor_sync(0xffffffffu, rmax0, o));
            rmax1 = fmaxf(rmax1, __shfl_xor_sync(0xffffffffu, rmax1, o));
        }
        const float mn0 = fmaxf(m0, rmax0);
        const float mn1 = fmaxf(m1, rmax1);
        const float corr0 = __expf(m0 - mn0);
        const float corr1 = __expf(m1 - mn1);
        float rsum0 = 0.f, rsum1 = 0.f;
        #pragma unroll
        for (int nb = 0; nb < 8; nb++) {
            const int cb = nb * 8 + 2 * kc;
            float p0 = __expf(sacc[nb][0] - mn0);
            float p1 = __expf(sacc[nb][1] - mn0);
            float p2 = __expf(sacc[nb][2] - mn1);
            float p3 = __expf(sacc[nb][3] - mn1);
            rsum0 += p0 + p1;
            rsum1 += p2 + p3;
            Ps[r0 * QK_STRIDE + cb]           = __uint_as_float(f2tf32(p0));
            Ps[r0 * QK_STRIDE + cb + 1]       = __uint_as_float(f2tf32(p1));
            Ps[(r0 + 8) * QK_STRIDE + cb]     = __uint_as_float(f2tf32(p2));
            Ps[(r0 + 8) * QK_STRIDE + cb + 1] = __uint_as_float(f2tf32(p3));
        }
        #pragma unroll
        for (int o = 1; o < 4; o <<= 1) {
            rsum0 += __shfl_xor_sync(0xffffffffu, rsum0, o);
            rsum1 += __shfl_xor_sync(0xffffffffu, rsum1, o);
        }
        l0 = l0 * corr0 + rsum0;
        l1 = l1 * corr1 + rsum1;
        m0 = mn0;
        m1 = mn1;
        #pragma unroll
        for (int nb = 0; nb < 8; nb++) {
            oacc[nb][0] *= corr0;
            oacc[nb][1] *= corr0;
            oacc[nb][2] *= corr1;
            oacc[nb][3] *= corr1;
        }
        __syncthreads();   // all P stores visible

        // ---- O += P @ V ----
        unsigned pfr[8][4];
        #pragma unroll
        for (int ks = 0; ks < 8; ks++) {
            const int kb = ks * 8 + kc;
            pfr[ks][0] = __float_as_uint(Ps[r0 * QK_STRIDE + kb]);
            pfr[ks][1] = __float_as_uint(Ps[(r0 + 8) * QK_STRIDE + kb]);
            pfr[ks][2] = __float_as_uint(Ps[r0 * QK_STRIDE + kb + 4]);
            pfr[ks][3] = __float_as_uint(Ps[(r0 + 8) * QK_STRIDE + kb + 4]);
        }
        #pragma unroll
        for (int nb = 0; nb < 8; nb++) {
            const int nn = nb * 8 + lq;
            #pragma unroll
            for (int ks = 0; ks < 8; ks++) {
                unsigned bfr[2];
                bfr[0] = __float_as_uint(Vs[(ks * 8 + kc) * V_STRIDE + nn]);
                bfr[1] = __float_as_uint(Vs[(ks * 8 + kc + 4) * V_STRIDE + nn]);
                mma_tf32(oacc[nb], pfr[ks], bfr);
            }
        }
    }

    // ---- write O / l (tf32-rounded for GEMM2) ----
    const float inv0 = 1.f / l0;
    const float inv1 = 1.f / l1;
    #pragma unroll
    for (int nb = 0; nb < 8; nb++) {
        const int col = nb * 8 + 2 * kc;
        if (r0 < qlen) {
            float2 v;
            v.x = __uint_as_float(f2tf32(oacc[nb][0] * inv0));
            v.y = __uint_as_float(f2tf32(oacc[nb][1] * inv0));
            *reinterpret_cast<float2*>(
                out + (size_t)(q0 + r0) * D_EMB + h * D_HEAD + col) = v;
        }
        if (r0 + 8 < qlen) {
            float2 v;
            v.x = __uint_as_float(f2tf32(oacc[nb][2] * inv1));
            v.y = __uint_as_float(f2tf32(oacc[nb][3] * inv1));
            *reinterpret_cast<float2*>(
                out + (size_t)(q0 + r0 + 8) * D_EMB + h * D_HEAD + col) = v;
        }
    }
}

// ---------------- launcher ----------------
extern "C" void kernel_launch(void* const* d_in, const int* in_sizes, int n_in,
                              void* d_out, int out_size)
{
    const float* x     = (const float*)d_in[0];
    const void*  batch = d_in[1];
    const float* W_in  = (const float*)d_in[2];
    const float* b_in  = (const float*)d_in[3];
    const float* W_out = (const float*)d_in[4];
    const float* b_out = (const float*)d_in[5];
    float*       out   = (float*)d_out;

    float* qkv;  cudaGetSymbolAddress((void**)&qkv,  g_qkv);
    float* attn; cudaGetSymbolAddress((void**)&attn, g_attn);
    float* xt;   cudaGetSymbolAddress((void**)&xt,   g_xt);
    float* wit;  cudaGetSymbolAddress((void**)&wit,  g_wit);
    float* wot;  cudaGetSymbolAddress((void**)&wot,  g_wot);

    cudaFuncSetAttribute(gemm_tf32_cp,
                         cudaFuncAttributeMaxDynamicSharedMemorySize, GEMM_SMEM);
    cudaFuncSetAttribute(attn_tc,
                         cudaFuncAttributeMaxDynamicSharedMemorySize, ATTN_SMEM);

    prep_kernel<<<1, 256>>>(batch);

    // tf32 pre-rounding passes
    {
        int n4 = (N_TOK * D_EMB) / 4;
        cvt_tf32_kernel<<<(n4 + 255) / 256, 256>>>((const float4*)x, (float4*)xt, n4);
        n4 = (D_EMB * D3) / 4;
        cvt_tf32_kernel<<<(n4 + 255) / 256, 256>>>((const float4*)W_in, (float4*)wit, n4);
        n4 = (D_EMB * D_EMB) / 4;
        cvt_tf32_kernel<<<(n4 + 255) / 256, 256>>>((const float4*)W_out, (float4*)wot, n4);
    }

    {   // qkv = x @ W_in + b_in
        dim3 grid(D3 / 256, N_TOK / 128);
        gemm_tf32_cp<<<grid, 256, GEMM_SMEM>>>(N_TOK, D3, D_EMB, xt, wit, b_in, qkv);
    }

    {   // segment-local tensor-core attention
        dim3 grid(MAX_TILES, N_HEADS);
        attn_tc<<<grid, 128, ATTN_SMEM>>>(qkv, attn);
    }

    {   // out = attn @ W_out + b_out
        dim3 grid(D_EMB / 256, N_TOK / 128);
        gemm_tf32_cp<<<grid, 256, GEMM_SMEM>>>(N_TOK, D_EMB, D_EMB, attn, wot, b_out, out);
    }
}

// round 12
// speedup vs baseline: 6.0018x; 1.4456x over previous
#include <cuda_runtime.h>
#include <cuda_fp16.h>
#include <cuda_bf16.h>
#include <math.h>

// Problem constants (fixed shapes per reference)
#define N_TOK   4096
#define D_EMB   1024
#define N_HEADS 16
#define D_HEAD  64
#define D3      (3 * D_EMB)   // 3072
#define N_GRAPHS 16

#define TQ 64
#define TK 64
#define MAX_TILES 80

// ---------------- scratch (no allocation allowed) ----------------
__device__ float  g_qkv[N_TOK * D3];       // fp32 qkv
__device__ __half g_attnh[N_TOK * D_EMB];  // attention output, fp16
__device__ __half g_xh[N_TOK * D_EMB];     // x, fp16
__device__ __half g_wih[D_EMB * D3];       // W_in, fp16  [K][N]
__device__ __half g_woh[D_EMB * D_EMB];    // W_out, fp16 [K][N]
__device__ int    g_batch[N_TOK];
__device__ int    g_seg[N_GRAPHS + 1];
__device__ int    g_tile_seg[MAX_TILES];
__device__ int    g_tile_q0[MAX_TILES];
__device__ int    g_ntiles;

// ---------------- prep ----------------
__global__ void prep_kernel(const void* __restrict__ batch_raw) {
    const int* w32 = (const int*)batch_raw;
    const bool is32 = (w32[N_TOK - 1] != 0);
    for (int i = threadIdx.x; i < N_TOK; i += blockDim.x) {
        int v;
        if (is32) v = w32[i];
        else      v = (int)((const long long*)batch_raw)[i];
        g_batch[i] = v;
    }
    __syncthreads();
    int g = threadIdx.x;
    if (g <= N_GRAPHS) {
        int lo = 0, hi = N_TOK;
        while (lo < hi) {
            int mid = (lo + hi) >> 1;
            if (g_batch[mid] < g) lo = mid + 1; else hi = mid;
        }
        g_seg[g] = lo;
    }
    __syncthreads();
    if (threadIdx.x == 0) {
        int cnt = 0;
        for (int s = 0; s < N_GRAPHS; s++)
            for (int q = g_seg[s]; q < g_seg[s + 1]; q += TQ) {
                g_tile_seg[cnt] = s;
                g_tile_q0[cnt]  = q;
                cnt++;
            }
        g_ntiles = cnt;
    }
}

// ---------------- helpers ----------------
__device__ __forceinline__ unsigned f2tf32(float x) {
    unsigned r;
    asm("cvt.rna.tf32.f32 %0, %1;" : "=r"(r) : "f"(x));
    return r;
}

__device__ __forceinline__ void mma_tf32(float* c, const unsigned* a, const unsigned* b) {
    asm volatile(
        "mma.sync.aligned.m16n8k8.row.col.f32.tf32.tf32.f32 "
        "{%0,%1,%2,%3}, {%4,%5,%6,%7}, {%8,%9}, {%0,%1,%2,%3};"
        : "+f"(c[0]), "+f"(c[1]), "+f"(c[2]), "+f"(c[3])
        : "r"(a[0]), "r"(a[1]), "r"(a[2]), "r"(a[3]),
          "r"(b[0]), "r"(b[1]));
}

__device__ __forceinline__ void mma_f16(float* c, const unsigned* a, const unsigned* b) {
    asm volatile(
        "mma.sync.aligned.m16n8k16.row.col.f32.f16.f16.f32 "
        "{%0,%1,%2,%3}, {%4,%5,%6,%7}, {%8,%9}, {%0,%1,%2,%3};"
        : "+f"(c[0]), "+f"(c[1]), "+f"(c[2]), "+f"(c[3])
        : "r"(a[0]), "r"(a[1]), "r"(a[2]), "r"(a[3]),
          "r"(b[0]), "r"(b[1]));
}

__device__ __forceinline__ void cp_async16(unsigned smem_addr, const void* gptr) {
    asm volatile("cp.async.ca.shared.global [%0], [%1], 16;"
                 :: "r"(smem_addr), "l"(gptr));
}

__device__ __forceinline__ void ldm_x4(unsigned* r, unsigned addr) {
    asm volatile("ldmatrix.sync.aligned.m8n8.x4.shared.b16 {%0,%1,%2,%3}, [%4];"
                 : "=r"(r[0]), "=r"(r[1]), "=r"(r[2]), "=r"(r[3]) : "r"(addr));
}

__device__ __forceinline__ void ldm_x4_t(unsigned* r, unsigned addr) {
    asm volatile("ldmatrix.sync.aligned.m8n8.x4.trans.shared.b16 {%0,%1,%2,%3}, [%4];"
                 : "=r"(r[0]), "=r"(r[1]), "=r"(r[2]), "=r"(r[3]) : "r"(addr));
}

// ---------------- fp32 -> fp16 conversion pass ----------------
__global__ void cvt_fp16_kernel(const float4* __restrict__ in,
                                uint2* __restrict__ out, int n4) {
    int i = blockIdx.x * blockDim.x + threadIdx.x;
    if (i < n4) {
        float4 v = in[i];
        __half2 lo = __floats2half2_rn(v.x, v.y);
        __half2 hi = __floats2half2_rn(v.z, v.w);
        uint2 r;
        r.x = *reinterpret_cast<unsigned*>(&lo);
        r.y = *reinterpret_cast<unsigned*>(&hi);
        out[i] = r;
    }
}

// ---------------- fp16 GEMM: block 128x256, warp 64x64, ldmatrix + m16n8k16 ----------------
// C[M,N] = A[M,K] @ B[K,N] + bias[N]; A,B fp16, C fp32. K mult of 32, N mult of 256.
#define A_STRIDE_B 80          // bytes/row (32 halves data + pad)
#define B_STRIDE_B 528         // bytes/row (256 halves + pad): 132 words ≡ 4 mod 32
#define A_BYTES (128 * A_STRIDE_B)   // 10240
#define B_BYTES (32 * B_STRIDE_B)    // 16896
#define GEMM_SMEM (2 * (A_BYTES + B_BYTES))

__global__ __launch_bounds__(256, 1)
void gemm_f16_cp(int M, int N, int K,
                 const __half* __restrict__ A,
                 const __half* __restrict__ B,
                 const float* __restrict__ bias,
                 float* __restrict__ C)
{
    extern __shared__ char smem[];
    const unsigned s0 = (unsigned)__cvta_generic_to_shared(smem);
    const unsigned aS[2] = { s0,              s0 + A_BYTES };
    const unsigned bS[2] = { s0 + 2*A_BYTES,  s0 + 2*A_BYTES + B_BYTES };

    const int tid  = threadIdx.x;
    const int warp = tid >> 5;
    const int lane = tid & 31;
    const int wm   = warp >> 2;      // 0..1
    const int wn   = warp & 3;       // 0..3
    const int bm   = blockIdx.y * 128;
    const int bn   = blockIdx.x * 256;

    // cp.async mapping
    const int ar  = tid >> 1;            // A row 0..127
    const int ac2 = (tid & 1) * 2;       // A chunks ac2, ac2+1 (16B each)
    const int bkr = tid >> 3;            // B k-row 0..31
    const int bc  = tid & 7;             // B chunks bc + 8q

    const __half* aSrc = A + (size_t)(bm + ar) * K + ac2 * 8;
    const __half* bSrc = B + (size_t)bkr * N + bn;   // FIX: no bc*8 here

    auto cp_tile = [&](int kt, int buf) {
        const int k0 = kt << 5;
        const __half* as = aSrc + k0;
        #pragma unroll
        for (int j = 0; j < 2; j++)
            cp_async16(aS[buf] + (unsigned)(ar * A_STRIDE_B + (ac2 + j) * 16),
                       as + j * 8);
        const __half* bs = bSrc + (size_t)k0 * N;
        #pragma unroll
        for (int q = 0; q < 4; q++)
            cp_async16(bS[buf] + (unsigned)(bkr * B_STRIDE_B + (bc + 8 * q) * 16),
                       bs + (bc + 8 * q) * 8);
        asm volatile("cp.async.commit_group;");
    };

    float acc[4][8][4];
    #pragma unroll
    for (int i = 0; i < 4; i++)
        #pragma unroll
        for (int j = 0; j < 8; j++)
            #pragma unroll
            for (int r = 0; r < 4; r++) acc[i][j][r] = 0.f;

    const int lrow = lane & 15;
    const int lseg = lane >> 4;

    const int KT = K >> 5;
    cp_tile(0, 0);

    for (int kt = 0; kt < KT; kt++) {
        const int buf = kt & 1;
        asm volatile("cp.async.wait_group 0;");
        __syncthreads();
        if (kt + 1 < KT) cp_tile(kt + 1, buf ^ 1);

        #pragma unroll
        for (int kb = 0; kb < 2; kb++) {
            unsigned afr[4][4], bfr[4][4];
            #pragma unroll
            for (int i = 0; i < 4; i++) {
                const unsigned ad = aS[buf]
                    + (unsigned)((wm * 64 + i * 16 + lrow) * A_STRIDE_B
                                 + kb * 32 + lseg * 16);
                ldm_x4(afr[i], ad);
            }
            #pragma unroll
            for (int j = 0; j < 4; j++) {
                const unsigned bd = bS[buf]
                    + (unsigned)((kb * 16 + lrow) * B_STRIDE_B
                                 + wn * 128 + j * 32 + lseg * 16);
                ldm_x4_t(bfr[j], bd);
            }
            #pragma unroll
            for (int i = 0; i < 4; i++)
                #pragma unroll
                for (int j8 = 0; j8 < 8; j8++)
                    mma_f16(acc[i][j8], afr[i], &bfr[j8 >> 1][(j8 & 1) * 2]);
        }
        __syncthreads();
    }

    // epilogue: bias + fp32 store
    const int lg = lane >> 2;
    const int lc = lane & 3;
    #pragma unroll
    for (int i = 0; i < 4; i++) {
        const int m0 = bm + wm * 64 + i * 16 + lg;
        #pragma unroll
        for (int j = 0; j < 8; j++) {
            const int n0 = bn + wn * 64 + j * 8 + lc * 2;
            const float bx = bias[n0];
            const float by = bias[n0 + 1];
            float2 v0 = make_float2(acc[i][j][0] + bx, acc[i][j][1] + by);
            float2 v1 = make_float2(acc[i][j][2] + bx, acc[i][j][3] + by);
            *reinterpret_cast<float2*>(C + (size_t)m0 * N + n0)       = v0;
            *reinterpret_cast<float2*>(C + (size_t)(m0 + 8) * N + n0) = v1;
        }
    }
}

// ---------------- tensor-core flash attention (R10; emits fp16) ----------------
#define QK_STRIDE 68
#define V_STRIDE  72
#define ATTN_SMEM ((3 * 64 * QK_STRIDE + 64 * V_STRIDE) * 4)

__global__ __launch_bounds__(128)
void attn_tc(const float* __restrict__ qkv, __half* __restrict__ out)
{
    const int tile = blockIdx.x;
    if (tile >= g_ntiles) return;
    const int h   = blockIdx.y;
    const int seg = g_tile_seg[tile];
    const int q0  = g_tile_q0[tile];
    const int e   = g_seg[seg + 1];
    const int qlen = min(TQ, e - q0);

    extern __shared__ float sm[];
    float* Qs = sm;
    float* Ks = Qs + 64 * QK_STRIDE;
    float* Ps = Ks + 64 * QK_STRIDE;
    float* Vs = Ps + 64 * QK_STRIDE;

    const int tid  = threadIdx.x;
    const int warp = tid >> 5;
    const int lane = tid & 31;
    const int lq   = lane >> 2;
    const int kc   = lane & 3;

    {
        const int i  = tid & 63;
        const int d0 = (tid >> 6) * 32;
        const bool valid = (i < qlen);
        const float* src = qkv + (size_t)(q0 + i) * D3 + h * D_HEAD + d0;
        #pragma unroll
        for (int f = 0; f < 8; f++) {
            float4 t = valid ? *reinterpret_cast<const float4*>(src + f * 4)
                             : make_float4(0.f, 0.f, 0.f, 0.f);
            float* dst = Qs + i * QK_STRIDE + d0 + f * 4;
            dst[0] = __uint_as_float(f2tf32(t.x));
            dst[1] = __uint_as_float(f2tf32(t.y));
            dst[2] = __uint_as_float(f2tf32(t.z));
            dst[3] = __uint_as_float(f2tf32(t.w));
        }
    }

    const int r0 = warp * 16 + lq;

    float m0 = -INFINITY, m1 = -INFINITY, l0 = 0.f, l1 = 0.f;
    float oacc[8][4];
    #pragma unroll
    for (int nb = 0; nb < 8; nb++)
        #pragma unroll
        for (int r = 0; r < 4; r++) oacc[nb][r] = 0.f;

    for (int mm0 = g_seg[seg]; mm0 < e; mm0 += TK) {
        const int klen = min(TK, e - mm0);
        __syncthreads();

        {
            const int j  = tid & 63;
            const int d0 = (tid >> 6) * 32;
            const bool valid = (j < klen);
            const float* ksrc = qkv + (size_t)(mm0 + j) * D3 + D_EMB     + h * D_HEAD + d0;
            const float* vsrc = qkv + (size_t)(mm0 + j) * D3 + 2 * D_EMB + h * D_HEAD + d0;
            #pragma unroll
            for (int f = 0; f < 8; f++) {
                float4 t = valid ? *reinterpret_cast<const float4*>(ksrc + f * 4)
                                 : make_float4(0.f, 0.f, 0.f, 0.f);
                float* kd = Ks + j * QK_STRIDE + d0 + f * 4;
                kd[0] = __uint_as_float(f2tf32(t.x));
                kd[1] = __uint_as_float(f2tf32(t.y));
                kd[2] = __uint_as_float(f2tf32(t.z));
                kd[3] = __uint_as_float(f2tf32(t.w));
                float4 v = valid ? *reinterpret_cast<const float4*>(vsrc + f * 4)
                                 : make_float4(0.f, 0.f, 0.f, 0.f);
                float* vd = Vs + j * V_STRIDE + d0 + f * 4;
                vd[0] = __uint_as_float(f2tf32(v.x));
                vd[1] = __uint_as_float(f2tf32(v.y));
                vd[2] = __uint_as_float(f2tf32(v.z));
                vd[3] = __uint_as_float(f2tf32(v.w));
            }
        }
        __syncthreads();

        unsigned afr[8][4];
        #pragma unroll
        for (int ks = 0; ks < 8; ks++) {
            const int kb = ks * 8 + kc;
            afr[ks][0] = __float_as_uint(Qs[r0 * QK_STRIDE + kb]);
            afr[ks][1] = __float_as_uint(Qs[(r0 + 8) * QK_STRIDE + kb]);
            afr[ks][2] = __float_as_uint(Qs[r0 * QK_STRIDE + kb + 4]);
            afr[ks][3] = __float_as_uint(Qs[(r0 + 8) * QK_STRIDE + kb + 4]);
        }
        float sacc[8][4];
        #pragma unroll
        for (int nb = 0; nb < 8; nb++) {
            #pragma unroll
            for (int r = 0; r < 4; r++) sacc[nb][r] = 0.f;
            const int brow = nb * 8 + lq;
            #pragma unroll
            for (int ks = 0; ks < 8; ks++) {
                unsigned bfr[2];
                bfr[0] = __float_as_uint(Ks[brow * QK_STRIDE + ks * 8 + kc]);
                bfr[1] = __float_as_uint(Ks[brow * QK_STRIDE + ks * 8 + kc + 4]);
                mma_tf32(sacc[nb], afr[ks], bfr);
            }
        }

        float rmax0 = -INFINITY, rmax1 = -INFINITY;
        #pragma unroll
        for (int nb = 0; nb < 8; nb++) {
            #pragma unroll
            for (int r = 0; r < 4; r++) {
                const int col = nb * 8 + 2 * kc + (r & 1);
                float s = (col < klen) ? sacc[nb][r] * 0.125f : -INFINITY;
                sacc[nb][r] = s;
                if (r < 2) rmax0 = fmaxf(rmax0, s);
                else       rmax1 = fmaxf(rmax1, s);
            }
        }
        #pragma unroll
        for (int o = 1; o < 4; o <<= 1) {
            rmax0 = fmaxf(rmax0, __shfl_xor_sync(0xffffffffu, rmax0, o));
            rmax1 = fmaxf(rmax1, __shfl_xor_sync(0xffffffffu, rmax1, o));
        }
        const float mn0 = fmaxf(m0, rmax0);
        const float mn1 = fmaxf(m1, rmax1);
        const float corr0 = __expf(m0 - mn0);
        const float corr1 = __expf(m1 - mn1);
        float rsum0 = 0.f, rsum1 = 0.f;
        #pragma unroll
        for (int nb = 0; nb < 8; nb++) {
            const int cb = nb * 8 + 2 * kc;
            float p0 = __expf(sacc[nb][0] - mn0);
            float p1 = __expf(sacc[nb][1] - mn0);
            float p2 = __expf(sacc[nb][2] - mn1);
            float p3 = __expf(sacc[nb][3] - mn1);
            rsum0 += p0 + p1;
            rsum1 += p2 + p3;
            Ps[r0 * QK_STRIDE + cb]           = __uint_as_float(f2tf32(p0));
            Ps[r0 * QK_STRIDE + cb + 1]       = __uint_as_float(f2tf32(p1));
            Ps[(r0 + 8) * QK_STRIDE + cb]     = __uint_as_float(f2tf32(p2));
            Ps[(r0 + 8) * QK_STRIDE + cb + 1] = __uint_as_float(f2tf32(p3));
        }
        #pragma unroll
        for (int o = 1; o < 4; o <<= 1) {
            rsum0 += __shfl_xor_sync(0xffffffffu, rsum0, o);
            rsum1 += __shfl_xor_sync(0xffffffffu, rsum1, o);
        }
        l0 = l0 * corr0 + rsum0;
        l1 = l1 * corr1 + rsum1;
        m0 = mn0;
        m1 = mn1;
        #pragma unroll
        for (int nb = 0; nb < 8; nb++) {
            oacc[nb][0] *= corr0;
            oacc[nb][1] *= corr0;
            oacc[nb][2] *= corr1;
            oacc[nb][3] *= corr1;
        }
        __syncthreads();

        unsigned pfr[8][4];
        #pragma unroll
        for (int ks = 0; ks < 8; ks++) {
            const int kb = ks * 8 + kc;
            pfr[ks][0] = __float_as_uint(Ps[r0 * QK_STRIDE + kb]);
            pfr[ks][1] = __float_as_uint(Ps[(r0 + 8) * QK_STRIDE + kb]);
            pfr[ks][2] = __float_as_uint(Ps[r0 * QK_STRIDE + kb + 4]);
            pfr[ks][3] = __float_as_uint(Ps[(r0 + 8) * QK_STRIDE + kb + 4]);
        }
        #pragma unroll
        for (int nb = 0; nb < 8; nb++) {
            const int nn = nb * 8 + lq;
            #pragma unroll
            for (int ks = 0; ks < 8; ks++) {
                unsigned bfr[2];
                bfr[0] = __float_as_uint(Vs[(ks * 8 + kc) * V_STRIDE + nn]);
                bfr[1] = __float_as_uint(Vs[(ks * 8 + kc + 4) * V_STRIDE + nn]);
                mma_tf32(oacc[nb], pfr[ks], bfr);
            }
        }
    }

    // write O (fp16 for GEMM2)
    const float inv0 = 1.f / l0;
    const float inv1 = 1.f / l1;
    #pragma unroll
    for (int nb = 0; nb < 8; nb++) {
        const int col = nb * 8 + 2 * kc;
        if (r0 < qlen) {
            __half2 v = __floats2half2_rn(oacc[nb][0] * inv0, oacc[nb][1] * inv0);
            *reinterpret_cast<__half2*>(
                out + (size_t)(q0 + r0) * D_EMB + h * D_HEAD + col) = v;
        }
        if (r0 + 8 < qlen) {
            __half2 v = __floats2half2_rn(oacc[nb][2] * inv1, oacc[nb][3] * inv1);
            *reinterpret_cast<__half2*>(
                out + (size_t)(q0 + r0 + 8) * D_EMB + h * D_HEAD + col) = v;
        }
    }
}

// ---------------- launcher ----------------
extern "C" void kernel_launch(void* const* d_in, const int* in_sizes, int n_in,
                              void* d_out, int out_size)
{
    const float* x     = (const float*)d_in[0];
    const void*  batch = d_in[1];
    const float* W_in  = (const float*)d_in[2];
    const float* b_in  = (const float*)d_in[3];
    const float* W_out = (const float*)d_in[4];
    const float* b_out = (const float*)d_in[5];
    float*       out   = (float*)d_out;

    float*  qkv;   cudaGetSymbolAddress((void**)&qkv,   g_qkv);
    __half* attnh; cudaGetSymbolAddress((void**)&attnh, g_attnh);
    __half* xh;    cudaGetSymbolAddress((void**)&xh,    g_xh);
    __half* wih;   cudaGetSymbolAddress((void**)&wih,   g_wih);
    __half* woh;   cudaGetSymbolAddress((void**)&woh,   g_woh);

    cudaFuncSetAttribute(gemm_f16_cp,
                         cudaFuncAttributeMaxDynamicSharedMemorySize, GEMM_SMEM);
    cudaFuncSetAttribute(attn_tc,
                         cudaFuncAttributeMaxDynamicSharedMemorySize, ATTN_SMEM);

    prep_kernel<<<1, 256>>>(batch);

    // fp16 conversion passes
    {
        int n4 = (N_TOK * D_EMB) / 4;
        cvt_fp16_kernel<<<(n4 + 255) / 256, 256>>>((const float4*)x, (uint2*)xh, n4);
        n4 = (D_EMB * D3) / 4;
        cvt_fp16_kernel<<<(n4 + 255) / 256, 256>>>((const float4*)W_in, (uint2*)wih, n4);
        n4 = (D_EMB * D_EMB) / 4;
        cvt_fp16_kernel<<<(n4 + 255) / 256, 256>>>((const float4*)W_out, (uint2*)woh, n4);
    }

    {   // qkv = x @ W_in + b_in   (fp16 in, fp32 out)
        dim3 grid(D3 / 256, N_TOK / 128);
        gemm_f16_cp<<<grid, 256, GEMM_SMEM>>>(N_TOK, D3, D_EMB, xh, wih, b_in, qkv);
    }

    {   // segment-local tensor-core attention (fp16 out)
        dim3 grid(MAX_TILES, N_HEADS);
        attn_tc<<<grid, 128, ATTN_SMEM>>>(qkv, attnh);
    }

    {   // out = attn @ W_out + b_out
        dim3 grid(D_EMB / 256, N_TOK / 128);
        gemm_f16_cp<<<grid, 256, GEMM_SMEM>>>(N_TOK, D_EMB, D_EMB, attnh, woh, b_out, out);
    }
}

// round 14
// speedup vs baseline: 8.3175x; 1.3858x over previous
#include <cuda_runtime.h>
#include <cuda_fp16.h>
#include <cuda_bf16.h>
#include <math.h>

// Problem constants (fixed shapes per reference)
#define N_TOK   4096
#define D_EMB   1024
#define N_HEADS 16
#define D_HEAD  64
#define D3      (3 * D_EMB)   // 3072
#define N_GRAPHS 16

#define TQ 64
#define TK 64
#define MAX_TILES 80

// ---------------- scratch (no allocation allowed) ----------------
__device__ __half g_qkvh[N_TOK * D3];      // qkv, fp16
__device__ __half g_attnh[N_TOK * D_EMB];  // attention output, fp16
__device__ __half g_xh[N_TOK * D_EMB];     // x, fp16
__device__ __half g_wih[D_EMB * D3];       // W_in, fp16  [K][N]
__device__ __half g_woh[D_EMB * D_EMB];    // W_out, fp16 [K][N]
__device__ int    g_batch[N_TOK];
__device__ int    g_seg[N_GRAPHS + 1];
__device__ int    g_tile_seg[MAX_TILES];
__device__ int    g_tile_q0[MAX_TILES];
__device__ int    g_ntiles;

// ---------------- prep ----------------
__global__ void prep_kernel(const void* __restrict__ batch_raw) {
    const int* w32 = (const int*)batch_raw;
    const bool is32 = (w32[N_TOK - 1] != 0);
    for (int i = threadIdx.x; i < N_TOK; i += blockDim.x) {
        int v;
        if (is32) v = w32[i];
        else      v = (int)((const long long*)batch_raw)[i];
        g_batch[i] = v;
    }
    __syncthreads();
    int g = threadIdx.x;
    if (g <= N_GRAPHS) {
        int lo = 0, hi = N_TOK;
        while (lo < hi) {
            int mid = (lo + hi) >> 1;
            if (g_batch[mid] < g) lo = mid + 1; else hi = mid;
        }
        g_seg[g] = lo;
    }
    __syncthreads();
    if (threadIdx.x == 0) {
        int cnt = 0;
        for (int s = 0; s < N_GRAPHS; s++)
            for (int q = g_seg[s]; q < g_seg[s + 1]; q += TQ) {
                g_tile_seg[cnt] = s;
                g_tile_q0[cnt]  = q;
                cnt++;
            }
        g_ntiles = cnt;
    }
}

// ---------------- helpers ----------------
__device__ __forceinline__ void mma_f16(float* c, const unsigned* a, const unsigned* b) {
    asm volatile(
        "mma.sync.aligned.m16n8k16.row.col.f32.f16.f16.f32 "
        "{%0,%1,%2,%3}, {%4,%5,%6,%7}, {%8,%9}, {%0,%1,%2,%3};"
        : "+f"(c[0]), "+f"(c[1]), "+f"(c[2]), "+f"(c[3])
        : "r"(a[0]), "r"(a[1]), "r"(a[2]), "r"(a[3]),
          "r"(b[0]), "r"(b[1]));
}

__device__ __forceinline__ void cp_async16(unsigned smem_addr, const void* gptr) {
    asm volatile("cp.async.ca.shared.global [%0], [%1], 16;"
                 :: "r"(smem_addr), "l"(gptr));
}

__device__ __forceinline__ void ldm_x4(unsigned* r, unsigned addr) {
    asm volatile("ldmatrix.sync.aligned.m8n8.x4.shared.b16 {%0,%1,%2,%3}, [%4];"
                 : "=r"(r[0]), "=r"(r[1]), "=r"(r[2]), "=r"(r[3]) : "r"(addr));
}

__device__ __forceinline__ void ldm_x4_t(unsigned* r, unsigned addr) {
    asm volatile("ldmatrix.sync.aligned.m8n8.x4.trans.shared.b16 {%0,%1,%2,%3}, [%4];"
                 : "=r"(r[0]), "=r"(r[1]), "=r"(r[2]), "=r"(r[3]) : "r"(addr));
}

// ---------------- fp32 -> fp16 conversion pass ----------------
__global__ void cvt_fp16_kernel(const float4* __restrict__ in,
                                uint2* __restrict__ out, int n4) {
    int i = blockIdx.x * blockDim.x + threadIdx.x;
    if (i < n4) {
        float4 v = in[i];
        __half2 lo = __floats2half2_rn(v.x, v.y);
        __half2 hi = __floats2half2_rn(v.z, v.w);
        uint2 r;
        r.x = *reinterpret_cast<unsigned*>(&lo);
        r.y = *reinterpret_cast<unsigned*>(&hi);
        out[i] = r;
    }
}

// ---------------- fp16 GEMM: block 128x256, warp 64x64, ldmatrix + m16n8k16 ----------------
// C[M,N] = A[M,K] @ B[K,N] + bias[N]; A,B fp16, C fp32 or fp16.
#define A_STRIDE_B 80
#define B_STRIDE_B 528
#define A_BYTES (128 * A_STRIDE_B)
#define B_BYTES (32 * B_STRIDE_B)
#define GEMM_SMEM (2 * (A_BYTES + B_BYTES))

template <typename OutT>
__global__ __launch_bounds__(256, 1)
void gemm_f16_cp(int M, int N, int K,
                 const __half* __restrict__ A,
                 const __half* __restrict__ B,
                 const float* __restrict__ bias,
                 OutT* __restrict__ C)
{
    extern __shared__ char smem[];
    const unsigned s0 = (unsigned)__cvta_generic_to_shared(smem);
    const unsigned aS[2] = { s0,              s0 + A_BYTES };
    const unsigned bS[2] = { s0 + 2*A_BYTES,  s0 + 2*A_BYTES + B_BYTES };

    const int tid  = threadIdx.x;
    const int warp = tid >> 5;
    const int lane = tid & 31;
    const int wm   = warp >> 2;
    const int wn   = warp & 3;
    const int bm   = blockIdx.y * 128;
    const int bn   = blockIdx.x * 256;

    const int ar  = tid >> 1;
    const int ac2 = (tid & 1) * 2;
    const int bkr = tid >> 3;
    const int bc  = tid & 7;

    const __half* aSrc = A + (size_t)(bm + ar) * K + ac2 * 8;
    const __half* bSrc = B + (size_t)bkr * N + bn;

    auto cp_tile = [&](int kt, int buf) {
        const int k0 = kt << 5;
        const __half* as = aSrc + k0;
        #pragma unroll
        for (int j = 0; j < 2; j++)
            cp_async16(aS[buf] + (unsigned)(ar * A_STRIDE_B + (ac2 + j) * 16),
                       as + j * 8);
        const __half* bs = bSrc + (size_t)k0 * N;
        #pragma unroll
        for (int q = 0; q < 4; q++)
            cp_async16(bS[buf] + (unsigned)(bkr * B_STRIDE_B + (bc + 8 * q) * 16),
                       bs + (bc + 8 * q) * 8);
        asm volatile("cp.async.commit_group;");
    };

    float acc[4][8][4];
    #pragma unroll
    for (int i = 0; i < 4; i++)
        #pragma unroll
        for (int j = 0; j < 8; j++)
            #pragma unroll
            for (int r = 0; r < 4; r++) acc[i][j][r] = 0.f;

    const int lrow = lane & 15;
    const int lseg = lane >> 4;

    const int KT = K >> 5;
    cp_tile(0, 0);

    for (int kt = 0; kt < KT; kt++) {
        const int buf = kt & 1;
        asm volatile("cp.async.wait_group 0;");
        __syncthreads();
        if (kt + 1 < KT) cp_tile(kt + 1, buf ^ 1);

        #pragma unroll
        for (int kb = 0; kb < 2; kb++) {
            unsigned afr[4][4], bfr[4][4];
            #pragma unroll
            for (int i = 0; i < 4; i++) {
                const unsigned ad = aS[buf]
                    + (unsigned)((wm * 64 + i * 16 + lrow) * A_STRIDE_B
                                 + kb * 32 + lseg * 16);
                ldm_x4(afr[i], ad);
            }
            #pragma unroll
            for (int j = 0; j < 4; j++) {
                const unsigned bd = bS[buf]
                    + (unsigned)((kb * 16 + lrow) * B_STRIDE_B
                                 + wn * 128 + j * 32 + lseg * 16);
                ldm_x4_t(bfr[j], bd);
            }
            #pragma unroll
            for (int i = 0; i < 4; i++)
                #pragma unroll
                for (int j8 = 0; j8 < 8; j8++)
                    mma_f16(acc[i][j8], afr[i], &bfr[j8 >> 1][(j8 & 1) * 2]);
        }
        __syncthreads();
    }

    // epilogue: bias + store (fp32 or fp16)
    const int lg = lane >> 2;
    const int lc = lane & 3;
    #pragma unroll
    for (int i = 0; i < 4; i++) {
        const int m0 = bm + wm * 64 + i * 16 + lg;
        #pragma unroll
        for (int j = 0; j < 8; j++) {
            const int n0 = bn + wn * 64 + j * 8 + lc * 2;
            const float bx = bias[n0];
            const float by = bias[n0 + 1];
            if constexpr (sizeof(OutT) == 4) {
                float2 v0 = make_float2(acc[i][j][0] + bx, acc[i][j][1] + by);
                float2 v1 = make_float2(acc[i][j][2] + bx, acc[i][j][3] + by);
                *reinterpret_cast<float2*>((float*)C + (size_t)m0 * N + n0)       = v0;
                *reinterpret_cast<float2*>((float*)C + (size_t)(m0 + 8) * N + n0) = v1;
            } else {
                __half2 v0 = __floats2half2_rn(acc[i][j][0] + bx, acc[i][j][1] + by);
                __half2 v1 = __floats2half2_rn(acc[i][j][2] + bx, acc[i][j][3] + by);
                *reinterpret_cast<__half2*>((__half*)C + (size_t)m0 * N + n0)       = v0;
                *reinterpret_cast<__half2*>((__half*)C + (size_t)(m0 + 8) * N + n0) = v1;
            }
        }
    }
}

// ---------------- fp16 tensor-core flash attention ----------------
// One block per (head, 64-q tile); 128 threads = 4 warps, warp owns 16 rows.
#define AQ_STR 72   // halves per row = 144 B (9 x 16B chunks)

__global__ __launch_bounds__(128)
void attn_f16(const __half* __restrict__ qkv, __half* __restrict__ out)
{
    const int tile = blockIdx.x;
    if (tile >= g_ntiles) return;
    const int h   = blockIdx.y;
    const int seg = g_tile_seg[tile];
    const int q0  = g_tile_q0[tile];
    const int e   = g_seg[seg + 1];
    const int qlen = min(TQ, e - q0);

    __shared__ __half Qs[64 * AQ_STR];
    __shared__ __half Ks[64 * AQ_STR];
    __shared__ __half Ps[64 * AQ_STR];
    __shared__ __half Vs[64 * AQ_STR];

    const unsigned qB = (unsigned)__cvta_generic_to_shared(Qs);
    const unsigned kB = (unsigned)__cvta_generic_to_shared(Ks);
    const unsigned pB = (unsigned)__cvta_generic_to_shared(Ps);
    const unsigned vB = (unsigned)__cvta_generic_to_shared(Vs);

    const int tid  = threadIdx.x;
    const int warp = tid >> 5;
    const int lane = tid & 31;
    const int lq   = lane >> 2;
    const int kc   = lane & 3;
    const int lrow = lane & 15;
    const int lseg = lane >> 4;

    // ---- load Q: 64 rows x 64 halves = 512 16B-chunks over 128 threads ----
    #pragma unroll
    for (int c = tid; c < 512; c += 128) {
        const int row = c >> 3, ch = c & 7;
        uint4 v = (row < qlen)
            ? *reinterpret_cast<const uint4*>(qkv + (size_t)(q0 + row) * D3 + h * D_HEAD + ch * 8)
            : make_uint4(0, 0, 0, 0);
        *reinterpret_cast<uint4*>(&Qs[row * AQ_STR + ch * 8]) = v;
    }

    const int r0 = warp * 16 + lq;

    float m0 = -INFINITY, m1 = -INFINITY, l0 = 0.f, l1 = 0.f;
    float oacc[8][4];
    #pragma unroll
    for (int nb = 0; nb < 8; nb++)
        #pragma unroll
        for (int r = 0; r < 4; r++) oacc[nb][r] = 0.f;

    for (int mm0 = g_seg[seg]; mm0 < e; mm0 += TK) {
        const int klen = min(TK, e - mm0);
        __syncthreads();

        // ---- load K, V: 512 chunks each ----
        #pragma unroll
        for (int c = tid; c < 512; c += 128) {
            const int row = c >> 3, ch = c & 7;
            const bool valid = (row < klen);
            uint4 kv = valid
                ? *reinterpret_cast<const uint4*>(qkv + (size_t)(mm0 + row) * D3 + D_EMB + h * D_HEAD + ch * 8)
                : make_uint4(0, 0, 0, 0);
            *reinterpret_cast<uint4*>(&Ks[row * AQ_STR + ch * 8]) = kv;
            uint4 vv = valid
                ? *reinterpret_cast<const uint4*>(qkv + (size_t)(mm0 + row) * D3 + 2 * D_EMB + h * D_HEAD + ch * 8)
                : make_uint4(0, 0, 0, 0);
            *reinterpret_cast<uint4*>(&Vs[row * AQ_STR + ch * 8]) = vv;
        }
        __syncthreads();

        // ---- S = Q @ K^T (fp16 m16n8k16) ----
        unsigned aq[4][4];
        #pragma unroll
        for (int kb = 0; kb < 4; kb++)
            ldm_x4(aq[kb], qB + (unsigned)(((warp * 16 + lrow) * AQ_STR + kb * 16 + lseg * 8) * 2));

        float sacc[8][4];
        #pragma unroll
        for (int nb = 0; nb < 8; nb++)
            #pragma unroll
            for (int r = 0; r < 4; r++) sacc[nb][r] = 0.f;

        #pragma unroll
        for (int kb = 0; kb < 4; kb++) {
            #pragma unroll
            for (int nbb = 0; nbb < 4; nbb++) {
                unsigned bk[4];
                ldm_x4(bk, kB + (unsigned)(((nbb * 16 + lrow) * AQ_STR + kb * 16 + lseg * 8) * 2));
                unsigned b0[2] = { bk[0], bk[2] };
                unsigned b1[2] = { bk[1], bk[3] };
                mma_f16(sacc[2 * nbb],     aq[kb], b0);
                mma_f16(sacc[2 * nbb + 1], aq[kb], b1);
            }
        }

        // ---- online softmax (fp32) ----
        float rmax0 = -INFINITY, rmax1 = -INFINITY;
        #pragma unroll
        for (int nb = 0; nb < 8; nb++) {
            #pragma unroll
            for (int r = 0; r < 4; r++) {
                const int col = nb * 8 + 2 * kc + (r & 1);
                float s = (col < klen) ? sacc[nb][r] * 0.125f : -INFINITY;
                sacc[nb][r] = s;
                if (r < 2) rmax0 = fmaxf(rmax0, s);
                else       rmax1 = fmaxf(rmax1, s);
            }
        }
        #pragma unroll
        for (int o = 1; o < 4; o <<= 1) {
            rmax0 = fmaxf(rmax0, __shfl_xor_sync(0xffffffffu, rmax0, o));
            rmax1 = fmaxf(rmax1, __shfl_xor_sync(0xffffffffu, rmax1, o));
        }
        const float mn0 = fmaxf(m0, rmax0);
        const float mn1 = fmaxf(m1, rmax1);
        const float corr0 = __expf(m0 - mn0);
        const float corr1 = __expf(m1 - mn1);
        float rsum0 = 0.f, rsum1 = 0.f;
        #pragma unroll
        for (int nb = 0; nb < 8; nb++) {
            const int cb = nb * 8 + 2 * kc;
            float p0 = __expf(sacc[nb][0] - mn0);
            float p1 = __expf(sacc[nb][1] - mn0);
            float p2 = __expf(sacc[nb][2] - mn1);
            float p3 = __expf(sacc[nb][3] - mn1);
            rsum0 += p0 + p1;
            rsum1 += p2 + p3;
            *reinterpret_cast<__half2*>(&Ps[r0 * AQ_STR + cb])       = __floats2half2_rn(p0, p1);
            *reinterpret_cast<__half2*>(&Ps[(r0 + 8) * AQ_STR + cb]) = __floats2half2_rn(p2, p3);
        }
        #pragma unroll
        for (int o = 1; o < 4; o <<= 1) {
            rsum0 += __shfl_xor_sync(0xffffffffu, rsum0, o);
            rsum1 += __shfl_xor_sync(0xffffffffu, rsum1, o);
        }
        l0 = l0 * corr0 + rsum0;
        l1 = l1 * corr1 + rsum1;
        m0 = mn0;
        m1 = mn1;
        #pragma unroll
        for (int nb = 0; nb < 8; nb++) {
            oacc[nb][0] *= corr0;
            oacc[nb][1] *= corr0;
            oacc[nb][2] *= corr1;
            oacc[nb][3] *= corr1;
        }
        __syncwarp();   // warp reads back only its own P rows

        // ---- O += P @ V (fp16 m16n8k16, V via trans ldmatrix) ----
        unsigned ap[4][4];
        #pragma unroll
        for (int kb = 0; kb < 4; kb++)
            ldm_x4(ap[kb], pB + (unsigned)(((warp * 16 + lrow) * AQ_STR + kb * 16 + lseg * 8) * 2));

        #pragma unroll
        for (int kb = 0; kb < 4; kb++) {
            #pragma unroll
            for (int j = 0; j < 4; j++) {
                unsigned bv[4];
                ldm_x4_t(bv, vB + (unsigned)(((kb * 16 + lrow) * AQ_STR + j * 16 + lseg * 8) * 2));
                mma_f16(oacc[2 * j],     ap[kb], &bv[0]);
                mma_f16(oacc[2 * j + 1], ap[kb], &bv[2]);
            }
        }
    }

    // ---- write O (fp16 for GEMM2) ----
    const float inv0 = 1.f / l0;
    const float inv1 = 1.f / l1;
    #pragma unroll
    for (int nb = 0; nb < 8; nb++) {
        const int col = nb * 8 + 2 * kc;
        if (r0 < qlen) {
            __half2 v = __floats2half2_rn(oacc[nb][0] * inv0, oacc[nb][1] * inv0);
            *reinterpret_cast<__half2*>(
                out + (size_t)(q0 + r0) * D_EMB + h * D_HEAD + col) = v;
        }
        if (r0 + 8 < qlen) {
            __half2 v = __floats2half2_rn(oacc[nb][2] * inv1, oacc[nb][3] * inv1);
            *reinterpret_cast<__half2*>(
                out + (size_t)(q0 + r0 + 8) * D_EMB + h * D_HEAD + col) = v;
        }
    }
}

// ---------------- launcher ----------------
extern "C" void kernel_launch(void* const* d_in, const int* in_sizes, int n_in,
                              void* d_out, int out_size)
{
    const float* x     = (const float*)d_in[0];
    const void*  batch = d_in[1];
    const float* W_in  = (const float*)d_in[2];
    const float* b_in  = (const float*)d_in[3];
    const float* W_out = (const float*)d_in[4];
    const float* b_out = (const float*)d_in[5];
    float*       out   = (float*)d_out;

    __half* qkvh;  cudaGetSymbolAddress((void**)&qkvh,  g_qkvh);
    __half* attnh; cudaGetSymbolAddress((void**)&attnh, g_attnh);
    __half* xh;    cudaGetSymbolAddress((void**)&xh,    g_xh);
    __half* wih;   cudaGetSymbolAddress((void**)&wih,   g_wih);
    __half* woh;   cudaGetSymbolAddress((void**)&woh,   g_woh);

    cudaFuncSetAttribute(gemm_f16_cp<__half>,
                         cudaFuncAttributeMaxDynamicSharedMemorySize, GEMM_SMEM);
    cudaFuncSetAttribute(gemm_f16_cp<float>,
                         cudaFuncAttributeMaxDynamicSharedMemorySize, GEMM_SMEM);

    prep_kernel<<<1, 256>>>(batch);

    // fp16 conversion passes
    {
        int n4 = (N_TOK * D_EMB) / 4;
        cvt_fp16_kernel<<<(n4 + 255) / 256, 256>>>((const float4*)x, (uint2*)xh, n4);
        n4 = (D_EMB * D3) / 4;
        cvt_fp16_kernel<<<(n4 + 255) / 256, 256>>>((const float4*)W_in, (uint2*)wih, n4);
        n4 = (D_EMB * D_EMB) / 4;
        cvt_fp16_kernel<<<(n4 + 255) / 256, 256>>>((const float4*)W_out, (uint2*)woh, n4);
    }

    {   // qkv = x @ W_in + b_in   (fp16 in, fp16 out)
        dim3 grid(D3 / 256, N_TOK / 128);
        gemm_f16_cp<__half><<<grid, 256, GEMM_SMEM>>>(N_TOK, D3, D_EMB, xh, wih, b_in, qkvh);
    }

    {   // segment-local fp16 tensor-core attention
        dim3 grid(MAX_TILES, N_HEADS);
        attn_f16<<<grid, 128>>>(qkvh, attnh);
    }

    {   // out = attn @ W_out + b_out  (fp32 out)
        dim3 grid(D_EMB / 256, N_TOK / 128);
        gemm_f16_cp<float><<<grid, 256, GEMM_SMEM>>>(N_TOK, D_EMB, D_EMB, attnh, woh, b_out, out);
    }
}

// round 15
// speedup vs baseline: 9.0212x; 1.0846x over previous
#include <cuda_runtime.h>
#include <cuda_fp16.h>
#include <cuda_bf16.h>
#include <math.h>

// Problem constants (fixed shapes per reference)
#define N_TOK   4096
#define D_EMB   1024
#define N_HEADS 16
#define D_HEAD  64
#define D3      (3 * D_EMB)   // 3072
#define N_GRAPHS 16

#define TQ 64
#define TK 64
#define MAX_TILES 80

// ---------------- scratch (no allocation allowed) ----------------
__device__ __half g_qkvh[N_TOK * D3];      // qkv, fp16
__device__ __half g_attnh[N_TOK * D_EMB];  // attention output, fp16
__device__ __half g_xh[N_TOK * D_EMB];     // x, fp16
__device__ __half g_wih[D_EMB * D3];       // W_in, fp16  [K][N]
__device__ __half g_woh[D_EMB * D_EMB];    // W_out, fp16 [K][N]
__device__ int    g_batch[N_TOK];
__device__ int    g_seg[N_GRAPHS + 1];
__device__ int    g_tile_seg[MAX_TILES];
__device__ int    g_tile_q0[MAX_TILES];
__device__ int    g_ntiles;

// ---------------- prep ----------------
__global__ void prep_kernel(const void* __restrict__ batch_raw) {
    const int* w32 = (const int*)batch_raw;
    const bool is32 = (w32[N_TOK - 1] != 0);
    for (int i = threadIdx.x; i < N_TOK; i += blockDim.x) {
        int v;
        if (is32) v = w32[i];
        else      v = (int)((const long long*)batch_raw)[i];
        g_batch[i] = v;
    }
    __syncthreads();
    int g = threadIdx.x;
    if (g <= N_GRAPHS) {
        int lo = 0, hi = N_TOK;
        while (lo < hi) {
            int mid = (lo + hi) >> 1;
            if (g_batch[mid] < g) lo = mid + 1; else hi = mid;
        }
        g_seg[g] = lo;
    }
    __syncthreads();
    if (threadIdx.x == 0) {
        int cnt = 0;
        for (int s = 0; s < N_GRAPHS; s++)
            for (int q = g_seg[s]; q < g_seg[s + 1]; q += TQ) {
                g_tile_seg[cnt] = s;
                g_tile_q0[cnt]  = q;
                cnt++;
            }
        g_ntiles = cnt;
    }
}

// ---------------- helpers ----------------
__device__ __forceinline__ void mma_f16(float* c, const unsigned* a, const unsigned* b) {
    asm volatile(
        "mma.sync.aligned.m16n8k16.row.col.f32.f16.f16.f32 "
        "{%0,%1,%2,%3}, {%4,%5,%6,%7}, {%8,%9}, {%0,%1,%2,%3};"
        : "+f"(c[0]), "+f"(c[1]), "+f"(c[2]), "+f"(c[3])
        : "r"(a[0]), "r"(a[1]), "r"(a[2]), "r"(a[3]),
          "r"(b[0]), "r"(b[1]));
}

__device__ __forceinline__ void cp_async16(unsigned smem_addr, const void* gptr) {
    asm volatile("cp.async.ca.shared.global [%0], [%1], 16;"
                 :: "r"(smem_addr), "l"(gptr));
}

__device__ __forceinline__ void ldm_x4(unsigned* r, unsigned addr) {
    asm volatile("ldmatrix.sync.aligned.m8n8.x4.shared.b16 {%0,%1,%2,%3}, [%4];"
                 : "=r"(r[0]), "=r"(r[1]), "=r"(r[2]), "=r"(r[3]) : "r"(addr));
}

__device__ __forceinline__ void ldm_x4_t(unsigned* r, unsigned addr) {
    asm volatile("ldmatrix.sync.aligned.m8n8.x4.trans.shared.b16 {%0,%1,%2,%3}, [%4];"
                 : "=r"(r[0]), "=r"(r[1]), "=r"(r[2]), "=r"(r[3]) : "r"(addr));
}

// ---------------- fused fp32 -> fp16 conversion (x, W_in, W_out in one launch) ----------------
__global__ void cvt_all_fp16(const float4* __restrict__ x,   uint2* __restrict__ xo,   int nx,
                             const float4* __restrict__ wi,  uint2* __restrict__ wio,  int nwi,
                             const float4* __restrict__ wo,  uint2* __restrict__ woo,  int nwo) {
    int i = blockIdx.x * blockDim.x + threadIdx.x;
    const float4* in;
    uint2* out;
    int j;
    if (i < nx)                 { in = x;  out = xo;  j = i; }
    else if (i < nx + nwi)      { in = wi; out = wio; j = i - nx; }
    else if (i < nx + nwi + nwo){ in = wo; out = woo; j = i - nx - nwi; }
    else return;
    float4 v = in[j];
    __half2 lo = __floats2half2_rn(v.x, v.y);
    __half2 hi = __floats2half2_rn(v.z, v.w);
    uint2 r;
    r.x = *reinterpret_cast<unsigned*>(&lo);
    r.y = *reinterpret_cast<unsigned*>(&hi);
    out[j] = r;
}

// ---------------- fp16 GEMM: block 128x256, warp 64x64, BK=64, ldmatrix + m16n8k16 ----------------
// C[M,N] = A[M,K] @ B[K,N] + bias[N]; A,B fp16, C fp32 or fp16. K mult of 64, N mult of 256.
#define A_STRIDE_B 144         // bytes/row: 64 halves (128B) + 16 pad; 9x16B odd -> ldm conflict-free
#define B_STRIDE_B 528         // bytes/row: 256 halves + pad
#define A_BYTES (128 * A_STRIDE_B)   // 18432
#define B_BYTES (64 * B_STRIDE_B)    // 33792
#define GEMM_SMEM (2 * (A_BYTES + B_BYTES))   // 104448

template <typename OutT>
__global__ __launch_bounds__(256, 1)
void gemm_f16_cp(int M, int N, int K,
                 const __half* __restrict__ A,
                 const __half* __restrict__ B,
                 const float* __restrict__ bias,
                 OutT* __restrict__ C)
{
    extern __shared__ char smem[];
    const unsigned s0 = (unsigned)__cvta_generic_to_shared(smem);
    const unsigned aS[2] = { s0,              s0 + A_BYTES };
    const unsigned bS[2] = { s0 + 2*A_BYTES,  s0 + 2*A_BYTES + B_BYTES };

    const int tid  = threadIdx.x;
    const int warp = tid >> 5;
    const int lane = tid & 31;
    const int wm   = warp >> 2;
    const int wn   = warp & 3;
    const int bm   = blockIdx.y * 128;
    const int bn   = blockIdx.x * 256;

    // cp.async mapping (BK=64)
    const int ar  = tid >> 1;            // A row 0..127
    const int ac4 = (tid & 1) * 4;       // A chunks ac4..ac4+3 (16B each; 8 chunks/row)
    const int bkr = tid >> 2;            // B k-row 0..63
    const int bc  = tid & 3;             // B chunks bc + 4q, q=0..7 (32 chunks/row)

    const __half* aSrc = A + (size_t)(bm + ar) * K + ac4 * 8;
    const __half* bSrc = B + (size_t)bkr * N + bn;

    auto cp_tile = [&](int kt, int buf) {
        const int k0 = kt << 6;
        const __half* as = aSrc + k0;
        #pragma unroll
        for (int j = 0; j < 4; j++)
            cp_async16(aS[buf] + (unsigned)(ar * A_STRIDE_B + (ac4 + j) * 16),
                       as + j * 8);
        const __half* bs = bSrc + (size_t)k0 * N;
        #pragma unroll
        for (int q = 0; q < 8; q++)
            cp_async16(bS[buf] + (unsigned)(bkr * B_STRIDE_B + (bc + 4 * q) * 16),
                       bs + (bc + 4 * q) * 8);
        asm volatile("cp.async.commit_group;");
    };

    float acc[4][8][4];
    #pragma unroll
    for (int i = 0; i < 4; i++)
        #pragma unroll
        for (int j = 0; j < 8; j++)
            #pragma unroll
            for (int r = 0; r < 4; r++) acc[i][j][r] = 0.f;

    const int lrow = lane & 15;
    const int lseg = lane >> 4;

    const int KT = K >> 6;
    cp_tile(0, 0);

    for (int kt = 0; kt < KT; kt++) {
        const int buf = kt & 1;
        asm volatile("cp.async.wait_group 0;");
        __syncthreads();
        if (kt + 1 < KT) cp_tile(kt + 1, buf ^ 1);

        #pragma unroll
        for (int kb = 0; kb < 4; kb++) {   // 4 k16 steps per BK=64 tile
            unsigned afr[4][4], bfr[4][4];
            #pragma unroll
            for (int i = 0; i < 4; i++) {
                const unsigned ad = aS[buf]
                    + (unsigned)((wm * 64 + i * 16 + lrow) * A_STRIDE_B
                                 + kb * 32 + lseg * 16);
                ldm_x4(afr[i], ad);
            }
            #pragma unroll
            for (int j = 0; j < 4; j++) {
                const unsigned bd = bS[buf]
                    + (unsigned)((kb * 16 + lrow) * B_STRIDE_B
                                 + wn * 128 + j * 32 + lseg * 16);
                ldm_x4_t(bfr[j], bd);
            }
            #pragma unroll
            for (int i = 0; i < 4; i++)
                #pragma unroll
                for (int j8 = 0; j8 < 8; j8++)
                    mma_f16(acc[i][j8], afr[i], &bfr[j8 >> 1][(j8 & 1) * 2]);
        }
        __syncthreads();
    }

    // epilogue: bias + store (fp32 or fp16)
    const int lg = lane >> 2;
    const int lc = lane & 3;
    #pragma unroll
    for (int i = 0; i < 4; i++) {
        const int m0 = bm + wm * 64 + i * 16 + lg;
        #pragma unroll
        for (int j = 0; j < 8; j++) {
            const int n0 = bn + wn * 64 + j * 8 + lc * 2;
            const float bx = bias[n0];
            const float by = bias[n0 + 1];
            if constexpr (sizeof(OutT) == 4) {
                float2 v0 = make_float2(acc[i][j][0] + bx, acc[i][j][1] + by);
                float2 v1 = make_float2(acc[i][j][2] + bx, acc[i][j][3] + by);
                *reinterpret_cast<float2*>((float*)C + (size_t)m0 * N + n0)       = v0;
                *reinterpret_cast<float2*>((float*)C + (size_t)(m0 + 8) * N + n0) = v1;
            } else {
                __half2 v0 = __floats2half2_rn(acc[i][j][0] + bx, acc[i][j][1] + by);
                __half2 v1 = __floats2half2_rn(acc[i][j][2] + bx, acc[i][j][3] + by);
                *reinterpret_cast<__half2*>((__half*)C + (size_t)m0 * N + n0)       = v0;
                *reinterpret_cast<__half2*>((__half*)C + (size_t)(m0 + 8) * N + n0) = v1;
            }
        }
    }
}

// ---------------- fp16 tensor-core flash attention (R14) ----------------
#define AQ_STR 72   // halves per row = 144 B

__global__ __launch_bounds__(128)
void attn_f16(const __half* __restrict__ qkv, __half* __restrict__ out)
{
    const int tile = blockIdx.x;
    if (tile >= g_ntiles) return;
    const int h   = blockIdx.y;
    const int seg = g_tile_seg[tile];
    const int q0  = g_tile_q0[tile];
    const int e   = g_seg[seg + 1];
    const int qlen = min(TQ, e - q0);

    __shared__ __half Qs[64 * AQ_STR];
    __shared__ __half Ks[64 * AQ_STR];
    __shared__ __half Ps[64 * AQ_STR];
    __shared__ __half Vs[64 * AQ_STR];

    const unsigned qB = (unsigned)__cvta_generic_to_shared(Qs);
    const unsigned kB = (unsigned)__cvta_generic_to_shared(Ks);
    const unsigned pB = (unsigned)__cvta_generic_to_shared(Ps);
    const unsigned vB = (unsigned)__cvta_generic_to_shared(Vs);

    const int tid  = threadIdx.x;
    const int warp = tid >> 5;
    const int lane = tid & 31;
    const int lq   = lane >> 2;
    const int kc   = lane & 3;
    const int lrow = lane & 15;
    const int lseg = lane >> 4;

    // ---- load Q: 64 rows x 64 halves = 512 16B-chunks ----
    #pragma unroll
    for (int c = tid; c < 512; c += 128) {
        const int row = c >> 3, ch = c & 7;
        uint4 v = (row < qlen)
            ? *reinterpret_cast<const uint4*>(qkv + (size_t)(q0 + row) * D3 + h * D_HEAD + ch * 8)
            : make_uint4(0, 0, 0, 0);
        *reinterpret_cast<uint4*>(&Qs[row * AQ_STR + ch * 8]) = v;
    }

    const int r0 = warp * 16 + lq;

    float m0 = -INFINITY, m1 = -INFINITY, l0 = 0.f, l1 = 0.f;
    float oacc[8][4];
    #pragma unroll
    for (int nb = 0; nb < 8; nb++)
        #pragma unroll
        for (int r = 0; r < 4; r++) oacc[nb][r] = 0.f;

    for (int mm0 = g_seg[seg]; mm0 < e; mm0 += TK) {
        const int klen = min(TK, e - mm0);
        __syncthreads();

        #pragma unroll
        for (int c = tid; c < 512; c += 128) {
            const int row = c >> 3, ch = c & 7;
            const bool valid = (row < klen);
            uint4 kv = valid
                ? *reinterpret_cast<const uint4*>(qkv + (size_t)(mm0 + row) * D3 + D_EMB + h * D_HEAD + ch * 8)
                : make_uint4(0, 0, 0, 0);
            *reinterpret_cast<uint4*>(&Ks[row * AQ_STR + ch * 8]) = kv;
            uint4 vv = valid
                ? *reinterpret_cast<const uint4*>(qkv + (size_t)(mm0 + row) * D3 + 2 * D_EMB + h * D_HEAD + ch * 8)
                : make_uint4(0, 0, 0, 0);
            *reinterpret_cast<uint4*>(&Vs[row * AQ_STR + ch * 8]) = vv;
        }
        __syncthreads();

        // ---- S = Q @ K^T ----
        unsigned aq[4][4];
        #pragma unroll
        for (int kb = 0; kb < 4; kb++)
            ldm_x4(aq[kb], qB + (unsigned)(((warp * 16 + lrow) * AQ_STR + kb * 16 + lseg * 8) * 2));

        float sacc[8][4];
        #pragma unroll
        for (int nb = 0; nb < 8; nb++)
            #pragma unroll
            for (int r = 0; r < 4; r++) sacc[nb][r] = 0.f;

        #pragma unroll
        for (int kb = 0; kb < 4; kb++) {
            #pragma unroll
            for (int nbb = 0; nbb < 4; nbb++) {
                unsigned bk[4];
                ldm_x4(bk, kB + (unsigned)(((nbb * 16 + lrow) * AQ_STR + kb * 16 + lseg * 8) * 2));
                unsigned b0[2] = { bk[0], bk[2] };
                unsigned b1[2] = { bk[1], bk[3] };
                mma_f16(sacc[2 * nbb],     aq[kb], b0);
                mma_f16(sacc[2 * nbb + 1], aq[kb], b1);
            }
        }

        // ---- online softmax (fp32) ----
        float rmax0 = -INFINITY, rmax1 = -INFINITY;
        #pragma unroll
        for (int nb = 0; nb < 8; nb++) {
            #pragma unroll
            for (int r = 0; r < 4; r++) {
                const int col = nb * 8 + 2 * kc + (r & 1);
                float s = (col < klen) ? sacc[nb][r] * 0.125f : -INFINITY;
                sacc[nb][r] = s;
                if (r < 2) rmax0 = fmaxf(rmax0, s);
                else       rmax1 = fmaxf(rmax1, s);
            }
        }
        #pragma unroll
        for (int o = 1; o < 4; o <<= 1) {
            rmax0 = fmaxf(rmax0, __shfl_xor_sync(0xffffffffu, rmax0, o));
            rmax1 = fmaxf(rmax1, __shfl_xor_sync(0xffffffffu, rmax1, o));
        }
        const float mn0 = fmaxf(m0, rmax0);
        const float mn1 = fmaxf(m1, rmax1);
        const float corr0 = __expf(m0 - mn0);
        const float corr1 = __expf(m1 - mn1);
        float rsum0 = 0.f, rsum1 = 0.f;
        #pragma unroll
        for (int nb = 0; nb < 8; nb++) {
            const int cb = nb * 8 + 2 * kc;
            float p0 = __expf(sacc[nb][0] - mn0);
            float p1 = __expf(sacc[nb][1] - mn0);
            float p2 = __expf(sacc[nb][2] - mn1);
            float p3 = __expf(sacc[nb][3] - mn1);
            rsum0 += p0 + p1;
            rsum1 += p2 + p3;
            *reinterpret_cast<__half2*>(&Ps[r0 * AQ_STR + cb])       = __floats2half2_rn(p0, p1);
            *reinterpret_cast<__half2*>(&Ps[(r0 + 8) * AQ_STR + cb]) = __floats2half2_rn(p2, p3);
        }
        #pragma unroll
        for (int o = 1; o < 4; o <<= 1) {
            rsum0 += __shfl_xor_sync(0xffffffffu, rsum0, o);
            rsum1 += __shfl_xor_sync(0xffffffffu, rsum1, o);
        }
        l0 = l0 * corr0 + rsum0;
        l1 = l1 * corr1 + rsum1;
        m0 = mn0;
        m1 = mn1;
        #pragma unroll
        for (int nb = 0; nb < 8; nb++) {
            oacc[nb][0] *= corr0;
            oacc[nb][1] *= corr0;
            oacc[nb][2] *= corr1;
            oacc[nb][3] *= corr1;
        }
        __syncwarp();

        // ---- O += P @ V ----
        unsigned ap[4][4];
        #pragma unroll
        for (int kb = 0; kb < 4; kb++)
            ldm_x4(ap[kb], pB + (unsigned)(((warp * 16 + lrow) * AQ_STR + kb * 16 + lseg * 8) * 2));

        #pragma unroll
        for (int kb = 0; kb < 4; kb++) {
            #pragma unroll
            for (int j = 0; j < 4; j++) {
                unsigned bv[4];
                ldm_x4_t(bv, vB + (unsigned)(((kb * 16 + lrow) * AQ_STR + j * 16 + lseg * 8) * 2));
                mma_f16(oacc[2 * j],     ap[kb], &bv[0]);
                mma_f16(oacc[2 * j + 1], ap[kb], &bv[2]);
            }
        }
    }

    // ---- write O (fp16 for GEMM2) ----
    const float inv0 = 1.f / l0;
    const float inv1 = 1.f / l1;
    #pragma unroll
    for (int nb = 0; nb < 8; nb++) {
        const int col = nb * 8 + 2 * kc;
        if (r0 < qlen) {
            __half2 v = __floats2half2_rn(oacc[nb][0] * inv0, oacc[nb][1] * inv0);
            *reinterpret_cast<__half2*>(
                out + (size_t)(q0 + r0) * D_EMB + h * D_HEAD + col) = v;
        }
        if (r0 + 8 < qlen) {
            __half2 v = __floats2half2_rn(oacc[nb][2] * inv1, oacc[nb][3] * inv1);
            *reinterpret_cast<__half2*>(
                out + (size_t)(q0 + r0 + 8) * D_EMB + h * D_HEAD + col) = v;
        }
    }
}

// ---------------- launcher ----------------
extern "C" void kernel_launch(void* const* d_in, const int* in_sizes, int n_in,
                              void* d_out, int out_size)
{
    const float* x     = (const float*)d_in[0];
    const void*  batch = d_in[1];
    const float* W_in  = (const float*)d_in[2];
    const float* b_in  = (const float*)d_in[3];
    const float* W_out = (const float*)d_in[4];
    const float* b_out = (const float*)d_in[5];
    float*       out   = (float*)d_out;

    __half* qkvh;  cudaGetSymbolAddress((void**)&qkvh,  g_qkvh);
    __half* attnh; cudaGetSymbolAddress((void**)&attnh, g_attnh);
    __half* xh;    cudaGetSymbolAddress((void**)&xh,    g_xh);
    __half* wih;   cudaGetSymbolAddress((void**)&wih,   g_wih);
    __half* woh;   cudaGetSymbolAddress((void**)&woh,   g_woh);

    cudaFuncSetAttribute(gemm_f16_cp<__half>,
                         cudaFuncAttributeMaxDynamicSharedMemorySize, GEMM_SMEM);
    cudaFuncSetAttribute(gemm_f16_cp<float>,
                         cudaFuncAttributeMaxDynamicSharedMemorySize, GEMM_SMEM);

    prep_kernel<<<1, 256>>>(batch);

    // fused fp16 conversion (single launch)
    {
        const int nx  = (N_TOK * D_EMB) / 4;
        const int nwi = (D_EMB * D3) / 4;
        const int nwo = (D_EMB * D_EMB) / 4;
        const int tot = nx + nwi + nwo;
        cvt_all_fp16<<<(tot + 255) / 256, 256>>>(
            (const float4*)x,     (uint2*)xh,  nx,
            (const float4*)W_in,  (uint2*)wih, nwi,
            (const float4*)W_out, (uint2*)woh, nwo);
    }

    {   // qkv = x @ W_in + b_in   (fp16 in, fp16 out)
        dim3 grid(D3 / 256, N_TOK / 128);
        gemm_f16_cp<__half><<<grid, 256, GEMM_SMEM>>>(N_TOK, D3, D_EMB, xh, wih, b_in, qkvh);
    }

    {   // segment-local fp16 tensor-core attention
        dim3 grid(MAX_TILES, N_HEADS);
        attn_f16<<<grid, 128>>>(qkvh, attnh);
    }

    {   // out = attn @ W_out + b_out  (fp32 out)
        dim3 grid(D_EMB / 256, N_TOK / 128);
        gemm_f16_cp<float><<<grid, 256, GEMM_SMEM>>>(N_TOK, D_EMB, D_EMB, attnh, woh, b_out, out);
    }
}